// round 11
// baseline (speedup 1.0000x reference)
#include <cuda_runtime.h>
#include <math.h>
#include <stdint.h>

#define BB 32
#define HID 512
#define CTXD 512
#define EMBD 256
#define ATTN 256
#define VOC 5000
#define TT 160
#define NG 2560
#define KST 1024
#define NA 257
#define GB 128           // persistent grid blocks

// ---------------- device scratch (static; no allocation) ----------------
__device__ float g_ctx_embed[BB*ATTN*CTXD];
__device__ float g_xproj[TT*BB*NG];
__device__ float g_Xemb[TT*BB*EMBD];
__device__ float g_Wpack[KST*NG];
__device__ float g_WxPack[EMBD*NG];
__device__ float g_biasPack[NG];
__device__ float g_A[BB*KST];          // [unused(512) | h(512)]
__device__ float g_c[BB*HID];
__device__ float g_gp[32*BB*NG];       // gates partials: 32 splitK buckets
__device__ float g_p3[2*16*BB*HID];    // fr0@Wfr, h@Who partials
__device__ float g_p4[2*16*BB*HID];    // fr@Wfre, hol@Whoe partials
__device__ float g_p7[16*BB*HID];      // visph@Watt partials
__device__ float g_fr0[BB*HID];
__device__ float g_scores[BB*NA];
__device__ float g_visph[BB*HID];
__device__ float g_outh[TT*BB*HID];
__device__ float g_logits[TT*BB*VOC];

// ---- tree-barrier state: per-group counter/flag on separate 256B-strided lines ----
__device__ unsigned g_bar_grp[16*64];    // arrival counter for group g at [g*64]
__device__ unsigned g_bar_root[64];      // root arrival counter at [0]
__device__ unsigned g_bar_flag[16*64];   // release generation flag for group g at [g*64]

// dynamic shared layout (floats):
// [0      .. 32768)  s_ctx  : 64 x 512 ctx_embed slice (step-invariant)
// [32768  .. 33280)  s_hoe  : 512
// [33280  .. 33792)  s_fre  : 512
// [33792  .. 39168)  gtask region: sA 32x36 (1152) + sW 32x132 (4224); P6 aliases this
extern __shared__ float dsh[];
#define SOFF_HOE 32768
#define SOFF_FRE 33280
#define SOFF_GT  33792
#define SW_PITCH 132
#define SMEM_FLOATS 39168

__device__ __forceinline__ float sigf(float x){ return 1.f/(1.f+expf(-x)); }
__device__ __forceinline__ float tanha(float x){ float y; asm("tanh.approx.f32 %0, %1;" : "=f"(y) : "f"(x)); return y; }
__device__ __forceinline__ uint32_t f2tf32(float x){
    uint32_t u; asm("cvt.rna.tf32.f32 %0, %1;" : "=r"(u) : "f"(x)); return u;
}
__device__ __forceinline__ uint4 f4tf32(float4 v){
    uint4 t; t.x=f2tf32(v.x); t.y=f2tf32(v.y); t.z=f2tf32(v.z); t.w=f2tf32(v.w); return t;
}
#define MMA_TF32(d, a, b) \
    asm volatile("mma.sync.aligned.m16n8k8.row.col.f32.tf32.tf32.f32 " \
        "{%0,%1,%2,%3}, {%4,%5,%6,%7}, {%8,%9}, {%0,%1,%2,%3};" \
        : "+f"((d)[0]), "+f"((d)[1]), "+f"((d)[2]), "+f"((d)[3]) \
        : "r"((a)[0]), "r"((a)[1]), "r"((a)[2]), "r"((a)[3]), "r"((b)[0]), "r"((b)[1]))

// ---------------- setup kernels ----------------
__global__ void k_init(){
    int i = blockIdx.x*256 + threadIdx.x;
    if (i < BB*KST) g_A[i] = 0.f;
    if (i < BB*HID) g_c[i] = 0.f;
}

__global__ void k_packW(const float* __restrict__ Wih, const float* __restrict__ Whh,
                        const float* __restrict__ Wi2h, const float* __restrict__ Wh2h){
    int idx = blockIdx.x*256 + threadIdx.x;   // exactly KST*NG
    int k = idx / NG, n = idx % NG;
    float v;
    if (k < HID) v = (n < 4*HID) ? Wih[(size_t)(EMBD+k)*4*HID + n] : Wi2h[(size_t)(EMBD+k)*HID + (n-4*HID)];
    else         v = (n < 4*HID) ? Whh[(size_t)(k-HID)*4*HID + n]  : Wh2h[(size_t)(k-HID)*HID + (n-4*HID)];
    g_Wpack[idx] = v;
}

__global__ void k_packX(const float* __restrict__ Wih, const float* __restrict__ Wi2h,
                        const float* __restrict__ bih, const float* __restrict__ bhh,
                        const float* __restrict__ bi2h, const float* __restrict__ bh2h){
    int idx = blockIdx.x*256 + threadIdx.x;   // exactly EMBD*NG
    if (idx < NG)
        g_biasPack[idx] = (idx < 4*HID) ? (bih[idx] + bhh[idx]) : (bi2h[idx-4*HID] + bh2h[idx-4*HID]);
    int k = idx / NG, n = idx % NG;
    g_WxPack[idx] = (n < 4*HID) ? Wih[(size_t)k*4*HID + n] : Wi2h[(size_t)k*HID + (n-4*HID)];
}

__global__ void k_gather(const int* __restrict__ seq, const float* __restrict__ embed){
    int idx = blockIdx.x*256 + threadIdx.x;   // exactly TT*BB*EMBD
    int e = idx & (EMBD-1);
    int r = idx >> 8;
    int t = r >> 5, b = r & 31;
    int tok = seq[b*161 + t];
    g_Xemb[idx] = embed[(size_t)tok*EMBD + e];
}

// ---------------- big GEMM: 64x64 tile fp32 (pre-processing; stays fp32) ----------------
__global__ void __launch_bounds__(256) gemm_big(int mode, const float* __restrict__ Aext,
                        const float* __restrict__ Wext, const float* __restrict__ bext,
                        int N, int K, int act){
    const float* A; const float* W; const float* bias; float* C; int lda, ldw, ldc;
    if (mode == 0){ A=Aext;   W=Wext;     bias=bext;      C=g_ctx_embed; lda=512; ldw=512;  ldc=512; }
    else          { A=g_Xemb; W=g_WxPack; bias=g_biasPack; C=g_xproj;   lda=256; ldw=NG;   ldc=NG;  }

    __shared__ float sAT[32][68];
    __shared__ float sW[32][68];
    int tid = threadIdx.x;
    int row0 = blockIdx.y*64, col0 = blockIdx.x*64;
    int w = tid>>5, l = tid&31;
    int m4 = 32*(w&1) + 4*(l&7);
    int n4 = 16*(w>>1) + 4*(l>>3);
    float acc[4][4];
#pragma unroll
    for (int i=0;i<4;i++)
#pragma unroll
        for (int j=0;j<4;j++) acc[i][j]=0.f;

    for (int k0=0; k0<K; k0+=32){
#pragma unroll
        for (int rep=0;rep<2;rep++){
            int f = tid + rep*256; int m = f>>3, kq = (f&7)<<2;
            float4 v = *(const float4*)(A + (size_t)(row0+m)*lda + k0 + kq);
            sAT[kq][m]=v.x; sAT[kq+1][m]=v.y; sAT[kq+2][m]=v.z; sAT[kq+3][m]=v.w;
        }
#pragma unroll
        for (int rep=0;rep<2;rep++){
            int f = tid + rep*256; int r = f>>4, cq = (f&15)<<2; int col = col0+cq;
            float4 v = make_float4(0.f,0.f,0.f,0.f);
            if (col < N) v = *(const float4*)(W + (size_t)(k0+r)*ldw + col);
            *(float4*)&sW[r][cq] = v;
        }
        __syncthreads();
#pragma unroll
        for (int kk=0;kk<32;kk++){
            float4 av = *(const float4*)&sAT[kk][m4];
            float4 bv = *(const float4*)&sW[kk][n4];
            acc[0][0]+=av.x*bv.x; acc[0][1]+=av.x*bv.y; acc[0][2]+=av.x*bv.z; acc[0][3]+=av.x*bv.w;
            acc[1][0]+=av.y*bv.x; acc[1][1]+=av.y*bv.y; acc[1][2]+=av.y*bv.z; acc[1][3]+=av.y*bv.w;
            acc[2][0]+=av.z*bv.x; acc[2][1]+=av.z*bv.y; acc[2][2]+=av.z*bv.z; acc[2][3]+=av.z*bv.w;
            acc[3][0]+=av.w*bv.x; acc[3][1]+=av.w*bv.y; acc[3][2]+=av.w*bv.z; acc[3][3]+=av.w*bv.w;
        }
        __syncthreads();
    }
#pragma unroll
    for (int i=0;i<4;i++){
        int r = row0 + m4 + i;
#pragma unroll
        for (int j=0;j<4;j++){
            int c = col0 + n4 + j;
            if (c < N){
                float v = acc[i][j] + (bias ? bias[c] : 0.f);
                if (act == 1) v = fmaxf(v, 0.f);
                C[(size_t)r*ldc + c] = v;
            }
        }
    }
}

// ---------------- tf32 tensor-core logits GEMM ----------------
__global__ void __launch_bounds__(256) k_logits_tf32(const float* __restrict__ Wlog,
                                                     const float* __restrict__ blog){
    __shared__ uint32_t sA[128*36];
    __shared__ uint32_t sB[32*68];
    int tid = threadIdx.x;
    int row0 = blockIdx.y*128, col0 = blockIdx.x*64;
    int w = tid>>5, lane = tid&31;
    int wm = w&3, wn = w>>2;
    int gid = lane>>2, sub = lane&3;

    float acc[2][4][4];
#pragma unroll
    for (int mt=0; mt<2; mt++)
#pragma unroll
        for (int nt=0; nt<4; nt++)
#pragma unroll
            for (int i=0;i<4;i++) acc[mt][nt][i]=0.f;

    for (int k0=0; k0<HID; k0+=32){
#pragma unroll
        for (int r=0;r<4;r++){
            int f = tid + r*256;
            int m = f>>3, kq = (f&7)<<2;
            float4 v = *(const float4*)(g_outh + (size_t)(row0+m)*HID + k0 + kq);
            *(uint4*)&sA[m*36+kq] = f4tf32(v);
        }
#pragma unroll
        for (int r=0;r<2;r++){
            int f = tid + r*256;
            int kr = f>>4, cq = (f&15)<<2;
            int c = col0 + cq;
            float4 v;
            if (c + 3 < VOC){
                v = *(const float4*)(Wlog + (size_t)(k0+kr)*VOC + c);
            } else {
                v.x = (c   < VOC) ? Wlog[(size_t)(k0+kr)*VOC + c  ] : 0.f;
                v.y = (c+1 < VOC) ? Wlog[(size_t)(k0+kr)*VOC + c+1] : 0.f;
                v.z = (c+2 < VOC) ? Wlog[(size_t)(k0+kr)*VOC + c+2] : 0.f;
                v.w = (c+3 < VOC) ? Wlog[(size_t)(k0+kr)*VOC + c+3] : 0.f;
            }
            *(uint4*)&sB[kr*68+cq] = f4tf32(v);
        }
        __syncthreads();
#pragma unroll
        for (int ks=0; ks<4; ks++){
            int kb = ks*8;
            uint32_t a[2][4];
#pragma unroll
            for (int mt=0; mt<2; mt++){
                int rbase = wm*32 + mt*16;
                a[mt][0] = sA[(rbase+gid  )*36 + kb+sub  ];
                a[mt][1] = sA[(rbase+gid+8)*36 + kb+sub  ];
                a[mt][2] = sA[(rbase+gid  )*36 + kb+sub+4];
                a[mt][3] = sA[(rbase+gid+8)*36 + kb+sub+4];
            }
            uint32_t b[4][2];
#pragma unroll
            for (int nt=0; nt<4; nt++){
                int cbase = wn*32 + nt*8 + gid;
                b[nt][0] = sB[(kb+sub  )*68 + cbase];
                b[nt][1] = sB[(kb+sub+4)*68 + cbase];
            }
#pragma unroll
            for (int mt=0; mt<2; mt++)
#pragma unroll
                for (int nt=0; nt<4; nt++)
                    MMA_TF32(acc[mt][nt], a[mt], b[nt]);
        }
        __syncthreads();
    }
#pragma unroll
    for (int mt=0; mt<2; mt++){
        int r = row0 + wm*32 + mt*16 + gid;
#pragma unroll
        for (int nt=0; nt<4; nt++){
            int c = col0 + wn*32 + nt*8 + sub*2;
            if (c+1 < VOC){
                float2 v0 = make_float2(acc[mt][nt][0] + blog[c], acc[mt][nt][1] + blog[c+1]);
                float2 v1 = make_float2(acc[mt][nt][2] + blog[c], acc[mt][nt][3] + blog[c+1]);
                *(float2*)(g_logits + (size_t)r*VOC + c)     = v0;
                *(float2*)(g_logits + (size_t)(r+8)*VOC + c) = v1;
            } else if (c < VOC){
                g_logits[(size_t)r*VOC + c]     = acc[mt][nt][0] + blog[c];
                g_logits[(size_t)(r+8)*VOC + c] = acc[mt][nt][2] + blog[c];
            }
        }
    }
}

// ---------------- two-level tree grid barrier ----------------
// 16 groups x 8 blocks. Generation lives in a register (seeded from the quiescent
// flag at kernel entry), so no leading load. Arrival RMWs spread across 16 lines.
__device__ __forceinline__ void gridbar(unsigned &gen, int grp){
    __syncthreads();
    if (threadIdx.x == 0){
        gen += 1u;
        unsigned old;
        asm volatile("atom.acq_rel.gpu.global.add.u32 %0, [%1], %2;"
                     : "=r"(old) : "l"(g_bar_grp + grp*64), "r"(1u) : "memory");
        if (old == 7u){
            asm volatile("st.relaxed.gpu.global.u32 [%0], %1;"
                         :: "l"(g_bar_grp + grp*64), "r"(0u) : "memory");
            unsigned rold;
            asm volatile("atom.acq_rel.gpu.global.add.u32 %0, [%1], %2;"
                         : "=r"(rold) : "l"(g_bar_root), "r"(1u) : "memory");
            if (rold == 15u){
                asm volatile("st.relaxed.gpu.global.u32 [%0], %1;"
                             :: "l"(g_bar_root), "r"(0u) : "memory");
#pragma unroll
                for (int g=0; g<16; g++)
                    asm volatile("st.release.gpu.global.u32 [%0], %1;"
                                 :: "l"(g_bar_flag + g*64), "r"(gen) : "memory");
            } else {
                unsigned cur;
                do {
                    asm volatile("ld.acquire.gpu.global.u32 %0, [%1];"
                                 : "=r"(cur) : "l"(g_bar_flag + grp*64) : "memory");
                } while ((int)(cur - gen) < 0);
            }
        } else {
            unsigned cur;
            do {
                asm volatile("ld.acquire.gpu.global.u32 %0, [%1];"
                             : "=r"(cur) : "l"(g_bar_flag + grp*64) : "memory");
            } while ((int)(cur - gen) < 0);
        }
    }
    __syncthreads();
}

// One GEMM task via tf32 mma: out[0:32, col0:+128] (partial) = A[0:32, k0:+32] @ W[k0:+32, col0:+128]
// stage_mode: -1 load A directly; 1 relu(sum16 partials + bias); 2 tanh(...).
__device__ __forceinline__ void gtask_mma(const float* A, int lda,
                                          const float* W, int ldw,
                                          int col0, int k0,
                                          float* out, int ldo,
                                          const float* stage_base, const float* stage_bias,
                                          int stage_mode){
    uint32_t* sA = (uint32_t*)(dsh + SOFF_GT);            // pitch 36
    uint32_t* sW = (uint32_t*)(dsh + SOFF_GT + 1152);     // pitch 132
    int tid = threadIdx.x;
    {
        int m = tid>>3, kq = (tid&7)<<2;
        float4 av;
        if (stage_mode < 0){
            av = *(const float4*)(A + (size_t)m*lda + k0 + kq);
        } else {
            float4 s = *(const float4*)(stage_bias + k0 + kq);
#pragma unroll
            for (int p=0;p<16;p++){
                const float4 v = *(const float4*)(stage_base + p*(BB*HID) + m*HID + k0 + kq);
                s.x+=v.x; s.y+=v.y; s.z+=v.z; s.w+=v.w;
            }
            if (stage_mode == 1){ s.x=fmaxf(s.x,0.f); s.y=fmaxf(s.y,0.f); s.z=fmaxf(s.z,0.f); s.w=fmaxf(s.w,0.f); }
            else                { s.x=tanhf(s.x); s.y=tanhf(s.y); s.z=tanhf(s.z); s.w=tanhf(s.w); }
            av = s;
        }
        *(uint4*)&sA[m*36 + kq] = f4tf32(av);
    }
#pragma unroll
    for (int rep=0;rep<4;rep++){
        int f = tid + rep*256;
        int row = f>>5, j4 = (f&31)<<2;
        float4 v = *(const float4*)(W + (size_t)(k0+row)*ldw + col0 + j4);
        *(uint4*)&sW[row*SW_PITCH + j4] = f4tf32(v);
    }
    __syncthreads();
    int w = tid>>5, lane = tid&31, gid = lane>>2, sub = lane&3;
    float acc[2][2][4];
#pragma unroll
    for (int mt=0;mt<2;mt++)
#pragma unroll
        for (int nt=0;nt<2;nt++)
#pragma unroll
            for (int i=0;i<4;i++) acc[mt][nt][i]=0.f;
#pragma unroll
    for (int kb=0; kb<32; kb+=8){
        uint32_t a[2][4];
#pragma unroll
        for (int mt=0; mt<2; mt++){
            int rbase = mt*16;
            a[mt][0] = sA[(rbase+gid  )*36 + kb+sub  ];
            a[mt][1] = sA[(rbase+gid+8)*36 + kb+sub  ];
            a[mt][2] = sA[(rbase+gid  )*36 + kb+sub+4];
            a[mt][3] = sA[(rbase+gid+8)*36 + kb+sub+4];
        }
        uint32_t b[2][2];
#pragma unroll
        for (int nt=0; nt<2; nt++){
            int cbase = w*16 + nt*8 + gid;
            b[nt][0] = sW[(kb+sub  )*SW_PITCH + cbase];
            b[nt][1] = sW[(kb+sub+4)*SW_PITCH + cbase];
        }
#pragma unroll
        for (int mt=0; mt<2; mt++)
#pragma unroll
            for (int nt=0; nt<2; nt++)
                MMA_TF32(acc[mt][nt], a[mt], b[nt]);
    }
    __syncthreads();
#pragma unroll
    for (int mt=0; mt<2; mt++){
        int r = mt*16 + gid;
#pragma unroll
        for (int nt=0; nt<2; nt++){
            int c = col0 + w*16 + nt*8 + sub*2;
            *(float2*)(out + (size_t)r*ldo + c)     = make_float2(acc[mt][nt][0], acc[mt][nt][1]);
            *(float2*)(out + (size_t)(r+8)*ldo + c) = make_float2(acc[mt][nt][2], acc[mt][nt][3]);
        }
    }
}

__global__ void __launch_bounds__(256, 1) persist_kernel(
        const float* __restrict__ cnn,
        const float* __restrict__ Wfr,  const float* __restrict__ bfr,
        const float* __restrict__ Who,  const float* __restrict__ bho,
        const float* __restrict__ Wfre, const float* __restrict__ bfre,
        const float* __restrict__ Whoe, const float* __restrict__ bhoe,
        const float* __restrict__ Wa,   const float* __restrict__ ba,
        const float* __restrict__ Watt, const float* __restrict__ batt){
    int tid = threadIdx.x;
    int blk = blockIdx.x;
    int bq  = blk>>2, qq = blk&3;      // P5/P6 block role: (batch, quarter)
    int grp = blk>>3;                  // barrier group
    int l   = tid&31;
    uint32_t* sAu = (uint32_t*)(dsh + SOFF_GT);
    uint32_t* sWu = (uint32_t*)(dsh + SOFF_GT + 1152);

    // seed barrier generation from quiescent flag (consistent across graph replays)
    unsigned bgen = 0;
    if (tid == 0) bgen = g_bar_flag[grp*64];

    // ---- one-time preload: ctx_embed slice into smem; Wa into regs
    for (int i = tid; i < 8192; i += 256){
        ((float4*)dsh)[i] = *(const float4*)(g_ctx_embed
            + ((size_t)bq*ATTN + qq*64 + (i>>7))*CTXD + (i&127)*4);
    }
    float4 wa0 = *(const float4*)(Wa + 0*128 + l*4);
    float4 wa1 = *(const float4*)(Wa + 1*128 + l*4);
    float4 wa2 = *(const float4*)(Wa + 2*128 + l*4);
    float4 wa3 = *(const float4*)(Wa + 3*128 + l*4);
    float ba0 = ba[0];
    gridbar(bgen, grp);

    for (int t=0; t<TT; t++){
        // ======== P1: gates partials (640 tasks, 5/block), pipelined, tf32 mma ========
        {
            int m = tid>>3, kq = (tid&7)<<2;
            int wrow = tid>>5, wj4 = (tid&31)*4;
            float4 pA, pW0, pW1, pW2, pW3;
            {
                int task = blk; int ks = task/20, nt = task%20;
                int k0 = ks*32, col0 = nt*128;
                if (ks < 16){
                    if (t == 0) pA = make_float4(0.f,0.f,0.f,0.f);
                    else {
                        float4 s = *(const float4*)(batt + k0 + kq);
#pragma unroll
                        for (int p=0;p<16;p++){
                            const float4 v = *(const float4*)(g_p7 + (size_t)p*(BB*HID) + m*HID + k0 + kq);
                            s.x+=v.x; s.y+=v.y; s.z+=v.z; s.w+=v.w;
                        }
                        s.x=tanhf(s.x); s.y=tanhf(s.y); s.z=tanhf(s.z); s.w=tanhf(s.w);
                        pA = s;
                    }
                } else pA = *(const float4*)(g_A + (size_t)m*KST + k0 + kq);
                const float* wb = g_Wpack + (size_t)k0*NG + col0;
                pW0 = *(const float4*)(wb + (size_t)(wrow   )*NG + wj4);
                pW1 = *(const float4*)(wb + (size_t)(wrow+ 8)*NG + wj4);
                pW2 = *(const float4*)(wb + (size_t)(wrow+16)*NG + wj4);
                pW3 = *(const float4*)(wb + (size_t)(wrow+24)*NG + wj4);
                if (ks < 16 && nt == 0 && t > 0)
                    *(float4*)(g_outh + (size_t)(t-1)*(BB*HID) + m*HID + k0 + kq) = pA;
                *(uint4*)&sAu[m*36 + kq] = f4tf32(pA);
                *(uint4*)&sWu[(wrow   )*SW_PITCH + wj4] = f4tf32(pW0);
                *(uint4*)&sWu[(wrow+ 8)*SW_PITCH + wj4] = f4tf32(pW1);
                *(uint4*)&sWu[(wrow+16)*SW_PITCH + wj4] = f4tf32(pW2);
                *(uint4*)&sWu[(wrow+24)*SW_PITCH + wj4] = f4tf32(pW3);
            }
            __syncthreads();
            for (int r=0; r<5; r++){
                if (r < 4){
                    int task = blk + (r+1)*GB; int ks = task/20, nt = task%20;
                    int k0 = ks*32, col0 = nt*128;
                    if (ks < 16){
                        if (t == 0) pA = make_float4(0.f,0.f,0.f,0.f);
                        else {
                            float4 s = *(const float4*)(batt + k0 + kq);
#pragma unroll
                            for (int p=0;p<16;p++){
                                const float4 v = *(const float4*)(g_p7 + (size_t)p*(BB*HID) + m*HID + k0 + kq);
                                s.x+=v.x; s.y+=v.y; s.z+=v.z; s.w+=v.w;
                            }
                            s.x=tanhf(s.x); s.y=tanhf(s.y); s.z=tanhf(s.z); s.w=tanhf(s.w);
                            pA = s;
                        }
                    } else pA = *(const float4*)(g_A + (size_t)m*KST + k0 + kq);
                    const float* wb = g_Wpack + (size_t)k0*NG + col0;
                    pW0 = *(const float4*)(wb + (size_t)(wrow   )*NG + wj4);
                    pW1 = *(const float4*)(wb + (size_t)(wrow+ 8)*NG + wj4);
                    pW2 = *(const float4*)(wb + (size_t)(wrow+16)*NG + wj4);
                    pW3 = *(const float4*)(wb + (size_t)(wrow+24)*NG + wj4);
                }
                {
                    int task = blk + r*GB; int ks = task/20, nt = task%20;
                    int col0 = nt*128;
                    float* outp = g_gp + (size_t)ks*(BB*NG);
                    int w = tid>>5, lane = tid&31, gid = lane>>2, sub = lane&3;
                    float acc[2][2][4];
#pragma unroll
                    for (int mt=0;mt<2;mt++)
#pragma unroll
                        for (int nt2=0;nt2<2;nt2++)
#pragma unroll
                            for (int i=0;i<4;i++) acc[mt][nt2][i]=0.f;
#pragma unroll
                    for (int kb=0; kb<32; kb+=8){
                        uint32_t a[2][4];
#pragma unroll
                        for (int mt=0; mt<2; mt++){
                            int rbase = mt*16;
                            a[mt][0] = sAu[(rbase+gid  )*36 + kb+sub  ];
                            a[mt][1] = sAu[(rbase+gid+8)*36 + kb+sub  ];
                            a[mt][2] = sAu[(rbase+gid  )*36 + kb+sub+4];
                            a[mt][3] = sAu[(rbase+gid+8)*36 + kb+sub+4];
                        }
                        uint32_t b[2][2];
#pragma unroll
                        for (int nt2=0; nt2<2; nt2++){
                            int cbase = w*16 + nt2*8 + gid;
                            b[nt2][0] = sWu[(kb+sub  )*SW_PITCH + cbase];
                            b[nt2][1] = sWu[(kb+sub+4)*SW_PITCH + cbase];
                        }
#pragma unroll
                        for (int mt=0; mt<2; mt++)
#pragma unroll
                            for (int nt2=0; nt2<2; nt2++)
                                MMA_TF32(acc[mt][nt2], a[mt], b[nt2]);
                    }
#pragma unroll
                    for (int mt=0; mt<2; mt++){
                        int rr = mt*16 + gid;
#pragma unroll
                        for (int nt2=0; nt2<2; nt2++){
                            int c = col0 + w*16 + nt2*8 + sub*2;
                            *(float2*)(outp + (size_t)rr*NG + c)     = make_float2(acc[mt][nt2][0], acc[mt][nt2][1]);
                            *(float2*)(outp + (size_t)(rr+8)*NG + c) = make_float2(acc[mt][nt2][2], acc[mt][nt2][3]);
                        }
                    }
                }
                __syncthreads();
                if (r < 4){
                    int task = blk + (r+1)*GB; int ks = task/20, nt = task%20;
                    int k0 = ks*32;
                    if (ks < 16 && nt == 0 && t > 0)
                        *(float4*)(g_outh + (size_t)(t-1)*(BB*HID) + m*HID + k0 + kq) = pA;
                    *(uint4*)&sAu[m*36 + kq] = f4tf32(pA);
                    *(uint4*)&sWu[(wrow   )*SW_PITCH + wj4] = f4tf32(pW0);
                    *(uint4*)&sWu[(wrow+ 8)*SW_PITCH + wj4] = f4tf32(pW1);
                    *(uint4*)&sWu[(wrow+16)*SW_PITCH + wj4] = f4tf32(pW2);
                    *(uint4*)&sWu[(wrow+24)*SW_PITCH + wj4] = f4tf32(pW3);
                    __syncthreads();
                }
            }
        }
        gridbar(bgen, grp);

        // ======== P2: reduce gates + LSTM elementwise ========
        if (tid < 128){
            int idx = blk*128 + tid;
            int quad = idx>>2, sub = idx&3;
            int b = quad>>7, j = (quad&127)<<2;
            float4 gg[5];
#pragma unroll
            for (int c=0;c<5;c++){
                int col = c*HID + j;
                float4 x;
                if (sub == 0) x = *(const float4*)(g_xproj + (size_t)t*(BB*NG) + b*NG + col);
                else x = make_float4(0.f,0.f,0.f,0.f);
#pragma unroll
                for (int s=0;s<8;s++){
                    const float4 v = *(const float4*)(g_gp + (size_t)(sub*8+s)*(BB*NG) + b*NG + col);
                    x.x+=v.x; x.y+=v.y; x.z+=v.z; x.w+=v.w;
                }
                gg[c] = x;
            }
#pragma unroll
            for (int c=0;c<5;c++){
                gg[c].x += __shfl_down_sync(0xffffffffu, gg[c].x, 2);
                gg[c].y += __shfl_down_sync(0xffffffffu, gg[c].y, 2);
                gg[c].z += __shfl_down_sync(0xffffffffu, gg[c].z, 2);
                gg[c].w += __shfl_down_sync(0xffffffffu, gg[c].w, 2);
                gg[c].x += __shfl_down_sync(0xffffffffu, gg[c].x, 1);
                gg[c].y += __shfl_down_sync(0xffffffffu, gg[c].y, 1);
                gg[c].z += __shfl_down_sync(0xffffffffu, gg[c].z, 1);
                gg[c].w += __shfl_down_sync(0xffffffffu, gg[c].w, 1);
            }
            if (sub == 0){
                float4 cold = *(const float4*)(g_c + b*HID + j);
                float co[4] = {cold.x, cold.y, cold.z, cold.w};
                float iv4[4] = {gg[0].x,gg[0].y,gg[0].z,gg[0].w};
                float fv4[4] = {gg[1].x,gg[1].y,gg[1].z,gg[1].w};
                float gv4[4] = {gg[2].x,gg[2].y,gg[2].z,gg[2].w};
                float ov4[4] = {gg[3].x,gg[3].y,gg[3].z,gg[3].w};
                float n54[4] = {gg[4].x,gg[4].y,gg[4].z,gg[4].w};
                float cn4[4], hn4[4], f04[4];
#pragma unroll
                for (int e=0;e<4;e++){
                    float cn = sigf(fv4[e])*co[e] + sigf(iv4[e])*tanhf(gv4[e]);
                    float tc = tanhf(cn);
                    cn4[e] = cn;
                    hn4[e] = sigf(ov4[e])*tc;
                    f04[e] = sigf(n54[e])*tc;
                }
                *(float4*)(g_c   + b*HID + j) = make_float4(cn4[0],cn4[1],cn4[2],cn4[3]);
                *(float4*)(g_A   + b*KST + HID + j) = make_float4(hn4[0],hn4[1],hn4[2],hn4[3]);
                *(float4*)(g_fr0 + b*HID + j) = make_float4(f04[0],f04[1],f04[2],f04[3]);
            }
        }
        gridbar(bgen, grp);

        // ======== P3: fr0@Wfr and h@Who partials (128 tasks) ========
        {
            int ks = blk & 15, nt = (blk>>4)&3, mat = blk>>6;
            const float* A = mat ? (g_A + HID) : g_fr0;
            int lda = mat ? KST : HID;
            const float* W = mat ? Who : Wfr;
            gtask_mma(A, lda, W, HID, nt*128, ks*32,
                  g_p3 + (size_t)mat*(16*BB*HID) + (size_t)ks*(BB*HID), HID,
                  nullptr, nullptr, -1);
        }
        gridbar(bgen, grp);

        // ======== P4: fr@Wfre, hol@Whoe partials (A staged from p3) ========
        {
            int ks = blk & 15, nt = (blk>>4)&3, mat = blk>>6;
            const float* W = mat ? Whoe : Wfre;
            gtask_mma(nullptr, 0, W, HID, nt*128, ks*32,
                  g_p4 + (size_t)mat*(16*BB*HID) + (size_t)ks*(BB*HID), HID,
                  g_p3 + (size_t)mat*(16*BB*HID), mat ? bho : bfr, mat ? 2 : 1);
        }
        gridbar(bgen, grp);

        // ======== P5: attention scores (smem ctx; hoe/fre staged from p4) ========
        {
            if (tid < 128){
                int j = tid*4;
                float4 s = *(const float4*)(bhoe + j);
#pragma unroll
                for (int p=0;p<16;p++){
                    const float4 v = *(const float4*)(g_p4 + (size_t)(16+p)*(BB*HID) + bq*HID + j);
                    s.x+=v.x; s.y+=v.y; s.z+=v.z; s.w+=v.w;
                }
                *(float4*)&dsh[SOFF_HOE + j] = s;
            } else if (qq == 0){
                int j = (tid-128)*4;
                float4 s = *(const float4*)(bfre + j);
#pragma unroll
                for (int p=0;p<16;p++){
                    const float4 v = *(const float4*)(g_p4 + (size_t)p*(BB*HID) + bq*HID + j);
                    s.x+=v.x; s.y+=v.y; s.z+=v.z; s.w+=v.w;
                }
                *(float4*)&dsh[SOFF_FRE + j] = s;
            }
            __syncthreads();
            int w = tid>>5;
            float4 hv0 = *(const float4*)&dsh[SOFF_HOE + 0*128 + l*4];
            float4 hv1 = *(const float4*)&dsh[SOFF_HOE + 1*128 + l*4];
            float4 hv2 = *(const float4*)&dsh[SOFF_HOE + 2*128 + l*4];
            float4 hv3 = *(const float4*)&dsh[SOFF_HOE + 3*128 + l*4];
#pragma unroll
            for (int it=0; it<8; it++){
                int al = it*8 + w;
                const float* e = dsh + al*512;
                float acc = 0.f;
                float4 ev;
                ev = *(const float4*)&e[0*128 + l*4];
                acc += wa0.x*tanha(ev.x+hv0.x); acc += wa0.y*tanha(ev.y+hv0.y);
                acc += wa0.z*tanha(ev.z+hv0.z); acc += wa0.w*tanha(ev.w+hv0.w);
                ev = *(const float4*)&e[1*128 + l*4];
                acc += wa1.x*tanha(ev.x+hv1.x); acc += wa1.y*tanha(ev.y+hv1.y);
                acc += wa1.z*tanha(ev.z+hv1.z); acc += wa1.w*tanha(ev.w+hv1.w);
                ev = *(const float4*)&e[2*128 + l*4];
                acc += wa2.x*tanha(ev.x+hv2.x); acc += wa2.y*tanha(ev.y+hv2.y);
                acc += wa2.z*tanha(ev.z+hv2.z); acc += wa2.w*tanha(ev.w+hv2.w);
                ev = *(const float4*)&e[3*128 + l*4];
                acc += wa3.x*tanha(ev.x+hv3.x); acc += wa3.y*tanha(ev.y+hv3.y);
                acc += wa3.z*tanha(ev.z+hv3.z); acc += wa3.w*tanha(ev.w+hv3.w);
#pragma unroll
                for (int off=16; off; off>>=1) acc += __shfl_xor_sync(0xffffffffu, acc, off);
                if (l == 0) g_scores[bq*NA + qq*64 + al + 1] = acc + ba0;
            }
            if (qq == 0 && w == 0){
                float acc = 0.f;
                float4 ev;
                ev = *(const float4*)&dsh[SOFF_FRE + 0*128 + l*4];
                acc += wa0.x*tanha(ev.x+hv0.x); acc += wa0.y*tanha(ev.y+hv0.y);
                acc += wa0.z*tanha(ev.z+hv0.z); acc += wa0.w*tanha(ev.w+hv0.w);
                ev = *(const float4*)&dsh[SOFF_FRE + 1*128 + l*4];
                acc += wa1.x*tanha(ev.x+hv1.x); acc += wa1.y*tanha(ev.y+hv1.y);
                acc += wa1.z*tanha(ev.z+hv1.z); acc += wa1.w*tanha(ev.w+hv1.w);
                ev = *(const float4*)&dsh[SOFF_FRE + 2*128 + l*4];
                acc += wa2.x*tanha(ev.x+hv2.x); acc += wa2.y*tanha(ev.y+hv2.y);
                acc += wa2.z*tanha(ev.z+hv2.z); acc += wa2.w*tanha(ev.w+hv2.w);
                ev = *(const float4*)&dsh[SOFF_FRE + 3*128 + l*4];
                acc += wa3.x*tanha(ev.x+hv3.x); acc += wa3.y*tanha(ev.y+hv3.y);
                acc += wa3.z*tanha(ev.z+hv3.z); acc += wa3.w*tanha(ev.w+hv3.w);
#pragma unroll
                for (int off=16; off; off>>=1) acc += __shfl_xor_sync(0xffffffffu, acc, off);
                if (l == 0) g_scores[bq*NA] = acc + ba0;
            }
        }
        gridbar(bgen, grp);

        // ======== P6: softmax + vis (fr, hol reduced inline) -> visph ========
        {
            float* s_sc  = dsh + SOFF_GT;
            float* s_red = dsh + SOFF_GT + 272;
            float* s_v   = dsh + SOFF_GT + 544;
            s_sc[tid] = g_scores[bq*NA + tid];
            if (tid == 0) s_sc[256] = g_scores[bq*NA + 256];
            __syncthreads();
            float mv = s_sc[tid];
            if (tid == 0) mv = fmaxf(mv, s_sc[256]);
            s_red[tid] = mv; __syncthreads();
            for (int st=128; st; st>>=1){ if (tid<st) s_red[tid] = fmaxf(s_red[tid], s_red[tid+st]); __syncthreads(); }
            float mx = s_red[0]; __syncthreads();
            float ev  = expf(s_sc[tid] - mx);
            float ev2 = (tid==0) ? expf(s_sc[256] - mx) : 0.f;
            s_red[tid] = ev + ev2; __syncthreads();
            for (int st=128; st; st>>=1){ if (tid<st) s_red[tid] += s_red[tid+st]; __syncthreads(); }
            float inv = 1.f / s_red[0];
            __syncthreads();
            s_sc[tid] = ev * inv;
            if (tid == 0) s_sc[256] = ev2 * inv;
            __syncthreads();
            int aa = tid>>5, hq = tid&31;
            int h = qq*128 + hq*4;
            float4 acc = make_float4(0.f,0.f,0.f,0.f);
            int astart = aa;
            if (aa == 0){
                float4 s = *(const float4*)(bfr + h);
#pragma unroll
                for (int p=0;p<16;p++){
                    const float4 v = *(const float4*)(g_p3 + (size_t)p*(BB*HID) + bq*HID + h);
                    s.x+=v.x; s.y+=v.y; s.z+=v.z; s.w+=v.w;
                }
                s.x=fmaxf(s.x,0.f); s.y=fmaxf(s.y,0.f); s.z=fmaxf(s.z,0.f); s.w=fmaxf(s.w,0.f);
                float w0 = s_sc[0];
                acc.x = w0*s.x; acc.y = w0*s.y; acc.z = w0*s.z; acc.w = w0*s.w;
                astart = 8;
            }
            for (int a = astart; a < NA; a += 8){
                float w = s_sc[a];
                float4 v = *(const float4*)(cnn + ((size_t)bq*ATTN + (a-1))*CTXD + h);
                acc.x += w*v.x; acc.y += w*v.y; acc.z += w*v.z; acc.w += w*v.w;
            }
            *(float4*)&s_v[aa*128 + hq*4] = acc;
            __syncthreads();
            if (tid < 32){
                int h2 = qq*128 + tid*4;
                float4 s = make_float4(0.f,0.f,0.f,0.f);
#pragma unroll
                for (int a2=0;a2<8;a2++){
                    const float4 v = *(const float4*)&s_v[a2*128 + tid*4];
                    s.x+=v.x; s.y+=v.y; s.z+=v.z; s.w+=v.w;
                }
                float4 ho = *(const float4*)(bho + h2);
#pragma unroll
                for (int p=0;p<16;p++){
                    const float4 v = *(const float4*)(g_p3 + (size_t)(16+p)*(BB*HID) + bq*HID + h2);
                    ho.x+=v.x; ho.y+=v.y; ho.z+=v.z; ho.w+=v.w;
                }
                s.x += tanhf(ho.x); s.y += tanhf(ho.y); s.z += tanhf(ho.z); s.w += tanhf(ho.w);
                *(float4*)(g_visph + bq*HID + h2) = s;
            }
            __syncthreads();
        }
        gridbar(bgen, grp);

        // ======== P7: outh partials (64 tasks) ========
        if (blk < 64){
            int ks = blk & 15, nt = blk>>4;
            gtask_mma(g_visph, HID, Watt, HID, nt*128, ks*32,
                  g_p7 + (size_t)ks*(BB*HID), HID, nullptr, nullptr, -1);
        }
        gridbar(bgen, grp);
    }

    // ---- epilogue: finalize out(TT-1) into g_outh[TT-1]
    if (tid < 32){
        int quad = blk*32 + tid;
        int b = quad>>7, j = (quad&127)<<2;
        float4 s = *(const float4*)(batt + j);
#pragma unroll
        for (int p=0;p<16;p++){
            const float4 v = *(const float4*)(g_p7 + (size_t)p*(BB*HID) + b*HID + j);
            s.x+=v.x; s.y+=v.y; s.z+=v.z; s.w+=v.w;
        }
        s.x=tanhf(s.x); s.y=tanhf(s.y); s.z=tanhf(s.z); s.w=tanhf(s.w);
        *(float4*)(g_outh + (size_t)(TT-1)*(BB*HID) + b*HID + j) = s;
    }
}

// ---------------- log_softmax + [t][b] -> [b][t] remap ----------------
__global__ void k_logsm(float* __restrict__ out){
    int r = blockIdx.x;
    int t = r >> 5, b = r & 31;
    const float* row = g_logits + (size_t)r*VOC;
    float* orow = out + ((size_t)b*TT + t)*VOC;
    __shared__ float red[256];
    int tid = threadIdx.x;
    float mx = -1e30f;
    for (int i=tid; i<VOC; i+=256) mx = fmaxf(mx, row[i]);
    red[tid] = mx; __syncthreads();
    for (int st=128; st>0; st>>=1){ if (tid<st) red[tid] = fmaxf(red[tid], red[tid+st]); __syncthreads(); }
    mx = red[0]; __syncthreads();
    float sm = 0.f;
    for (int i=tid; i<VOC; i+=256) sm += expf(row[i] - mx);
    red[tid] = sm; __syncthreads();
    for (int st=128; st>0; st>>=1){ if (tid<st) red[tid] += red[tid+st]; __syncthreads(); }
    float ls = mx + logf(red[0]);
    for (int i=tid; i<VOC; i+=256) orow[i] = row[i] - ls;
}

// ---------------- launch ----------------
extern "C" void kernel_launch(void* const* d_in, const int* in_sizes, int n_in,
                              void* d_out, int out_size){
    const float* cnn  = (const float*)d_in[0];
    const int*   seq  = (const int*)  d_in[1];
    const float* emb  = (const float*)d_in[2];
    const float* Wce  = (const float*)d_in[3];  const float* bce  = (const float*)d_in[4];
    const float* Wih  = (const float*)d_in[5];  const float* bih  = (const float*)d_in[6];
    const float* Whh  = (const float*)d_in[7];  const float* bhh  = (const float*)d_in[8];
    const float* Wi2h = (const float*)d_in[9];  const float* bi2h = (const float*)d_in[10];
    const float* Wh2h = (const float*)d_in[11]; const float* bh2h = (const float*)d_in[12];
    const float* Wfr  = (const float*)d_in[13]; const float* bfr  = (const float*)d_in[14];
    const float* Wfre = (const float*)d_in[15]; const float* bfre = (const float*)d_in[16];
    const float* Who  = (const float*)d_in[17]; const float* bho  = (const float*)d_in[18];
    const float* Whoe = (const float*)d_in[19]; const float* bhoe = (const float*)d_in[20];
    const float* Wa   = (const float*)d_in[21]; const float* ba   = (const float*)d_in[22];
    const float* Watt = (const float*)d_in[23]; const float* batt = (const float*)d_in[24];
    const float* Wlog = (const float*)d_in[25]; const float* blog = (const float*)d_in[26];
    float* out = (float*)d_out;

    cudaFuncSetAttribute(persist_kernel, cudaFuncAttributeMaxDynamicSharedMemorySize,
                         SMEM_FLOATS*4);

    k_init<<<192, 256>>>();
    k_packW<<<(KST*NG)/256, 256>>>(Wih, Whh, Wi2h, Wh2h);
    k_packX<<<(EMBD*NG)/256, 256>>>(Wih, Wi2h, bih, bhh, bi2h, bh2h);
    k_gather<<<(TT*BB*EMBD)/256, 256>>>(seq, emb);
    gemm_big<<<dim3(CTXD/64, (BB*ATTN)/64), 256>>>(0, cnn, Wce, bce, CTXD, CTXD, 1);
    gemm_big<<<dim3(NG/64, (TT*BB)/64), 256>>>(1, nullptr, nullptr, nullptr, NG, EMBD, 0);

    persist_kernel<<<GB, 256, SMEM_FLOATS*4>>>(cnn, Wfr, bfr, Who, bho, Wfre, bfre,
                                               Whoe, bhoe, Wa, ba, Watt, batt);

    k_logits_tf32<<<dim3((VOC+63)/64, (TT*BB)/128), 256>>>(Wlog, blog);
    k_logsm<<<TT*BB, 256>>>(out);
}

// round 12
// speedup vs baseline: 1.7828x; 1.7828x over previous
#include <cuda_runtime.h>
#include <math.h>
#include <stdint.h>

#define BB 32
#define HID 512
#define CTXD 512
#define EMBD 256
#define ATTN 256
#define VOC 5000
#define TT 160
#define NG 2560
#define KST 1024
#define NA 257
#define GB 128           // persistent grid blocks

// ---------------- device scratch (static; no allocation) ----------------
__device__ float g_ctx_embed[BB*ATTN*CTXD];
__device__ float g_xproj[TT*BB*NG];
__device__ float g_Xemb[TT*BB*EMBD];
__device__ float g_Wpack[KST*NG];
__device__ float g_WxPack[EMBD*NG];
__device__ float g_biasPack[NG];
__device__ float g_A[BB*KST];          // [unused(512) | h(512)]
__device__ float g_c[BB*HID];
__device__ float g_gp[32*BB*NG];       // gates partials: 32 splitK buckets
__device__ float g_p3[2*16*BB*HID];    // fr0@Wfr, h@Who partials
__device__ float g_p4[2*16*BB*HID];    // fr@Wfre, hol@Whoe partials
__device__ float g_p7[16*BB*HID];      // visph@Watt partials
__device__ float g_fr0[BB*HID];
__device__ float g_scores[BB*NA];
__device__ float g_visph[BB*HID];
__device__ float g_outh[TT*BB*HID];
__device__ float g_logits[TT*BB*VOC];

// ---- barrier v3: parallel tree arrivals, SINGLE release flag ----
__device__ unsigned g_bar_grp[16*64];    // arrival counter for group g at [g*64]
__device__ unsigned g_bar_root[64];      // root arrival counter at [0]
__device__ unsigned g_bar_flag[64];      // single release generation flag at [0]

// dynamic shared layout (floats):
// [0      .. 32768)  s_ctx  : 64 x 512 ctx_embed slice (step-invariant)
// [32768  .. 33280)  s_hoe  : 512
// [33280  .. 33792)  s_fre  : 512
// [33792  .. 39168)  gtask region: sA 32x36 (1152) + sW 32x132 (4224); P6 aliases this
extern __shared__ float dsh[];
#define SOFF_HOE 32768
#define SOFF_FRE 33280
#define SOFF_GT  33792
#define SW_PITCH 132
#define SMEM_FLOATS 39168

__device__ __forceinline__ float sigf(float x){ return 1.f/(1.f+expf(-x)); }
__device__ __forceinline__ float tanha(float x){ float y; asm("tanh.approx.f32 %0, %1;" : "=f"(y) : "f"(x)); return y; }
__device__ __forceinline__ uint32_t f2tf32(float x){
    uint32_t u; asm("cvt.rna.tf32.f32 %0, %1;" : "=r"(u) : "f"(x)); return u;
}
__device__ __forceinline__ uint4 f4tf32(float4 v){
    uint4 t; t.x=f2tf32(v.x); t.y=f2tf32(v.y); t.z=f2tf32(v.z); t.w=f2tf32(v.w); return t;
}
#define MMA_TF32(d, a, b) \
    asm volatile("mma.sync.aligned.m16n8k8.row.col.f32.tf32.tf32.f32 " \
        "{%0,%1,%2,%3}, {%4,%5,%6,%7}, {%8,%9}, {%0,%1,%2,%3};" \
        : "+f"((d)[0]), "+f"((d)[1]), "+f"((d)[2]), "+f"((d)[3]) \
        : "r"((a)[0]), "r"((a)[1]), "r"((a)[2]), "r"((a)[3]), "r"((b)[0]), "r"((b)[1]))

// ---------------- setup kernels ----------------
__global__ void k_init(){
    int i = blockIdx.x*256 + threadIdx.x;
    if (i < BB*KST) g_A[i] = 0.f;
    if (i < BB*HID) g_c[i] = 0.f;
}

__global__ void k_packW(const float* __restrict__ Wih, const float* __restrict__ Whh,
                        const float* __restrict__ Wi2h, const float* __restrict__ Wh2h){
    int idx = blockIdx.x*256 + threadIdx.x;   // exactly KST*NG
    int k = idx / NG, n = idx % NG;
    float v;
    if (k < HID) v = (n < 4*HID) ? Wih[(size_t)(EMBD+k)*4*HID + n] : Wi2h[(size_t)(EMBD+k)*HID + (n-4*HID)];
    else         v = (n < 4*HID) ? Whh[(size_t)(k-HID)*4*HID + n]  : Wh2h[(size_t)(k-HID)*HID + (n-4*HID)];
    g_Wpack[idx] = v;
}

__global__ void k_packX(const float* __restrict__ Wih, const float* __restrict__ Wi2h,
                        const float* __restrict__ bih, const float* __restrict__ bhh,
                        const float* __restrict__ bi2h, const float* __restrict__ bh2h){
    int idx = blockIdx.x*256 + threadIdx.x;   // exactly EMBD*NG
    if (idx < NG)
        g_biasPack[idx] = (idx < 4*HID) ? (bih[idx] + bhh[idx]) : (bi2h[idx-4*HID] + bh2h[idx-4*HID]);
    int k = idx / NG, n = idx % NG;
    g_WxPack[idx] = (n < 4*HID) ? Wih[(size_t)k*4*HID + n] : Wi2h[(size_t)k*HID + (n-4*HID)];
}

__global__ void k_gather(const int* __restrict__ seq, const float* __restrict__ embed){
    int idx = blockIdx.x*256 + threadIdx.x;   // exactly TT*BB*EMBD
    int e = idx & (EMBD-1);
    int r = idx >> 8;
    int t = r >> 5, b = r & 31;
    int tok = seq[b*161 + t];
    g_Xemb[idx] = embed[(size_t)tok*EMBD + e];
}

// ---------------- generic tf32 tensor-core GEMM (pre-GEMMs + logits) ----------------
// C[M,N] = act(A[M,K] @ W[K,N] + bias). M % 128 == 0, K % 32 == 0.
// mode 0: ctx_embed = relu(cnn@Wce+bce); mode 1: xproj; mode 2: logits.
__global__ void __launch_bounds__(256) k_gemm_tf32(int mode,
        const float* __restrict__ Aext, const float* __restrict__ Wext,
        const float* __restrict__ bext, int N, int K, int act){
    const float* A; const float* W; const float* bias; float* C; int lda, ldw, ldc;
    if (mode == 0){ A=Aext;   W=Wext;     bias=bext;       C=g_ctx_embed; lda=512; ldw=512; ldc=512; }
    else if (mode==1){ A=g_Xemb; W=g_WxPack; bias=g_biasPack; C=g_xproj;  lda=256; ldw=NG;  ldc=NG;  }
    else            { A=g_outh;  W=Wext;     bias=bext;       C=g_logits; lda=512; ldw=VOC; ldc=VOC; }

    __shared__ uint32_t sA[128*36];
    __shared__ uint32_t sB[32*68];
    int tid = threadIdx.x;
    int row0 = blockIdx.y*128, col0 = blockIdx.x*64;
    int w = tid>>5, lane = tid&31;
    int wm = w&3, wn = w>>2;
    int gid = lane>>2, sub = lane&3;

    float acc[2][4][4];
#pragma unroll
    for (int mt=0; mt<2; mt++)
#pragma unroll
        for (int nt=0; nt<4; nt++)
#pragma unroll
            for (int i=0;i<4;i++) acc[mt][nt][i]=0.f;

    for (int k0=0; k0<K; k0+=32){
#pragma unroll
        for (int r=0;r<4;r++){
            int f = tid + r*256;
            int m = f>>3, kq = (f&7)<<2;
            float4 v = *(const float4*)(A + (size_t)(row0+m)*lda + k0 + kq);
            *(uint4*)&sA[m*36+kq] = f4tf32(v);
        }
#pragma unroll
        for (int r=0;r<2;r++){
            int f = tid + r*256;
            int kr = f>>4, cq = (f&15)<<2;
            int c = col0 + cq;
            float4 v;
            if (c + 3 < N){
                v = *(const float4*)(W + (size_t)(k0+kr)*ldw + c);
            } else {
                v.x = (c   < N) ? W[(size_t)(k0+kr)*ldw + c  ] : 0.f;
                v.y = (c+1 < N) ? W[(size_t)(k0+kr)*ldw + c+1] : 0.f;
                v.z = (c+2 < N) ? W[(size_t)(k0+kr)*ldw + c+2] : 0.f;
                v.w = (c+3 < N) ? W[(size_t)(k0+kr)*ldw + c+3] : 0.f;
            }
            *(uint4*)&sB[kr*68+cq] = f4tf32(v);
        }
        __syncthreads();
#pragma unroll
        for (int ks=0; ks<4; ks++){
            int kb = ks*8;
            uint32_t a[2][4];
#pragma unroll
            for (int mt=0; mt<2; mt++){
                int rbase = wm*32 + mt*16;
                a[mt][0] = sA[(rbase+gid  )*36 + kb+sub  ];
                a[mt][1] = sA[(rbase+gid+8)*36 + kb+sub  ];
                a[mt][2] = sA[(rbase+gid  )*36 + kb+sub+4];
                a[mt][3] = sA[(rbase+gid+8)*36 + kb+sub+4];
            }
            uint32_t b[4][2];
#pragma unroll
            for (int nt=0; nt<4; nt++){
                int cbase = wn*32 + nt*8 + gid;
                b[nt][0] = sB[(kb+sub  )*68 + cbase];
                b[nt][1] = sB[(kb+sub+4)*68 + cbase];
            }
#pragma unroll
            for (int mt=0; mt<2; mt++)
#pragma unroll
                for (int nt=0; nt<4; nt++)
                    MMA_TF32(acc[mt][nt], a[mt], b[nt]);
        }
        __syncthreads();
    }
#pragma unroll
    for (int mt=0; mt<2; mt++){
        int r = row0 + wm*32 + mt*16 + gid;
#pragma unroll
        for (int nt=0; nt<4; nt++){
            int c = col0 + wn*32 + nt*8 + sub*2;
#pragma unroll
            for (int half=0; half<2; half++){
                int rr = r + half*8;
                float v0 = acc[mt][nt][half*2+0];
                float v1 = acc[mt][nt][half*2+1];
                if (c+1 < N){
                    v0 += bias[c]; v1 += bias[c+1];
                    if (act == 1){ v0 = fmaxf(v0,0.f); v1 = fmaxf(v1,0.f); }
                    *(float2*)(C + (size_t)rr*ldc + c) = make_float2(v0, v1);
                } else if (c < N){
                    v0 += bias[c];
                    if (act == 1) v0 = fmaxf(v0,0.f);
                    C[(size_t)rr*ldc + c] = v0;
                }
            }
        }
    }
}

// ---------------- barrier v3: tree arrival, single-flag release ----------------
__device__ __forceinline__ void gridbar(unsigned &gen, int grp){
    __syncthreads();
    if (threadIdx.x == 0){
        gen += 1u;
        unsigned old;
        asm volatile("atom.acq_rel.gpu.global.add.u32 %0, [%1], %2;"
                     : "=r"(old) : "l"(g_bar_grp + grp*64), "r"(1u) : "memory");
        if (old == 7u){
            asm volatile("st.relaxed.gpu.global.u32 [%0], %1;"
                         :: "l"(g_bar_grp + grp*64), "r"(0u) : "memory");
            unsigned rold;
            asm volatile("atom.acq_rel.gpu.global.add.u32 %0, [%1], %2;"
                         : "=r"(rold) : "l"(g_bar_root), "r"(1u) : "memory");
            if (rold == 15u){
                asm volatile("st.relaxed.gpu.global.u32 [%0], %1;"
                             :: "l"(g_bar_root), "r"(0u) : "memory");
                asm volatile("st.release.gpu.global.u32 [%0], %1;"
                             :: "l"(g_bar_flag), "r"(gen) : "memory");
            } else {
                unsigned cur;
                do {
                    asm volatile("ld.acquire.gpu.global.u32 %0, [%1];"
                                 : "=r"(cur) : "l"(g_bar_flag) : "memory");
                } while ((int)(cur - gen) < 0);
            }
        } else {
            unsigned cur;
            do {
                asm volatile("ld.acquire.gpu.global.u32 %0, [%1];"
                             : "=r"(cur) : "l"(g_bar_flag) : "memory");
            } while ((int)(cur - gen) < 0);
        }
    }
    __syncthreads();
}

// One GEMM task via tf32 mma: out[0:32, col0:+128] (partial) = A[0:32, k0:+32] @ W[k0:+32, col0:+128]
// stage_mode: -1 load A directly; 1 relu(sum16 partials + bias); 2 tanh(...).
__device__ __forceinline__ void gtask_mma(const float* A, int lda,
                                          const float* W, int ldw,
                                          int col0, int k0,
                                          float* out, int ldo,
                                          const float* stage_base, const float* stage_bias,
                                          int stage_mode){
    uint32_t* sA = (uint32_t*)(dsh + SOFF_GT);            // pitch 36
    uint32_t* sW = (uint32_t*)(dsh + SOFF_GT + 1152);     // pitch 132
    int tid = threadIdx.x;
    {
        int m = tid>>3, kq = (tid&7)<<2;
        float4 av;
        if (stage_mode < 0){
            av = *(const float4*)(A + (size_t)m*lda + k0 + kq);
        } else {
            float4 s = *(const float4*)(stage_bias + k0 + kq);
#pragma unroll
            for (int p=0;p<16;p++){
                const float4 v = *(const float4*)(stage_base + p*(BB*HID) + m*HID + k0 + kq);
                s.x+=v.x; s.y+=v.y; s.z+=v.z; s.w+=v.w;
            }
            if (stage_mode == 1){ s.x=fmaxf(s.x,0.f); s.y=fmaxf(s.y,0.f); s.z=fmaxf(s.z,0.f); s.w=fmaxf(s.w,0.f); }
            else                { s.x=tanhf(s.x); s.y=tanhf(s.y); s.z=tanhf(s.z); s.w=tanhf(s.w); }
            av = s;
        }
        *(uint4*)&sA[m*36 + kq] = f4tf32(av);
    }
#pragma unroll
    for (int rep=0;rep<4;rep++){
        int f = tid + rep*256;
        int row = f>>5, j4 = (f&31)<<2;
        float4 v = *(const float4*)(W + (size_t)(k0+row)*ldw + col0 + j4);
        *(uint4*)&sW[row*SW_PITCH + j4] = f4tf32(v);
    }
    __syncthreads();
    int w = tid>>5, lane = tid&31, gid = lane>>2, sub = lane&3;
    float acc[2][2][4];
#pragma unroll
    for (int mt=0;mt<2;mt++)
#pragma unroll
        for (int nt=0;nt<2;nt++)
#pragma unroll
            for (int i=0;i<4;i++) acc[mt][nt][i]=0.f;
#pragma unroll
    for (int kb=0; kb<32; kb+=8){
        uint32_t a[2][4];
#pragma unroll
        for (int mt=0; mt<2; mt++){
            int rbase = mt*16;
            a[mt][0] = sA[(rbase+gid  )*36 + kb+sub  ];
            a[mt][1] = sA[(rbase+gid+8)*36 + kb+sub  ];
            a[mt][2] = sA[(rbase+gid  )*36 + kb+sub+4];
            a[mt][3] = sA[(rbase+gid+8)*36 + kb+sub+4];
        }
        uint32_t b[2][2];
#pragma unroll
        for (int nt=0; nt<2; nt++){
            int cbase = w*16 + nt*8 + gid;
            b[nt][0] = sW[(kb+sub  )*SW_PITCH + cbase];
            b[nt][1] = sW[(kb+sub+4)*SW_PITCH + cbase];
        }
#pragma unroll
        for (int mt=0; mt<2; mt++)
#pragma unroll
            for (int nt=0; nt<2; nt++)
                MMA_TF32(acc[mt][nt], a[mt], b[nt]);
    }
    __syncthreads();
#pragma unroll
    for (int mt=0; mt<2; mt++){
        int r = mt*16 + gid;
#pragma unroll
        for (int nt=0; nt<2; nt++){
            int c = col0 + w*16 + nt*8 + sub*2;
            *(float2*)(out + (size_t)r*ldo + c)     = make_float2(acc[mt][nt][0], acc[mt][nt][1]);
            *(float2*)(out + (size_t)(r+8)*ldo + c) = make_float2(acc[mt][nt][2], acc[mt][nt][3]);
        }
    }
}

__global__ void __launch_bounds__(256, 1) persist_kernel(
        const float* __restrict__ cnn,
        const float* __restrict__ Wfr,  const float* __restrict__ bfr,
        const float* __restrict__ Who,  const float* __restrict__ bho,
        const float* __restrict__ Wfre, const float* __restrict__ bfre,
        const float* __restrict__ Whoe, const float* __restrict__ bhoe,
        const float* __restrict__ Wa,   const float* __restrict__ ba,
        const float* __restrict__ Watt, const float* __restrict__ batt){
    int tid = threadIdx.x;
    int blk = blockIdx.x;
    int bq  = blk>>2, qq = blk&3;      // P5/P6 block role: (batch, quarter)
    int grp = blk>>3;                  // barrier group
    int l   = tid&31;
    uint32_t* sAu = (uint32_t*)(dsh + SOFF_GT);
    uint32_t* sWu = (uint32_t*)(dsh + SOFF_GT + 1152);

    // seed barrier generation from quiescent flag (consistent across graph replays)
    unsigned bgen = 0;
    if (tid == 0) bgen = g_bar_flag[0];

    // ---- one-time preload: ctx_embed slice into smem; Wa into regs
    for (int i = tid; i < 8192; i += 256){
        ((float4*)dsh)[i] = *(const float4*)(g_ctx_embed
            + ((size_t)bq*ATTN + qq*64 + (i>>7))*CTXD + (i&127)*4);
    }
    float4 wa0 = *(const float4*)(Wa + 0*128 + l*4);
    float4 wa1 = *(const float4*)(Wa + 1*128 + l*4);
    float4 wa2 = *(const float4*)(Wa + 2*128 + l*4);
    float4 wa3 = *(const float4*)(Wa + 3*128 + l*4);
    float ba0 = ba[0];
    gridbar(bgen, grp);

    for (int t=0; t<TT; t++){
        // ======== P1: gates partials (640 tasks, 5/block), pipelined, tf32 mma ========
        {
            int m = tid>>3, kq = (tid&7)<<2;
            int wrow = tid>>5, wj4 = (tid&31)*4;
            float4 pA, pW0, pW1, pW2, pW3;
            {
                int task = blk; int ks = task/20, nt = task%20;
                int k0 = ks*32, col0 = nt*128;
                if (ks < 16){
                    if (t == 0) pA = make_float4(0.f,0.f,0.f,0.f);
                    else {
                        float4 s = *(const float4*)(batt + k0 + kq);
#pragma unroll
                        for (int p=0;p<16;p++){
                            const float4 v = *(const float4*)(g_p7 + (size_t)p*(BB*HID) + m*HID + k0 + kq);
                            s.x+=v.x; s.y+=v.y; s.z+=v.z; s.w+=v.w;
                        }
                        s.x=tanhf(s.x); s.y=tanhf(s.y); s.z=tanhf(s.z); s.w=tanhf(s.w);
                        pA = s;
                    }
                } else pA = *(const float4*)(g_A + (size_t)m*KST + k0 + kq);
                const float* wb = g_Wpack + (size_t)k0*NG + col0;
                pW0 = *(const float4*)(wb + (size_t)(wrow   )*NG + wj4);
                pW1 = *(const float4*)(wb + (size_t)(wrow+ 8)*NG + wj4);
                pW2 = *(const float4*)(wb + (size_t)(wrow+16)*NG + wj4);
                pW3 = *(const float4*)(wb + (size_t)(wrow+24)*NG + wj4);
                if (ks < 16 && nt == 0 && t > 0)
                    *(float4*)(g_outh + (size_t)(t-1)*(BB*HID) + m*HID + k0 + kq) = pA;
                *(uint4*)&sAu[m*36 + kq] = f4tf32(pA);
                *(uint4*)&sWu[(wrow   )*SW_PITCH + wj4] = f4tf32(pW0);
                *(uint4*)&sWu[(wrow+ 8)*SW_PITCH + wj4] = f4tf32(pW1);
                *(uint4*)&sWu[(wrow+16)*SW_PITCH + wj4] = f4tf32(pW2);
                *(uint4*)&sWu[(wrow+24)*SW_PITCH + wj4] = f4tf32(pW3);
            }
            __syncthreads();
            for (int r=0; r<5; r++){
                if (r < 4){
                    int task = blk + (r+1)*GB; int ks = task/20, nt = task%20;
                    int k0 = ks*32, col0 = nt*128;
                    if (ks < 16){
                        if (t == 0) pA = make_float4(0.f,0.f,0.f,0.f);
                        else {
                            float4 s = *(const float4*)(batt + k0 + kq);
#pragma unroll
                            for (int p=0;p<16;p++){
                                const float4 v = *(const float4*)(g_p7 + (size_t)p*(BB*HID) + m*HID + k0 + kq);
                                s.x+=v.x; s.y+=v.y; s.z+=v.z; s.w+=v.w;
                            }
                            s.x=tanhf(s.x); s.y=tanhf(s.y); s.z=tanhf(s.z); s.w=tanhf(s.w);
                            pA = s;
                        }
                    } else pA = *(const float4*)(g_A + (size_t)m*KST + k0 + kq);
                    const float* wb = g_Wpack + (size_t)k0*NG + col0;
                    pW0 = *(const float4*)(wb + (size_t)(wrow   )*NG + wj4);
                    pW1 = *(const float4*)(wb + (size_t)(wrow+ 8)*NG + wj4);
                    pW2 = *(const float4*)(wb + (size_t)(wrow+16)*NG + wj4);
                    pW3 = *(const float4*)(wb + (size_t)(wrow+24)*NG + wj4);
                }
                {
                    int task = blk + r*GB; int ks = task/20, nt = task%20;
                    int col0 = nt*128;
                    float* outp = g_gp + (size_t)ks*(BB*NG);
                    int w = tid>>5, lane = tid&31, gid = lane>>2, sub = lane&3;
                    float acc[2][2][4];
#pragma unroll
                    for (int mt=0;mt<2;mt++)
#pragma unroll
                        for (int nt2=0;nt2<2;nt2++)
#pragma unroll
                            for (int i=0;i<4;i++) acc[mt][nt2][i]=0.f;
#pragma unroll
                    for (int kb=0; kb<32; kb+=8){
                        uint32_t a[2][4];
#pragma unroll
                        for (int mt=0; mt<2; mt++){
                            int rbase = mt*16;
                            a[mt][0] = sAu[(rbase+gid  )*36 + kb+sub  ];
                            a[mt][1] = sAu[(rbase+gid+8)*36 + kb+sub  ];
                            a[mt][2] = sAu[(rbase+gid  )*36 + kb+sub+4];
                            a[mt][3] = sAu[(rbase+gid+8)*36 + kb+sub+4];
                        }
                        uint32_t b[2][2];
#pragma unroll
                        for (int nt2=0; nt2<2; nt2++){
                            int cbase = w*16 + nt2*8 + gid;
                            b[nt2][0] = sWu[(kb+sub  )*SW_PITCH + cbase];
                            b[nt2][1] = sWu[(kb+sub+4)*SW_PITCH + cbase];
                        }
#pragma unroll
                        for (int mt=0; mt<2; mt++)
#pragma unroll
                            for (int nt2=0; nt2<2; nt2++)
                                MMA_TF32(acc[mt][nt2], a[mt], b[nt2]);
                    }
#pragma unroll
                    for (int mt=0; mt<2; mt++){
                        int rr = mt*16 + gid;
#pragma unroll
                        for (int nt2=0; nt2<2; nt2++){
                            int c = col0 + w*16 + nt2*8 + sub*2;
                            *(float2*)(outp + (size_t)rr*NG + c)     = make_float2(acc[mt][nt2][0], acc[mt][nt2][1]);
                            *(float2*)(outp + (size_t)(rr+8)*NG + c) = make_float2(acc[mt][nt2][2], acc[mt][nt2][3]);
                        }
                    }
                }
                __syncthreads();
                if (r < 4){
                    int task = blk + (r+1)*GB; int ks = task/20, nt = task%20;
                    int k0 = ks*32;
                    if (ks < 16 && nt == 0 && t > 0)
                        *(float4*)(g_outh + (size_t)(t-1)*(BB*HID) + m*HID + k0 + kq) = pA;
                    *(uint4*)&sAu[m*36 + kq] = f4tf32(pA);
                    *(uint4*)&sWu[(wrow   )*SW_PITCH + wj4] = f4tf32(pW0);
                    *(uint4*)&sWu[(wrow+ 8)*SW_PITCH + wj4] = f4tf32(pW1);
                    *(uint4*)&sWu[(wrow+16)*SW_PITCH + wj4] = f4tf32(pW2);
                    *(uint4*)&sWu[(wrow+24)*SW_PITCH + wj4] = f4tf32(pW3);
                    __syncthreads();
                }
            }
        }
        gridbar(bgen, grp);

        // ======== P2: reduce gates + LSTM elementwise ========
        if (tid < 128){
            int idx = blk*128 + tid;
            int quad = idx>>2, sub = idx&3;
            int b = quad>>7, j = (quad&127)<<2;
            float4 gg[5];
#pragma unroll
            for (int c=0;c<5;c++){
                int col = c*HID + j;
                float4 x;
                if (sub == 0) x = *(const float4*)(g_xproj + (size_t)t*(BB*NG) + b*NG + col);
                else x = make_float4(0.f,0.f,0.f,0.f);
#pragma unroll
                for (int s=0;s<8;s++){
                    const float4 v = *(const float4*)(g_gp + (size_t)(sub*8+s)*(BB*NG) + b*NG + col);
                    x.x+=v.x; x.y+=v.y; x.z+=v.z; x.w+=v.w;
                }
                gg[c] = x;
            }
#pragma unroll
            for (int c=0;c<5;c++){
                gg[c].x += __shfl_down_sync(0xffffffffu, gg[c].x, 2);
                gg[c].y += __shfl_down_sync(0xffffffffu, gg[c].y, 2);
                gg[c].z += __shfl_down_sync(0xffffffffu, gg[c].z, 2);
                gg[c].w += __shfl_down_sync(0xffffffffu, gg[c].w, 2);
                gg[c].x += __shfl_down_sync(0xffffffffu, gg[c].x, 1);
                gg[c].y += __shfl_down_sync(0xffffffffu, gg[c].y, 1);
                gg[c].z += __shfl_down_sync(0xffffffffu, gg[c].z, 1);
                gg[c].w += __shfl_down_sync(0xffffffffu, gg[c].w, 1);
            }
            if (sub == 0){
                float4 cold = *(const float4*)(g_c + b*HID + j);
                float co[4] = {cold.x, cold.y, cold.z, cold.w};
                float iv4[4] = {gg[0].x,gg[0].y,gg[0].z,gg[0].w};
                float fv4[4] = {gg[1].x,gg[1].y,gg[1].z,gg[1].w};
                float gv4[4] = {gg[2].x,gg[2].y,gg[2].z,gg[2].w};
                float ov4[4] = {gg[3].x,gg[3].y,gg[3].z,gg[3].w};
                float n54[4] = {gg[4].x,gg[4].y,gg[4].z,gg[4].w};
                float cn4[4], hn4[4], f04[4];
#pragma unroll
                for (int e=0;e<4;e++){
                    float cn = sigf(fv4[e])*co[e] + sigf(iv4[e])*tanhf(gv4[e]);
                    float tc = tanhf(cn);
                    cn4[e] = cn;
                    hn4[e] = sigf(ov4[e])*tc;
                    f04[e] = sigf(n54[e])*tc;
                }
                *(float4*)(g_c   + b*HID + j) = make_float4(cn4[0],cn4[1],cn4[2],cn4[3]);
                *(float4*)(g_A   + b*KST + HID + j) = make_float4(hn4[0],hn4[1],hn4[2],hn4[3]);
                *(float4*)(g_fr0 + b*HID + j) = make_float4(f04[0],f04[1],f04[2],f04[3]);
            }
        }
        gridbar(bgen, grp);

        // ======== P3: fr0@Wfr and h@Who partials (128 tasks) ========
        {
            int ks = blk & 15, nt = (blk>>4)&3, mat = blk>>6;
            const float* A = mat ? (g_A + HID) : g_fr0;
            int lda = mat ? KST : HID;
            const float* W = mat ? Who : Wfr;
            gtask_mma(A, lda, W, HID, nt*128, ks*32,
                  g_p3 + (size_t)mat*(16*BB*HID) + (size_t)ks*(BB*HID), HID,
                  nullptr, nullptr, -1);
        }
        gridbar(bgen, grp);

        // ======== P4: fr@Wfre, hol@Whoe partials (A staged from p3) ========
        {
            int ks = blk & 15, nt = (blk>>4)&3, mat = blk>>6;
            const float* W = mat ? Whoe : Wfre;
            gtask_mma(nullptr, 0, W, HID, nt*128, ks*32,
                  g_p4 + (size_t)mat*(16*BB*HID) + (size_t)ks*(BB*HID), HID,
                  g_p3 + (size_t)mat*(16*BB*HID), mat ? bho : bfr, mat ? 2 : 1);
        }
        gridbar(bgen, grp);

        // ======== P5: attention scores (smem ctx; hoe/fre staged from p4) ========
        {
            if (tid < 128){
                int j = tid*4;
                float4 s = *(const float4*)(bhoe + j);
#pragma unroll
                for (int p=0;p<16;p++){
                    const float4 v = *(const float4*)(g_p4 + (size_t)(16+p)*(BB*HID) + bq*HID + j);
                    s.x+=v.x; s.y+=v.y; s.z+=v.z; s.w+=v.w;
                }
                *(float4*)&dsh[SOFF_HOE + j] = s;
            } else if (qq == 0){
                int j = (tid-128)*4;
                float4 s = *(const float4*)(bfre + j);
#pragma unroll
                for (int p=0;p<16;p++){
                    const float4 v = *(const float4*)(g_p4 + (size_t)p*(BB*HID) + bq*HID + j);
                    s.x+=v.x; s.y+=v.y; s.z+=v.z; s.w+=v.w;
                }
                *(float4*)&dsh[SOFF_FRE + j] = s;
            }
            __syncthreads();
            int w = tid>>5;
            float4 hv0 = *(const float4*)&dsh[SOFF_HOE + 0*128 + l*4];
            float4 hv1 = *(const float4*)&dsh[SOFF_HOE + 1*128 + l*4];
            float4 hv2 = *(const float4*)&dsh[SOFF_HOE + 2*128 + l*4];
            float4 hv3 = *(const float4*)&dsh[SOFF_HOE + 3*128 + l*4];
#pragma unroll
            for (int it=0; it<8; it++){
                int al = it*8 + w;
                const float* e = dsh + al*512;
                float acc = 0.f;
                float4 ev;
                ev = *(const float4*)&e[0*128 + l*4];
                acc += wa0.x*tanha(ev.x+hv0.x); acc += wa0.y*tanha(ev.y+hv0.y);
                acc += wa0.z*tanha(ev.z+hv0.z); acc += wa0.w*tanha(ev.w+hv0.w);
                ev = *(const float4*)&e[1*128 + l*4];
                acc += wa1.x*tanha(ev.x+hv1.x); acc += wa1.y*tanha(ev.y+hv1.y);
                acc += wa1.z*tanha(ev.z+hv1.z); acc += wa1.w*tanha(ev.w+hv1.w);
                ev = *(const float4*)&e[2*128 + l*4];
                acc += wa2.x*tanha(ev.x+hv2.x); acc += wa2.y*tanha(ev.y+hv2.y);
                acc += wa2.z*tanha(ev.z+hv2.z); acc += wa2.w*tanha(ev.w+hv2.w);
                ev = *(const float4*)&e[3*128 + l*4];
                acc += wa3.x*tanha(ev.x+hv3.x); acc += wa3.y*tanha(ev.y+hv3.y);
                acc += wa3.z*tanha(ev.z+hv3.z); acc += wa3.w*tanha(ev.w+hv3.w);
#pragma unroll
                for (int off=16; off; off>>=1) acc += __shfl_xor_sync(0xffffffffu, acc, off);
                if (l == 0) g_scores[bq*NA + qq*64 + al + 1] = acc + ba0;
            }
            if (qq == 0 && w == 0){
                float acc = 0.f;
                float4 ev;
                ev = *(const float4*)&dsh[SOFF_FRE + 0*128 + l*4];
                acc += wa0.x*tanha(ev.x+hv0.x); acc += wa0.y*tanha(ev.y+hv0.y);
                acc += wa0.z*tanha(ev.z+hv0.z); acc += wa0.w*tanha(ev.w+hv0.w);
                ev = *(const float4*)&dsh[SOFF_FRE + 1*128 + l*4];
                acc += wa1.x*tanha(ev.x+hv1.x); acc += wa1.y*tanha(ev.y+hv1.y);
                acc += wa1.z*tanha(ev.z+hv1.z); acc += wa1.w*tanha(ev.w+hv1.w);
                ev = *(const float4*)&dsh[SOFF_FRE + 2*128 + l*4];
                acc += wa2.x*tanha(ev.x+hv2.x); acc += wa2.y*tanha(ev.y+hv2.y);
                acc += wa2.z*tanha(ev.z+hv2.z); acc += wa2.w*tanha(ev.w+hv2.w);
                ev = *(const float4*)&dsh[SOFF_FRE + 3*128 + l*4];
                acc += wa3.x*tanha(ev.x+hv3.x); acc += wa3.y*tanha(ev.y+hv3.y);
                acc += wa3.z*tanha(ev.z+hv3.z); acc += wa3.w*tanha(ev.w+hv3.w);
#pragma unroll
                for (int off=16; off; off>>=1) acc += __shfl_xor_sync(0xffffffffu, acc, off);
                if (l == 0) g_scores[bq*NA] = acc + ba0;
            }
        }
        gridbar(bgen, grp);

        // ======== P6: softmax + vis (fr, hol reduced inline) -> visph ========
        {
            float* s_sc  = dsh + SOFF_GT;
            float* s_red = dsh + SOFF_GT + 272;
            float* s_v   = dsh + SOFF_GT + 544;
            s_sc[tid] = g_scores[bq*NA + tid];
            if (tid == 0) s_sc[256] = g_scores[bq*NA + 256];
            __syncthreads();
            float mv = s_sc[tid];
            if (tid == 0) mv = fmaxf(mv, s_sc[256]);
            s_red[tid] = mv; __syncthreads();
            for (int st=128; st; st>>=1){ if (tid<st) s_red[tid] = fmaxf(s_red[tid], s_red[tid+st]); __syncthreads(); }
            float mx = s_red[0]; __syncthreads();
            float ev  = expf(s_sc[tid] - mx);
            float ev2 = (tid==0) ? expf(s_sc[256] - mx) : 0.f;
            s_red[tid] = ev + ev2; __syncthreads();
            for (int st=128; st; st>>=1){ if (tid<st) s_red[tid] += s_red[tid+st]; __syncthreads(); }
            float inv = 1.f / s_red[0];
            __syncthreads();
            s_sc[tid] = ev * inv;
            if (tid == 0) s_sc[256] = ev2 * inv;
            __syncthreads();
            int aa = tid>>5, hq = tid&31;
            int h = qq*128 + hq*4;
            float4 acc = make_float4(0.f,0.f,0.f,0.f);
            int astart = aa;
            if (aa == 0){
                float4 s = *(const float4*)(bfr + h);
#pragma unroll
                for (int p=0;p<16;p++){
                    const float4 v = *(const float4*)(g_p3 + (size_t)p*(BB*HID) + bq*HID + h);
                    s.x+=v.x; s.y+=v.y; s.z+=v.z; s.w+=v.w;
                }
                s.x=fmaxf(s.x,0.f); s.y=fmaxf(s.y,0.f); s.z=fmaxf(s.z,0.f); s.w=fmaxf(s.w,0.f);
                float w0 = s_sc[0];
                acc.x = w0*s.x; acc.y = w0*s.y; acc.z = w0*s.z; acc.w = w0*s.w;
                astart = 8;
            }
            for (int a = astart; a < NA; a += 8){
                float w = s_sc[a];
                float4 v = *(const float4*)(cnn + ((size_t)bq*ATTN + (a-1))*CTXD + h);
                acc.x += w*v.x; acc.y += w*v.y; acc.z += w*v.z; acc.w += w*v.w;
            }
            *(float4*)&s_v[aa*128 + hq*4] = acc;
            __syncthreads();
            if (tid < 32){
                int h2 = qq*128 + tid*4;
                float4 s = make_float4(0.f,0.f,0.f,0.f);
#pragma unroll
                for (int a2=0;a2<8;a2++){
                    const float4 v = *(const float4*)&s_v[a2*128 + tid*4];
                    s.x+=v.x; s.y+=v.y; s.z+=v.z; s.w+=v.w;
                }
                float4 ho = *(const float4*)(bho + h2);
#pragma unroll
                for (int p=0;p<16;p++){
                    const float4 v = *(const float4*)(g_p3 + (size_t)(16+p)*(BB*HID) + bq*HID + h2);
                    ho.x+=v.x; ho.y+=v.y; ho.z+=v.z; ho.w+=v.w;
                }
                s.x += tanhf(ho.x); s.y += tanhf(ho.y); s.z += tanhf(ho.z); s.w += tanhf(ho.w);
                *(float4*)(g_visph + bq*HID + h2) = s;
            }
            __syncthreads();
        }
        gridbar(bgen, grp);

        // ======== P7: outh partials (64 tasks) ========
        if (blk < 64){
            int ks = blk & 15, nt = blk>>4;
            gtask_mma(g_visph, HID, Watt, HID, nt*128, ks*32,
                  g_p7 + (size_t)ks*(BB*HID), HID, nullptr, nullptr, -1);
        }
        gridbar(bgen, grp);
    }

    // ---- epilogue: finalize out(TT-1) into g_outh[TT-1]
    if (tid < 32){
        int quad = blk*32 + tid;
        int b = quad>>7, j = (quad&127)<<2;
        float4 s = *(const float4*)(batt + j);
#pragma unroll
        for (int p=0;p<16;p++){
            const float4 v = *(const float4*)(g_p7 + (size_t)p*(BB*HID) + b*HID + j);
            s.x+=v.x; s.y+=v.y; s.z+=v.z; s.w+=v.w;
        }
        s.x=tanhf(s.x); s.y=tanhf(s.y); s.z=tanhf(s.z); s.w=tanhf(s.w);
        *(float4*)(g_outh + (size_t)(TT-1)*(BB*HID) + b*HID + j) = s;
    }
}

// ---------------- log_softmax + [t][b] -> [b][t] remap ----------------
__global__ void k_logsm(float* __restrict__ out){
    int r = blockIdx.x;
    int t = r >> 5, b = r & 31;
    const float* row = g_logits + (size_t)r*VOC;
    float* orow = out + ((size_t)b*TT + t)*VOC;
    __shared__ float red[256];
    int tid = threadIdx.x;
    float mx = -1e30f;
    for (int i=tid; i<VOC; i+=256) mx = fmaxf(mx, row[i]);
    red[tid] = mx; __syncthreads();
    for (int st=128; st>0; st>>=1){ if (tid<st) red[tid] = fmaxf(red[tid], red[tid+st]); __syncthreads(); }
    mx = red[0]; __syncthreads();
    float sm = 0.f;
    for (int i=tid; i<VOC; i+=256) sm += expf(row[i] - mx);
    red[tid] = sm; __syncthreads();
    for (int st=128; st>0; st>>=1){ if (tid<st) red[tid] += red[tid+st]; __syncthreads(); }
    float ls = mx + logf(red[0]);
    for (int i=tid; i<VOC; i+=256) orow[i] = row[i] - ls;
}

// ---------------- launch ----------------
extern "C" void kernel_launch(void* const* d_in, const int* in_sizes, int n_in,
                              void* d_out, int out_size){
    const float* cnn  = (const float*)d_in[0];
    const int*   seq  = (const int*)  d_in[1];
    const float* emb  = (const float*)d_in[2];
    const float* Wce  = (const float*)d_in[3];  const float* bce  = (const float*)d_in[4];
    const float* Wih  = (const float*)d_in[5];  const float* bih  = (const float*)d_in[6];
    const float* Whh  = (const float*)d_in[7];  const float* bhh  = (const float*)d_in[8];
    const float* Wi2h = (const float*)d_in[9];  const float* bi2h = (const float*)d_in[10];
    const float* Wh2h = (const float*)d_in[11]; const float* bh2h = (const float*)d_in[12];
    const float* Wfr  = (const float*)d_in[13]; const float* bfr  = (const float*)d_in[14];
    const float* Wfre = (const float*)d_in[15]; const float* bfre = (const float*)d_in[16];
    const float* Who  = (const float*)d_in[17]; const float* bho  = (const float*)d_in[18];
    const float* Whoe = (const float*)d_in[19]; const float* bhoe = (const float*)d_in[20];
    const float* Wa   = (const float*)d_in[21]; const float* ba   = (const float*)d_in[22];
    const float* Watt = (const float*)d_in[23]; const float* batt = (const float*)d_in[24];
    const float* Wlog = (const float*)d_in[25]; const float* blog = (const float*)d_in[26];
    float* out = (float*)d_out;

    cudaFuncSetAttribute(persist_kernel, cudaFuncAttributeMaxDynamicSharedMemorySize,
                         SMEM_FLOATS*4);

    k_init<<<192, 256>>>();
    k_packW<<<(KST*NG)/256, 256>>>(Wih, Whh, Wi2h, Wh2h);
    k_packX<<<(EMBD*NG)/256, 256>>>(Wih, Wi2h, bih, bhh, bi2h, bh2h);
    k_gather<<<(TT*BB*EMBD)/256, 256>>>(seq, emb);
    k_gemm_tf32<<<dim3(CTXD/64, (BB*ATTN)/128), 256>>>(0, cnn, Wce, bce, CTXD, CTXD, 1);
    k_gemm_tf32<<<dim3(NG/64, (TT*BB)/128), 256>>>(1, nullptr, nullptr, nullptr, NG, EMBD, 0);

    persist_kernel<<<GB, 256, SMEM_FLOATS*4>>>(cnn, Wfr, bfr, Who, bho, Wfre, bfre,
                                               Whoe, bhoe, Wa, ba, Watt, batt);

    k_gemm_tf32<<<dim3((VOC+63)/64, (TT*BB)/128), 256>>>(2, nullptr, Wlog, blog, VOC, HID, 0);
    k_logsm<<<TT*BB, 256>>>(out);
}

// round 13
// speedup vs baseline: 2.0221x; 1.1342x over previous
#include <cuda_runtime.h>
#include <math.h>
#include <stdint.h>

#define BB 32
#define HID 512
#define CTXD 512
#define EMBD 256
#define ATTN 256
#define VOC 5000
#define TT 160
#define NG 2560
#define KST 1024
#define NA 257
#define GB 128           // persistent grid blocks

// ---------------- device scratch (static; no allocation) ----------------
__device__ float g_ctx_embed[BB*ATTN*CTXD];
__device__ float g_xproj[TT*BB*NG];
__device__ float g_Xemb[TT*BB*EMBD];
__device__ float g_Wpack[KST*NG];
__device__ float g_WxPack[EMBD*NG];
__device__ float g_biasPack[NG];
__device__ float g_A[BB*KST];          // [unused(512) | h(512)]
__device__ float g_c[BB*HID];
__device__ float g_gp[32*BB*NG];       // gates partials: 32 splitK buckets
__device__ float g_p3[2*16*BB*HID];    // fr0@Wfr, h@Who partials
__device__ float g_p4[2*16*BB*HID];    // fr@Wfre, hol@Whoe partials
__device__ float g_p7[16*BB*HID];      // visph@Watt partials
__device__ float g_fr0[BB*HID];
__device__ float g_scores[BB*NA];
__device__ float g_visph[BB*HID];
__device__ float g_outh[TT*BB*HID];
__device__ float g_logits[TT*BB*VOC];

// flat grid barrier state (round-9 validated optimum)
__device__ unsigned g_barg;
__device__ unsigned g_barc;

// dynamic shared layout (floats):
// [0      .. 32768)  s_ctx  : 64 x 512 ctx_embed slice (step-invariant)
// [32768  .. 33280)  s_hoe  : 512
// [33280  .. 33792)  s_fre  : 512
// [33792  .. 39168)  gtask region: sA 32x36 (1152) + sW 32x132 (4224); P6 aliases this
extern __shared__ float dsh[];
#define SOFF_HOE 32768
#define SOFF_FRE 33280
#define SOFF_GT  33792
#define SW_PITCH 132
#define SMEM_FLOATS 39168

__device__ __forceinline__ float sigf(float x){ return 1.f/(1.f+expf(-x)); }
__device__ __forceinline__ float tanha(float x){ float y; asm("tanh.approx.f32 %0, %1;" : "=f"(y) : "f"(x)); return y; }
__device__ __forceinline__ uint32_t f2tf32(float x){
    uint32_t u; asm("cvt.rna.tf32.f32 %0, %1;" : "=r"(u) : "f"(x)); return u;
}
__device__ __forceinline__ uint4 f4tf32(float4 v){
    uint4 t; t.x=f2tf32(v.x); t.y=f2tf32(v.y); t.z=f2tf32(v.z); t.w=f2tf32(v.w); return t;
}
#define MMA_TF32(d, a, b) \
    asm volatile("mma.sync.aligned.m16n8k8.row.col.f32.tf32.tf32.f32 " \
        "{%0,%1,%2,%3}, {%4,%5,%6,%7}, {%8,%9}, {%0,%1,%2,%3};" \
        : "+f"((d)[0]), "+f"((d)[1]), "+f"((d)[2]), "+f"((d)[3]) \
        : "r"((a)[0]), "r"((a)[1]), "r"((a)[2]), "r"((a)[3]), "r"((b)[0]), "r"((b)[1]))

// ---------------- setup kernels ----------------
__global__ void k_init(){
    int i = blockIdx.x*256 + threadIdx.x;
    if (i < BB*KST) g_A[i] = 0.f;
    if (i < BB*HID) g_c[i] = 0.f;
}

__global__ void k_packW(const float* __restrict__ Wih, const float* __restrict__ Whh,
                        const float* __restrict__ Wi2h, const float* __restrict__ Wh2h){
    int idx = blockIdx.x*256 + threadIdx.x;   // exactly KST*NG
    int k = idx / NG, n = idx % NG;
    float v;
    if (k < HID) v = (n < 4*HID) ? Wih[(size_t)(EMBD+k)*4*HID + n] : Wi2h[(size_t)(EMBD+k)*HID + (n-4*HID)];
    else         v = (n < 4*HID) ? Whh[(size_t)(k-HID)*4*HID + n]  : Wh2h[(size_t)(k-HID)*HID + (n-4*HID)];
    g_Wpack[idx] = v;
}

__global__ void k_packX(const float* __restrict__ Wih, const float* __restrict__ Wi2h,
                        const float* __restrict__ bih, const float* __restrict__ bhh,
                        const float* __restrict__ bi2h, const float* __restrict__ bh2h){
    int idx = blockIdx.x*256 + threadIdx.x;   // exactly EMBD*NG
    if (idx < NG)
        g_biasPack[idx] = (idx < 4*HID) ? (bih[idx] + bhh[idx]) : (bi2h[idx-4*HID] + bh2h[idx-4*HID]);
    int k = idx / NG, n = idx % NG;
    g_WxPack[idx] = (n < 4*HID) ? Wih[(size_t)k*4*HID + n] : Wi2h[(size_t)k*HID + (n-4*HID)];
}

__global__ void k_gather(const int* __restrict__ seq, const float* __restrict__ embed){
    int idx = blockIdx.x*256 + threadIdx.x;   // exactly TT*BB*EMBD
    int e = idx & (EMBD-1);
    int r = idx >> 8;
    int t = r >> 5, b = r & 31;
    int tok = seq[b*161 + t];
    g_Xemb[idx] = embed[(size_t)tok*EMBD + e];
}

// ---------------- generic tf32 tensor-core GEMM (pre-GEMMs + logits) ----------------
// C[M,N] = act(A[M,K] @ W[K,N] + bias). M % 128 == 0, K % 32 == 0.
// mode 0: ctx_embed = relu(cnn@Wce+bce); mode 1: xproj; mode 2: logits.
__global__ void __launch_bounds__(256) k_gemm_tf32(int mode,
        const float* __restrict__ Aext, const float* __restrict__ Wext,
        const float* __restrict__ bext, int N, int K, int act){
    const float* A; const float* W; const float* bias; float* C; int lda, ldw, ldc;
    if (mode == 0){ A=Aext;   W=Wext;     bias=bext;       C=g_ctx_embed; lda=512; ldw=512; ldc=512; }
    else if (mode==1){ A=g_Xemb; W=g_WxPack; bias=g_biasPack; C=g_xproj;  lda=256; ldw=NG;  ldc=NG;  }
    else            { A=g_outh;  W=Wext;     bias=bext;       C=g_logits; lda=512; ldw=VOC; ldc=VOC; }

    __shared__ uint32_t sA[128*36];
    __shared__ uint32_t sB[32*68];
    int tid = threadIdx.x;
    int row0 = blockIdx.y*128, col0 = blockIdx.x*64;
    int w = tid>>5, lane = tid&31;
    int wm = w&3, wn = w>>2;
    int gid = lane>>2, sub = lane&3;

    float acc[2][4][4];
#pragma unroll
    for (int mt=0; mt<2; mt++)
#pragma unroll
        for (int nt=0; nt<4; nt++)
#pragma unroll
            for (int i=0;i<4;i++) acc[mt][nt][i]=0.f;

    for (int k0=0; k0<K; k0+=32){
#pragma unroll
        for (int r=0;r<4;r++){
            int f = tid + r*256;
            int m = f>>3, kq = (f&7)<<2;
            float4 v = *(const float4*)(A + (size_t)(row0+m)*lda + k0 + kq);
            *(uint4*)&sA[m*36+kq] = f4tf32(v);
        }
#pragma unroll
        for (int r=0;r<2;r++){
            int f = tid + r*256;
            int kr = f>>4, cq = (f&15)<<2;
            int c = col0 + cq;
            float4 v;
            if (c + 3 < N){
                v = *(const float4*)(W + (size_t)(k0+kr)*ldw + c);
            } else {
                v.x = (c   < N) ? W[(size_t)(k0+kr)*ldw + c  ] : 0.f;
                v.y = (c+1 < N) ? W[(size_t)(k0+kr)*ldw + c+1] : 0.f;
                v.z = (c+2 < N) ? W[(size_t)(k0+kr)*ldw + c+2] : 0.f;
                v.w = (c+3 < N) ? W[(size_t)(k0+kr)*ldw + c+3] : 0.f;
            }
            *(uint4*)&sB[kr*68+cq] = f4tf32(v);
        }
        __syncthreads();
#pragma unroll
        for (int ks=0; ks<4; ks++){
            int kb = ks*8;
            uint32_t a[2][4];
#pragma unroll
            for (int mt=0; mt<2; mt++){
                int rbase = wm*32 + mt*16;
                a[mt][0] = sA[(rbase+gid  )*36 + kb+sub  ];
                a[mt][1] = sA[(rbase+gid+8)*36 + kb+sub  ];
                a[mt][2] = sA[(rbase+gid  )*36 + kb+sub+4];
                a[mt][3] = sA[(rbase+gid+8)*36 + kb+sub+4];
            }
            uint32_t b[4][2];
#pragma unroll
            for (int nt=0; nt<4; nt++){
                int cbase = wn*32 + nt*8 + gid;
                b[nt][0] = sB[(kb+sub  )*68 + cbase];
                b[nt][1] = sB[(kb+sub+4)*68 + cbase];
            }
#pragma unroll
            for (int mt=0; mt<2; mt++)
#pragma unroll
                for (int nt=0; nt<4; nt++)
                    MMA_TF32(acc[mt][nt], a[mt], b[nt]);
        }
        __syncthreads();
    }
#pragma unroll
    for (int mt=0; mt<2; mt++){
        int r = row0 + wm*32 + mt*16 + gid;
#pragma unroll
        for (int nt=0; nt<4; nt++){
            int c = col0 + wn*32 + nt*8 + sub*2;
#pragma unroll
            for (int half=0; half<2; half++){
                int rr = r + half*8;
                float v0 = acc[mt][nt][half*2+0];
                float v1 = acc[mt][nt][half*2+1];
                if (c+1 < N){
                    v0 += bias[c]; v1 += bias[c+1];
                    if (act == 1){ v0 = fmaxf(v0,0.f); v1 = fmaxf(v1,0.f); }
                    *(float2*)(C + (size_t)rr*ldc + c) = make_float2(v0, v1);
                } else if (c < N){
                    v0 += bias[c];
                    if (act == 1) v0 = fmaxf(v0,0.f);
                    C[(size_t)rr*ldc + c] = v0;
                }
            }
        }
    }
}

// ---------------- flat grid barrier (round-9 validated: acquire/release, continuous spin) ----
__device__ __forceinline__ void gridbar(){
    __syncthreads();
    if (threadIdx.x == 0){
        unsigned gen;
        asm volatile("ld.relaxed.gpu.global.u32 %0, [%1];" : "=r"(gen) : "l"(&g_barg));
        unsigned old;
        asm volatile("atom.acq_rel.gpu.global.add.u32 %0, [%1], %2;"
                     : "=r"(old) : "l"(&g_barc), "r"(1u) : "memory");
        if (old == (unsigned)(GB-1)){
            g_barc = 0u;
            unsigned ng = gen + 1u;
            asm volatile("st.release.gpu.global.u32 [%0], %1;" :: "l"(&g_barg), "r"(ng) : "memory");
        } else {
            unsigned cur;
            do {
                asm volatile("ld.acquire.gpu.global.u32 %0, [%1];" : "=r"(cur) : "l"(&g_barg) : "memory");
            } while (cur == gen);
        }
    }
    __syncthreads();
}

// One GEMM task via tf32 mma: out[0:32, col0:+128] (partial) = A[0:32, k0:+32] @ W[k0:+32, col0:+128]
// stage_mode: -1 load A directly; 1 relu(sum16 partials + bias); 2 tanh(...).
__device__ __forceinline__ void gtask_mma(const float* A, int lda,
                                          const float* W, int ldw,
                                          int col0, int k0,
                                          float* out, int ldo,
                                          const float* stage_base, const float* stage_bias,
                                          int stage_mode){
    uint32_t* sA = (uint32_t*)(dsh + SOFF_GT);            // pitch 36
    uint32_t* sW = (uint32_t*)(dsh + SOFF_GT + 1152);     // pitch 132
    int tid = threadIdx.x;
    {
        int m = tid>>3, kq = (tid&7)<<2;
        float4 av;
        if (stage_mode < 0){
            av = *(const float4*)(A + (size_t)m*lda + k0 + kq);
        } else {
            float4 s = *(const float4*)(stage_bias + k0 + kq);
#pragma unroll
            for (int p=0;p<16;p++){
                const float4 v = *(const float4*)(stage_base + p*(BB*HID) + m*HID + k0 + kq);
                s.x+=v.x; s.y+=v.y; s.z+=v.z; s.w+=v.w;
            }
            if (stage_mode == 1){ s.x=fmaxf(s.x,0.f); s.y=fmaxf(s.y,0.f); s.z=fmaxf(s.z,0.f); s.w=fmaxf(s.w,0.f); }
            else                { s.x=tanhf(s.x); s.y=tanhf(s.y); s.z=tanhf(s.z); s.w=tanhf(s.w); }
            av = s;
        }
        *(uint4*)&sA[m*36 + kq] = f4tf32(av);
    }
#pragma unroll
    for (int rep=0;rep<4;rep++){
        int f = tid + rep*256;
        int row = f>>5, j4 = (f&31)<<2;
        float4 v = *(const float4*)(W + (size_t)(k0+row)*ldw + col0 + j4);
        *(uint4*)&sW[row*SW_PITCH + j4] = f4tf32(v);
    }
    __syncthreads();
    int w = tid>>5, lane = tid&31, gid = lane>>2, sub = lane&3;
    float acc[2][2][4];
#pragma unroll
    for (int mt=0;mt<2;mt++)
#pragma unroll
        for (int nt=0;nt<2;nt++)
#pragma unroll
            for (int i=0;i<4;i++) acc[mt][nt][i]=0.f;
#pragma unroll
    for (int kb=0; kb<32; kb+=8){
        uint32_t a[2][4];
#pragma unroll
        for (int mt=0; mt<2; mt++){
            int rbase = mt*16;
            a[mt][0] = sA[(rbase+gid  )*36 + kb+sub  ];
            a[mt][1] = sA[(rbase+gid+8)*36 + kb+sub  ];
            a[mt][2] = sA[(rbase+gid  )*36 + kb+sub+4];
            a[mt][3] = sA[(rbase+gid+8)*36 + kb+sub+4];
        }
        uint32_t b[2][2];
#pragma unroll
        for (int nt=0; nt<2; nt++){
            int cbase = w*16 + nt*8 + gid;
            b[nt][0] = sW[(kb+sub  )*SW_PITCH + cbase];
            b[nt][1] = sW[(kb+sub+4)*SW_PITCH + cbase];
        }
#pragma unroll
        for (int mt=0; mt<2; mt++)
#pragma unroll
            for (int nt=0; nt<2; nt++)
                MMA_TF32(acc[mt][nt], a[mt], b[nt]);
    }
    __syncthreads();
#pragma unroll
    for (int mt=0; mt<2; mt++){
        int r = mt*16 + gid;
#pragma unroll
        for (int nt=0; nt<2; nt++){
            int c = col0 + w*16 + nt*8 + sub*2;
            *(float2*)(out + (size_t)r*ldo + c)     = make_float2(acc[mt][nt][0], acc[mt][nt][1]);
            *(float2*)(out + (size_t)(r+8)*ldo + c) = make_float2(acc[mt][nt][2], acc[mt][nt][3]);
        }
    }
}

__global__ void __launch_bounds__(256, 1) persist_kernel(
        const float* __restrict__ cnn,
        const float* __restrict__ Wfr,  const float* __restrict__ bfr,
        const float* __restrict__ Who,  const float* __restrict__ bho,
        const float* __restrict__ Wfre, const float* __restrict__ bfre,
        const float* __restrict__ Whoe, const float* __restrict__ bhoe,
        const float* __restrict__ Wa,   const float* __restrict__ ba,
        const float* __restrict__ Watt, const float* __restrict__ batt){
    int tid = threadIdx.x;
    int blk = blockIdx.x;
    int bq  = blk>>2, qq = blk&3;      // P5/P6 block role: (batch, quarter)
    int l   = tid&31;
    uint32_t* sAu = (uint32_t*)(dsh + SOFF_GT);
    uint32_t* sWu = (uint32_t*)(dsh + SOFF_GT + 1152);

    // ---- one-time preload: ctx_embed slice into smem; Wa into regs
    for (int i = tid; i < 8192; i += 256){
        ((float4*)dsh)[i] = *(const float4*)(g_ctx_embed
            + ((size_t)bq*ATTN + qq*64 + (i>>7))*CTXD + (i&127)*4);
    }
    float4 wa0 = *(const float4*)(Wa + 0*128 + l*4);
    float4 wa1 = *(const float4*)(Wa + 1*128 + l*4);
    float4 wa2 = *(const float4*)(Wa + 2*128 + l*4);
    float4 wa3 = *(const float4*)(Wa + 3*128 + l*4);
    float ba0 = ba[0];
    gridbar();

    for (int t=0; t<TT; t++){
        // ======== P1: gates partials (640 tasks, 5/block), pipelined, tf32 mma ========
        {
            int m = tid>>3, kq = (tid&7)<<2;
            int wrow = tid>>5, wj4 = (tid&31)*4;
            float4 pA, pW0, pW1, pW2, pW3;
            {
                int task = blk; int ks = task/20, nt = task%20;
                int k0 = ks*32, col0 = nt*128;
                if (ks < 16){
                    if (t == 0) pA = make_float4(0.f,0.f,0.f,0.f);
                    else {
                        float4 s = *(const float4*)(batt + k0 + kq);
#pragma unroll
                        for (int p=0;p<16;p++){
                            const float4 v = *(const float4*)(g_p7 + (size_t)p*(BB*HID) + m*HID + k0 + kq);
                            s.x+=v.x; s.y+=v.y; s.z+=v.z; s.w+=v.w;
                        }
                        s.x=tanhf(s.x); s.y=tanhf(s.y); s.z=tanhf(s.z); s.w=tanhf(s.w);
                        pA = s;
                    }
                } else pA = *(const float4*)(g_A + (size_t)m*KST + k0 + kq);
                const float* wb = g_Wpack + (size_t)k0*NG + col0;
                pW0 = *(const float4*)(wb + (size_t)(wrow   )*NG + wj4);
                pW1 = *(const float4*)(wb + (size_t)(wrow+ 8)*NG + wj4);
                pW2 = *(const float4*)(wb + (size_t)(wrow+16)*NG + wj4);
                pW3 = *(const float4*)(wb + (size_t)(wrow+24)*NG + wj4);
                if (ks < 16 && nt == 0 && t > 0)
                    *(float4*)(g_outh + (size_t)(t-1)*(BB*HID) + m*HID + k0 + kq) = pA;
                *(uint4*)&sAu[m*36 + kq] = f4tf32(pA);
                *(uint4*)&sWu[(wrow   )*SW_PITCH + wj4] = f4tf32(pW0);
                *(uint4*)&sWu[(wrow+ 8)*SW_PITCH + wj4] = f4tf32(pW1);
                *(uint4*)&sWu[(wrow+16)*SW_PITCH + wj4] = f4tf32(pW2);
                *(uint4*)&sWu[(wrow+24)*SW_PITCH + wj4] = f4tf32(pW3);
            }
            __syncthreads();
            for (int r=0; r<5; r++){
                if (r < 4){
                    int task = blk + (r+1)*GB; int ks = task/20, nt = task%20;
                    int k0 = ks*32, col0 = nt*128;
                    if (ks < 16){
                        if (t == 0) pA = make_float4(0.f,0.f,0.f,0.f);
                        else {
                            float4 s = *(const float4*)(batt + k0 + kq);
#pragma unroll
                            for (int p=0;p<16;p++){
                                const float4 v = *(const float4*)(g_p7 + (size_t)p*(BB*HID) + m*HID + k0 + kq);
                                s.x+=v.x; s.y+=v.y; s.z+=v.z; s.w+=v.w;
                            }
                            s.x=tanhf(s.x); s.y=tanhf(s.y); s.z=tanhf(s.z); s.w=tanhf(s.w);
                            pA = s;
                        }
                    } else pA = *(const float4*)(g_A + (size_t)m*KST + k0 + kq);
                    const float* wb = g_Wpack + (size_t)k0*NG + col0;
                    pW0 = *(const float4*)(wb + (size_t)(wrow   )*NG + wj4);
                    pW1 = *(const float4*)(wb + (size_t)(wrow+ 8)*NG + wj4);
                    pW2 = *(const float4*)(wb + (size_t)(wrow+16)*NG + wj4);
                    pW3 = *(const float4*)(wb + (size_t)(wrow+24)*NG + wj4);
                }
                {
                    int task = blk + r*GB; int ks = task/20, nt = task%20;
                    int col0 = nt*128;
                    float* outp = g_gp + (size_t)ks*(BB*NG);
                    int w = tid>>5, lane = tid&31, gid = lane>>2, sub = lane&3;
                    float acc[2][2][4];
#pragma unroll
                    for (int mt=0;mt<2;mt++)
#pragma unroll
                        for (int nt2=0;nt2<2;nt2++)
#pragma unroll
                            for (int i=0;i<4;i++) acc[mt][nt2][i]=0.f;
#pragma unroll
                    for (int kb=0; kb<32; kb+=8){
                        uint32_t a[2][4];
#pragma unroll
                        for (int mt=0; mt<2; mt++){
                            int rbase = mt*16;
                            a[mt][0] = sAu[(rbase+gid  )*36 + kb+sub  ];
                            a[mt][1] = sAu[(rbase+gid+8)*36 + kb+sub  ];
                            a[mt][2] = sAu[(rbase+gid  )*36 + kb+sub+4];
                            a[mt][3] = sAu[(rbase+gid+8)*36 + kb+sub+4];
                        }
                        uint32_t b[2][2];
#pragma unroll
                        for (int nt2=0; nt2<2; nt2++){
                            int cbase = w*16 + nt2*8 + gid;
                            b[nt2][0] = sWu[(kb+sub  )*SW_PITCH + cbase];
                            b[nt2][1] = sWu[(kb+sub+4)*SW_PITCH + cbase];
                        }
#pragma unroll
                        for (int mt=0; mt<2; mt++)
#pragma unroll
                            for (int nt2=0; nt2<2; nt2++)
                                MMA_TF32(acc[mt][nt2], a[mt], b[nt2]);
                    }
#pragma unroll
                    for (int mt=0; mt<2; mt++){
                        int rr = mt*16 + gid;
#pragma unroll
                        for (int nt2=0; nt2<2; nt2++){
                            int c = col0 + w*16 + nt2*8 + sub*2;
                            *(float2*)(outp + (size_t)rr*NG + c)     = make_float2(acc[mt][nt2][0], acc[mt][nt2][1]);
                            *(float2*)(outp + (size_t)(rr+8)*NG + c) = make_float2(acc[mt][nt2][2], acc[mt][nt2][3]);
                        }
                    }
                }
                __syncthreads();
                if (r < 4){
                    int task = blk + (r+1)*GB; int ks = task/20, nt = task%20;
                    int k0 = ks*32;
                    if (ks < 16 && nt == 0 && t > 0)
                        *(float4*)(g_outh + (size_t)(t-1)*(BB*HID) + m*HID + k0 + kq) = pA;
                    *(uint4*)&sAu[m*36 + kq] = f4tf32(pA);
                    *(uint4*)&sWu[(wrow   )*SW_PITCH + wj4] = f4tf32(pW0);
                    *(uint4*)&sWu[(wrow+ 8)*SW_PITCH + wj4] = f4tf32(pW1);
                    *(uint4*)&sWu[(wrow+16)*SW_PITCH + wj4] = f4tf32(pW2);
                    *(uint4*)&sWu[(wrow+24)*SW_PITCH + wj4] = f4tf32(pW3);
                    __syncthreads();
                }
            }
        }
        gridbar();

        // ======== P2: reduce gates + LSTM elementwise ========
        if (tid < 128){
            int idx = blk*128 + tid;
            int quad = idx>>2, sub = idx&3;
            int b = quad>>7, j = (quad&127)<<2;
            float4 gg[5];
#pragma unroll
            for (int c=0;c<5;c++){
                int col = c*HID + j;
                float4 x;
                if (sub == 0) x = *(const float4*)(g_xproj + (size_t)t*(BB*NG) + b*NG + col);
                else x = make_float4(0.f,0.f,0.f,0.f);
#pragma unroll
                for (int s=0;s<8;s++){
                    const float4 v = *(const float4*)(g_gp + (size_t)(sub*8+s)*(BB*NG) + b*NG + col);
                    x.x+=v.x; x.y+=v.y; x.z+=v.z; x.w+=v.w;
                }
                gg[c] = x;
            }
#pragma unroll
            for (int c=0;c<5;c++){
                gg[c].x += __shfl_down_sync(0xffffffffu, gg[c].x, 2);
                gg[c].y += __shfl_down_sync(0xffffffffu, gg[c].y, 2);
                gg[c].z += __shfl_down_sync(0xffffffffu, gg[c].z, 2);
                gg[c].w += __shfl_down_sync(0xffffffffu, gg[c].w, 2);
                gg[c].x += __shfl_down_sync(0xffffffffu, gg[c].x, 1);
                gg[c].y += __shfl_down_sync(0xffffffffu, gg[c].y, 1);
                gg[c].z += __shfl_down_sync(0xffffffffu, gg[c].z, 1);
                gg[c].w += __shfl_down_sync(0xffffffffu, gg[c].w, 1);
            }
            if (sub == 0){
                float4 cold = *(const float4*)(g_c + b*HID + j);
                float co[4] = {cold.x, cold.y, cold.z, cold.w};
                float iv4[4] = {gg[0].x,gg[0].y,gg[0].z,gg[0].w};
                float fv4[4] = {gg[1].x,gg[1].y,gg[1].z,gg[1].w};
                float gv4[4] = {gg[2].x,gg[2].y,gg[2].z,gg[2].w};
                float ov4[4] = {gg[3].x,gg[3].y,gg[3].z,gg[3].w};
                float n54[4] = {gg[4].x,gg[4].y,gg[4].z,gg[4].w};
                float cn4[4], hn4[4], f04[4];
#pragma unroll
                for (int e=0;e<4;e++){
                    float cn = sigf(fv4[e])*co[e] + sigf(iv4[e])*tanhf(gv4[e]);
                    float tc = tanhf(cn);
                    cn4[e] = cn;
                    hn4[e] = sigf(ov4[e])*tc;
                    f04[e] = sigf(n54[e])*tc;
                }
                *(float4*)(g_c   + b*HID + j) = make_float4(cn4[0],cn4[1],cn4[2],cn4[3]);
                *(float4*)(g_A   + b*KST + HID + j) = make_float4(hn4[0],hn4[1],hn4[2],hn4[3]);
                *(float4*)(g_fr0 + b*HID + j) = make_float4(f04[0],f04[1],f04[2],f04[3]);
            }
        }
        gridbar();

        // ======== P3: fr0@Wfr and h@Who partials (128 tasks) ========
        {
            int ks = blk & 15, nt = (blk>>4)&3, mat = blk>>6;
            const float* A = mat ? (g_A + HID) : g_fr0;
            int lda = mat ? KST : HID;
            const float* W = mat ? Who : Wfr;
            gtask_mma(A, lda, W, HID, nt*128, ks*32,
                  g_p3 + (size_t)mat*(16*BB*HID) + (size_t)ks*(BB*HID), HID,
                  nullptr, nullptr, -1);
        }
        gridbar();

        // ======== P4: fr@Wfre, hol@Whoe partials (A staged from p3) ========
        {
            int ks = blk & 15, nt = (blk>>4)&3, mat = blk>>6;
            const float* W = mat ? Whoe : Wfre;
            gtask_mma(nullptr, 0, W, HID, nt*128, ks*32,
                  g_p4 + (size_t)mat*(16*BB*HID) + (size_t)ks*(BB*HID), HID,
                  g_p3 + (size_t)mat*(16*BB*HID), mat ? bho : bfr, mat ? 2 : 1);
        }
        gridbar();

        // ======== P5: attention scores (smem ctx; hoe/fre staged from p4) ========
        {
            if (tid < 128){
                int j = tid*4;
                float4 s = *(const float4*)(bhoe + j);
#pragma unroll
                for (int p=0;p<16;p++){
                    const float4 v = *(const float4*)(g_p4 + (size_t)(16+p)*(BB*HID) + bq*HID + j);
                    s.x+=v.x; s.y+=v.y; s.z+=v.z; s.w+=v.w;
                }
                *(float4*)&dsh[SOFF_HOE + j] = s;
            } else if (qq == 0){
                int j = (tid-128)*4;
                float4 s = *(const float4*)(bfre + j);
#pragma unroll
                for (int p=0;p<16;p++){
                    const float4 v = *(const float4*)(g_p4 + (size_t)p*(BB*HID) + bq*HID + j);
                    s.x+=v.x; s.y+=v.y; s.z+=v.z; s.w+=v.w;
                }
                *(float4*)&dsh[SOFF_FRE + j] = s;
            }
            __syncthreads();
            int w = tid>>5;
            float4 hv0 = *(const float4*)&dsh[SOFF_HOE + 0*128 + l*4];
            float4 hv1 = *(const float4*)&dsh[SOFF_HOE + 1*128 + l*4];
            float4 hv2 = *(const float4*)&dsh[SOFF_HOE + 2*128 + l*4];
            float4 hv3 = *(const float4*)&dsh[SOFF_HOE + 3*128 + l*4];
#pragma unroll
            for (int it=0; it<8; it++){
                int al = it*8 + w;
                const float* e = dsh + al*512;
                float acc = 0.f;
                float4 ev;
                ev = *(const float4*)&e[0*128 + l*4];
                acc += wa0.x*tanha(ev.x+hv0.x); acc += wa0.y*tanha(ev.y+hv0.y);
                acc += wa0.z*tanha(ev.z+hv0.z); acc += wa0.w*tanha(ev.w+hv0.w);
                ev = *(const float4*)&e[1*128 + l*4];
                acc += wa1.x*tanha(ev.x+hv1.x); acc += wa1.y*tanha(ev.y+hv1.y);
                acc += wa1.z*tanha(ev.z+hv1.z); acc += wa1.w*tanha(ev.w+hv1.w);
                ev = *(const float4*)&e[2*128 + l*4];
                acc += wa2.x*tanha(ev.x+hv2.x); acc += wa2.y*tanha(ev.y+hv2.y);
                acc += wa2.z*tanha(ev.z+hv2.z); acc += wa2.w*tanha(ev.w+hv2.w);
                ev = *(const float4*)&e[3*128 + l*4];
                acc += wa3.x*tanha(ev.x+hv3.x); acc += wa3.y*tanha(ev.y+hv3.y);
                acc += wa3.z*tanha(ev.z+hv3.z); acc += wa3.w*tanha(ev.w+hv3.w);
#pragma unroll
                for (int off=16; off; off>>=1) acc += __shfl_xor_sync(0xffffffffu, acc, off);
                if (l == 0) g_scores[bq*NA + qq*64 + al + 1] = acc + ba0;
            }
            if (qq == 0 && w == 0){
                float acc = 0.f;
                float4 ev;
                ev = *(const float4*)&dsh[SOFF_FRE + 0*128 + l*4];
                acc += wa0.x*tanha(ev.x+hv0.x); acc += wa0.y*tanha(ev.y+hv0.y);
                acc += wa0.z*tanha(ev.z+hv0.z); acc += wa0.w*tanha(ev.w+hv0.w);
                ev = *(const float4*)&dsh[SOFF_FRE + 1*128 + l*4];
                acc += wa1.x*tanha(ev.x+hv1.x); acc += wa1.y*tanha(ev.y+hv1.y);
                acc += wa1.z*tanha(ev.z+hv1.z); acc += wa1.w*tanha(ev.w+hv1.w);
                ev = *(const float4*)&dsh[SOFF_FRE + 2*128 + l*4];
                acc += wa2.x*tanha(ev.x+hv2.x); acc += wa2.y*tanha(ev.y+hv2.y);
                acc += wa2.z*tanha(ev.z+hv2.z); acc += wa2.w*tanha(ev.w+hv2.w);
                ev = *(const float4*)&dsh[SOFF_FRE + 3*128 + l*4];
                acc += wa3.x*tanha(ev.x+hv3.x); acc += wa3.y*tanha(ev.y+hv3.y);
                acc += wa3.z*tanha(ev.z+hv3.z); acc += wa3.w*tanha(ev.w+hv3.w);
#pragma unroll
                for (int off=16; off; off>>=1) acc += __shfl_xor_sync(0xffffffffu, acc, off);
                if (l == 0) g_scores[bq*NA] = acc + ba0;
            }
        }
        gridbar();

        // ======== P6: softmax + vis (fr, hol reduced inline) -> visph ========
        {
            float* s_sc  = dsh + SOFF_GT;
            float* s_red = dsh + SOFF_GT + 272;
            float* s_v   = dsh + SOFF_GT + 544;
            s_sc[tid] = g_scores[bq*NA + tid];
            if (tid == 0) s_sc[256] = g_scores[bq*NA + 256];
            __syncthreads();
            float mv = s_sc[tid];
            if (tid == 0) mv = fmaxf(mv, s_sc[256]);
            s_red[tid] = mv; __syncthreads();
            for (int st=128; st; st>>=1){ if (tid<st) s_red[tid] = fmaxf(s_red[tid], s_red[tid+st]); __syncthreads(); }
            float mx = s_red[0]; __syncthreads();
            float ev  = expf(s_sc[tid] - mx);
            float ev2 = (tid==0) ? expf(s_sc[256] - mx) : 0.f;
            s_red[tid] = ev + ev2; __syncthreads();
            for (int st=128; st; st>>=1){ if (tid<st) s_red[tid] += s_red[tid+st]; __syncthreads(); }
            float inv = 1.f / s_red[0];
            __syncthreads();
            s_sc[tid] = ev * inv;
            if (tid == 0) s_sc[256] = ev2 * inv;
            __syncthreads();
            int aa = tid>>5, hq = tid&31;
            int h = qq*128 + hq*4;
            float4 acc = make_float4(0.f,0.f,0.f,0.f);
            int astart = aa;
            if (aa == 0){
                float4 s = *(const float4*)(bfr + h);
#pragma unroll
                for (int p=0;p<16;p++){
                    const float4 v = *(const float4*)(g_p3 + (size_t)p*(BB*HID) + bq*HID + h);
                    s.x+=v.x; s.y+=v.y; s.z+=v.z; s.w+=v.w;
                }
                s.x=fmaxf(s.x,0.f); s.y=fmaxf(s.y,0.f); s.z=fmaxf(s.z,0.f); s.w=fmaxf(s.w,0.f);
                float w0 = s_sc[0];
                acc.x = w0*s.x; acc.y = w0*s.y; acc.z = w0*s.z; acc.w = w0*s.w;
                astart = 8;
            }
            for (int a = astart; a < NA; a += 8){
                float w = s_sc[a];
                float4 v = *(const float4*)(cnn + ((size_t)bq*ATTN + (a-1))*CTXD + h);
                acc.x += w*v.x; acc.y += w*v.y; acc.z += w*v.z; acc.w += w*v.w;
            }
            *(float4*)&s_v[aa*128 + hq*4] = acc;
            __syncthreads();
            if (tid < 32){
                int h2 = qq*128 + tid*4;
                float4 s = make_float4(0.f,0.f,0.f,0.f);
#pragma unroll
                for (int a2=0;a2<8;a2++){
                    const float4 v = *(const float4*)&s_v[a2*128 + tid*4];
                    s.x+=v.x; s.y+=v.y; s.z+=v.z; s.w+=v.w;
                }
                float4 ho = *(const float4*)(bho + h2);
#pragma unroll
                for (int p=0;p<16;p++){
                    const float4 v = *(const float4*)(g_p3 + (size_t)(16+p)*(BB*HID) + bq*HID + h2);
                    ho.x+=v.x; ho.y+=v.y; ho.z+=v.z; ho.w+=v.w;
                }
                s.x += tanhf(ho.x); s.y += tanhf(ho.y); s.z += tanhf(ho.z); s.w += tanhf(ho.w);
                *(float4*)(g_visph + bq*HID + h2) = s;
            }
            __syncthreads();
        }
        gridbar();

        // ======== P7: outh partials (64 tasks) ========
        if (blk < 64){
            int ks = blk & 15, nt = blk>>4;
            gtask_mma(g_visph, HID, Watt, HID, nt*128, ks*32,
                  g_p7 + (size_t)ks*(BB*HID), HID, nullptr, nullptr, -1);
        }
        gridbar();
    }

    // ---- epilogue: finalize out(TT-1) into g_outh[TT-1]
    if (tid < 32){
        int quad = blk*32 + tid;
        int b = quad>>7, j = (quad&127)<<2;
        float4 s = *(const float4*)(batt + j);
#pragma unroll
        for (int p=0;p<16;p++){
            const float4 v = *(const float4*)(g_p7 + (size_t)p*(BB*HID) + b*HID + j);
            s.x+=v.x; s.y+=v.y; s.z+=v.z; s.w+=v.w;
        }
        s.x=tanhf(s.x); s.y=tanhf(s.y); s.z=tanhf(s.z); s.w=tanhf(s.w);
        *(float4*)(g_outh + (size_t)(TT-1)*(BB*HID) + b*HID + j) = s;
    }
}

// ---------------- log_softmax + [t][b] -> [b][t] remap ----------------
__global__ void k_logsm(float* __restrict__ out){
    int r = blockIdx.x;
    int t = r >> 5, b = r & 31;
    const float* row = g_logits + (size_t)r*VOC;
    float* orow = out + ((size_t)b*TT + t)*VOC;
    __shared__ float red[256];
    int tid = threadIdx.x;
    float mx = -1e30f;
    for (int i=tid; i<VOC; i+=256) mx = fmaxf(mx, row[i]);
    red[tid] = mx; __syncthreads();
    for (int st=128; st>0; st>>=1){ if (tid<st) red[tid] = fmaxf(red[tid], red[tid+st]); __syncthreads(); }
    mx = red[0]; __syncthreads();
    float sm = 0.f;
    for (int i=tid; i<VOC; i+=256) sm += expf(row[i] - mx);
    red[tid] = sm; __syncthreads();
    for (int st=128; st>0; st>>=1){ if (tid<st) red[tid] += red[tid+st]; __syncthreads(); }
    float ls = mx + logf(red[0]);
    for (int i=tid; i<VOC; i+=256) orow[i] = row[i] - ls;
}

// ---------------- launch ----------------
extern "C" void kernel_launch(void* const* d_in, const int* in_sizes, int n_in,
                              void* d_out, int out_size){
    const float* cnn  = (const float*)d_in[0];
    const int*   seq  = (const int*)  d_in[1];
    const float* emb  = (const float*)d_in[2];
    const float* Wce  = (const float*)d_in[3];  const float* bce  = (const float*)d_in[4];
    const float* Wih  = (const float*)d_in[5];  const float* bih  = (const float*)d_in[6];
    const float* Whh  = (const float*)d_in[7];  const float* bhh  = (const float*)d_in[8];
    const float* Wi2h = (const float*)d_in[9];  const float* bi2h = (const float*)d_in[10];
    const float* Wh2h = (const float*)d_in[11]; const float* bh2h = (const float*)d_in[12];
    const float* Wfr  = (const float*)d_in[13]; const float* bfr  = (const float*)d_in[14];
    const float* Wfre = (const float*)d_in[15]; const float* bfre = (const float*)d_in[16];
    const float* Who  = (const float*)d_in[17]; const float* bho  = (const float*)d_in[18];
    const float* Whoe = (const float*)d_in[19]; const float* bhoe = (const float*)d_in[20];
    const float* Wa   = (const float*)d_in[21]; const float* ba   = (const float*)d_in[22];
    const float* Watt = (const float*)d_in[23]; const float* batt = (const float*)d_in[24];
    const float* Wlog = (const float*)d_in[25]; const float* blog = (const float*)d_in[26];
    float* out = (float*)d_out;

    cudaFuncSetAttribute(persist_kernel, cudaFuncAttributeMaxDynamicSharedMemorySize,
                         SMEM_FLOATS*4);

    k_init<<<192, 256>>>();
    k_packW<<<(KST*NG)/256, 256>>>(Wih, Whh, Wi2h, Wh2h);
    k_packX<<<(EMBD*NG)/256, 256>>>(Wih, Wi2h, bih, bhh, bi2h, bh2h);
    k_gather<<<(TT*BB*EMBD)/256, 256>>>(seq, emb);
    k_gemm_tf32<<<dim3(CTXD/64, (BB*ATTN)/128), 256>>>(0, cnn, Wce, bce, CTXD, CTXD, 1);
    k_gemm_tf32<<<dim3(NG/64, (TT*BB)/128), 256>>>(1, nullptr, nullptr, nullptr, NG, EMBD, 0);

    persist_kernel<<<GB, 256, SMEM_FLOATS*4>>>(cnn, Wfr, bfr, Who, bho, Wfre, bfre,
                                               Whoe, bhoe, Wa, ba, Watt, batt);

    k_gemm_tf32<<<dim3((VOC+63)/64, (TT*BB)/128), 256>>>(2, nullptr, Wlog, blog, VOC, HID, 0);
    k_logsm<<<TT*BB, 256>>>(out);
}

// round 14
// speedup vs baseline: 2.0986x; 1.0378x over previous
#include <cuda_runtime.h>
#include <math.h>
#include <stdint.h>

#define BB 32
#define HID 512
#define CTXD 512
#define EMBD 256
#define ATTN 256
#define VOC 5000
#define TT 160
#define NG 2560
#define KST 1024
#define NA 257
#define GB 128           // persistent grid blocks

// ---------------- device scratch (static; no allocation) ----------------
__device__ float g_ctx_embed[BB*ATTN*CTXD];
__device__ float g_xproj[TT*BB*NG];
__device__ float g_Xemb[TT*BB*EMBD];
__device__ float g_Wpack[KST*NG];
__device__ float g_WxPack[EMBD*NG];
__device__ float g_biasPack[NG];
__device__ float g_A[BB*KST];          // [unused(512) | h(512)]
__device__ float g_c[BB*HID];
__device__ float g_gp[16*BB*NG];       // gates partials: 16 splitK buckets (K=64 each)
__device__ float g_p3[2*8*BB*HID];     // fr0@Wfr, h@Who partials (8 buckets)
__device__ float g_p4[2*8*BB*HID];     // fr@Wfre, hol@Whoe partials
__device__ float g_p7[8*BB*HID];       // visph@Watt partials
__device__ float g_fr0[BB*HID];
__device__ float g_scores[BB*NA];
__device__ float g_visph[BB*HID];
__device__ float g_outh[TT*BB*HID];
__device__ float g_logits[TT*BB*VOC];

// flat grid barrier state (round-9/12 validated optimum)
__device__ unsigned g_barg;
__device__ unsigned g_barc;

// dynamic shared layout (floats):
// [0      .. 32768)  s_ctx  : 64 x 512 ctx_embed slice (step-invariant)
// [32768  .. 33280)  s_hoe  : 512
// [33280  .. 33792)  s_fre  : 512
// [33792  .. 40320)  gtask region: sA 32x68 (2176) + sW 64x68 (4352); P6 aliases this
extern __shared__ float dsh[];
#define SOFF_HOE 32768
#define SOFF_FRE 33280
#define SOFF_GT  33792
#define SMEM_FLOATS 40320

__device__ __forceinline__ float sigf(float x){ return 1.f/(1.f+expf(-x)); }
__device__ __forceinline__ float tanha(float x){ float y; asm("tanh.approx.f32 %0, %1;" : "=f"(y) : "f"(x)); return y; }
__device__ __forceinline__ uint32_t f2tf32(float x){
    uint32_t u; asm("cvt.rna.tf32.f32 %0, %1;" : "=r"(u) : "f"(x)); return u;
}
__device__ __forceinline__ uint4 f4tf32(float4 v){
    uint4 t; t.x=f2tf32(v.x); t.y=f2tf32(v.y); t.z=f2tf32(v.z); t.w=f2tf32(v.w); return t;
}
#define MMA_TF32(d, a, b) \
    asm volatile("mma.sync.aligned.m16n8k8.row.col.f32.tf32.tf32.f32 " \
        "{%0,%1,%2,%3}, {%4,%5,%6,%7}, {%8,%9}, {%0,%1,%2,%3};" \
        : "+f"((d)[0]), "+f"((d)[1]), "+f"((d)[2]), "+f"((d)[3]) \
        : "r"((a)[0]), "r"((a)[1]), "r"((a)[2]), "r"((a)[3]), "r"((b)[0]), "r"((b)[1]))

// ---------------- setup kernels ----------------
__global__ void k_init(){
    int i = blockIdx.x*256 + threadIdx.x;
    if (i < BB*KST) g_A[i] = 0.f;
    if (i < BB*HID) g_c[i] = 0.f;
}

__global__ void k_packW(const float* __restrict__ Wih, const float* __restrict__ Whh,
                        const float* __restrict__ Wi2h, const float* __restrict__ Wh2h){
    int idx = blockIdx.x*256 + threadIdx.x;   // exactly KST*NG
    int k = idx / NG, n = idx % NG;
    float v;
    if (k < HID) v = (n < 4*HID) ? Wih[(size_t)(EMBD+k)*4*HID + n] : Wi2h[(size_t)(EMBD+k)*HID + (n-4*HID)];
    else         v = (n < 4*HID) ? Whh[(size_t)(k-HID)*4*HID + n]  : Wh2h[(size_t)(k-HID)*HID + (n-4*HID)];
    g_Wpack[idx] = v;
}

__global__ void k_packX(const float* __restrict__ Wih, const float* __restrict__ Wi2h,
                        const float* __restrict__ bih, const float* __restrict__ bhh,
                        const float* __restrict__ bi2h, const float* __restrict__ bh2h){
    int idx = blockIdx.x*256 + threadIdx.x;   // exactly EMBD*NG
    if (idx < NG)
        g_biasPack[idx] = (idx < 4*HID) ? (bih[idx] + bhh[idx]) : (bi2h[idx-4*HID] + bh2h[idx-4*HID]);
    int k = idx / NG, n = idx % NG;
    g_WxPack[idx] = (n < 4*HID) ? Wih[(size_t)k*4*HID + n] : Wi2h[(size_t)k*HID + (n-4*HID)];
}

__global__ void k_gather(const int* __restrict__ seq, const float* __restrict__ embed){
    int idx = blockIdx.x*256 + threadIdx.x;   // exactly TT*BB*EMBD
    int e = idx & (EMBD-1);
    int r = idx >> 8;
    int t = r >> 5, b = r & 31;
    int tok = seq[b*161 + t];
    g_Xemb[idx] = embed[(size_t)tok*EMBD + e];
}

// ---------------- generic tf32 tensor-core GEMM (pre-GEMMs + logits) ----------------
__global__ void __launch_bounds__(256) k_gemm_tf32(int mode,
        const float* __restrict__ Aext, const float* __restrict__ Wext,
        const float* __restrict__ bext, int N, int K, int act){
    const float* A; const float* W; const float* bias; float* C; int lda, ldw, ldc;
    if (mode == 0){ A=Aext;   W=Wext;     bias=bext;       C=g_ctx_embed; lda=512; ldw=512; ldc=512; }
    else if (mode==1){ A=g_Xemb; W=g_WxPack; bias=g_biasPack; C=g_xproj;  lda=256; ldw=NG;  ldc=NG;  }
    else            { A=g_outh;  W=Wext;     bias=bext;       C=g_logits; lda=512; ldw=VOC; ldc=VOC; }

    __shared__ uint32_t sA[128*36];
    __shared__ uint32_t sB[32*68];
    int tid = threadIdx.x;
    int row0 = blockIdx.y*128, col0 = blockIdx.x*64;
    int w = tid>>5, lane = tid&31;
    int wm = w&3, wn = w>>2;
    int gid = lane>>2, sub = lane&3;

    float acc[2][4][4];
#pragma unroll
    for (int mt=0; mt<2; mt++)
#pragma unroll
        for (int nt=0; nt<4; nt++)
#pragma unroll
            for (int i=0;i<4;i++) acc[mt][nt][i]=0.f;

    for (int k0=0; k0<K; k0+=32){
#pragma unroll
        for (int r=0;r<4;r++){
            int f = tid + r*256;
            int m = f>>3, kq = (f&7)<<2;
            float4 v = *(const float4*)(A + (size_t)(row0+m)*lda + k0 + kq);
            *(uint4*)&sA[m*36+kq] = f4tf32(v);
        }
#pragma unroll
        for (int r=0;r<2;r++){
            int f = tid + r*256;
            int kr = f>>4, cq = (f&15)<<2;
            int c = col0 + cq;
            float4 v;
            if (c + 3 < N){
                v = *(const float4*)(W + (size_t)(k0+kr)*ldw + c);
            } else {
                v.x = (c   < N) ? W[(size_t)(k0+kr)*ldw + c  ] : 0.f;
                v.y = (c+1 < N) ? W[(size_t)(k0+kr)*ldw + c+1] : 0.f;
                v.z = (c+2 < N) ? W[(size_t)(k0+kr)*ldw + c+2] : 0.f;
                v.w = (c+3 < N) ? W[(size_t)(k0+kr)*ldw + c+3] : 0.f;
            }
            *(uint4*)&sB[kr*68+cq] = f4tf32(v);
        }
        __syncthreads();
#pragma unroll
        for (int ks=0; ks<4; ks++){
            int kb = ks*8;
            uint32_t a[2][4];
#pragma unroll
            for (int mt=0; mt<2; mt++){
                int rbase = wm*32 + mt*16;
                a[mt][0] = sA[(rbase+gid  )*36 + kb+sub  ];
                a[mt][1] = sA[(rbase+gid+8)*36 + kb+sub  ];
                a[mt][2] = sA[(rbase+gid  )*36 + kb+sub+4];
                a[mt][3] = sA[(rbase+gid+8)*36 + kb+sub+4];
            }
            uint32_t b[4][2];
#pragma unroll
            for (int nt=0; nt<4; nt++){
                int cbase = wn*32 + nt*8 + gid;
                b[nt][0] = sB[(kb+sub  )*68 + cbase];
                b[nt][1] = sB[(kb+sub+4)*68 + cbase];
            }
#pragma unroll
            for (int mt=0; mt<2; mt++)
#pragma unroll
                for (int nt=0; nt<4; nt++)
                    MMA_TF32(acc[mt][nt], a[mt], b[nt]);
        }
        __syncthreads();
    }
#pragma unroll
    for (int mt=0; mt<2; mt++){
        int r = row0 + wm*32 + mt*16 + gid;
#pragma unroll
        for (int nt=0; nt<4; nt++){
            int c = col0 + wn*32 + nt*8 + sub*2;
#pragma unroll
            for (int half=0; half<2; half++){
                int rr = r + half*8;
                float v0 = acc[mt][nt][half*2+0];
                float v1 = acc[mt][nt][half*2+1];
                if (c+1 < N){
                    v0 += bias[c]; v1 += bias[c+1];
                    if (act == 1){ v0 = fmaxf(v0,0.f); v1 = fmaxf(v1,0.f); }
                    *(float2*)(C + (size_t)rr*ldc + c) = make_float2(v0, v1);
                } else if (c < N){
                    v0 += bias[c];
                    if (act == 1) v0 = fmaxf(v0,0.f);
                    C[(size_t)rr*ldc + c] = v0;
                }
            }
        }
    }
}

// ---------------- flat grid barrier ----------------
__device__ __forceinline__ void gridbar(){
    __syncthreads();
    if (threadIdx.x == 0){
        unsigned gen;
        asm volatile("ld.relaxed.gpu.global.u32 %0, [%1];" : "=r"(gen) : "l"(&g_barg));
        unsigned old;
        asm volatile("atom.acq_rel.gpu.global.add.u32 %0, [%1], %2;"
                     : "=r"(old) : "l"(&g_barc), "r"(1u) : "memory");
        if (old == (unsigned)(GB-1)){
            g_barc = 0u;
            unsigned ng = gen + 1u;
            asm volatile("st.release.gpu.global.u32 [%0], %1;" :: "l"(&g_barg), "r"(ng) : "memory");
        } else {
            unsigned cur;
            do {
                asm volatile("ld.acquire.gpu.global.u32 %0, [%1];" : "=r"(cur) : "l"(&g_barg) : "memory");
            } while (cur == gen);
        }
    }
    __syncthreads();
}

// One GEMM task via tf32 mma: out[0:32, col0:+64] (partial) = A[0:32, k0:+64] @ W[k0:+64, col0:+64]
// stage_mode: -1 load A directly; 1 relu(sum8 partials + bias); 2 tanh(...).
__device__ __forceinline__ void gtask64(const float* A, int lda,
                                        const float* W, int ldw,
                                        int col0, int k0,
                                        float* out, int ldo,
                                        const float* stage_base, const float* stage_bias,
                                        int stage_mode){
    uint32_t* sA = (uint32_t*)(dsh + SOFF_GT);           // 32 x 68
    uint32_t* sW = (uint32_t*)(dsh + SOFF_GT + 32*68);   // 64 x 68
    int tid = threadIdx.x;
    int q = tid>>4, j4 = (tid&15)<<2;
#pragma unroll
    for (int h=0; h<2; h++){
        int m = q + 16*h;
        float4 av;
        if (stage_mode < 0){
            av = *(const float4*)(A + (size_t)m*lda + k0 + j4);
        } else {
            float4 s = *(const float4*)(stage_bias + k0 + j4);
#pragma unroll
            for (int p=0;p<8;p++){
                const float4 v = *(const float4*)(stage_base + p*(BB*HID) + m*HID + k0 + j4);
                s.x+=v.x; s.y+=v.y; s.z+=v.z; s.w+=v.w;
            }
            if (stage_mode == 1){ s.x=fmaxf(s.x,0.f); s.y=fmaxf(s.y,0.f); s.z=fmaxf(s.z,0.f); s.w=fmaxf(s.w,0.f); }
            else                { s.x=tanhf(s.x); s.y=tanhf(s.y); s.z=tanhf(s.z); s.w=tanhf(s.w); }
            av = s;
        }
        *(uint4*)&sA[m*68 + j4] = f4tf32(av);
    }
#pragma unroll
    for (int rep=0;rep<4;rep++){
        int row = q + 16*rep;
        float4 v = *(const float4*)(W + (size_t)(k0+row)*ldw + col0 + j4);
        *(uint4*)&sW[row*68 + j4] = f4tf32(v);
    }
    __syncthreads();
    int w = tid>>5, lane = tid&31, gid = lane>>2, sub = lane&3;
    float acc[2][4];
#pragma unroll
    for (int mt=0;mt<2;mt++)
#pragma unroll
        for (int i=0;i<4;i++) acc[mt][i]=0.f;
#pragma unroll
    for (int kb=0; kb<64; kb+=8){
        uint32_t a[2][4];
#pragma unroll
        for (int mt=0; mt<2; mt++){
            int rbase = mt*16;
            a[mt][0] = sA[(rbase+gid  )*68 + kb+sub  ];
            a[mt][1] = sA[(rbase+gid+8)*68 + kb+sub  ];
            a[mt][2] = sA[(rbase+gid  )*68 + kb+sub+4];
            a[mt][3] = sA[(rbase+gid+8)*68 + kb+sub+4];
        }
        uint32_t b[2];
        b[0] = sW[(kb+sub  )*68 + w*8 + gid];
        b[1] = sW[(kb+sub+4)*68 + w*8 + gid];
        MMA_TF32(acc[0], a[0], b);
        MMA_TF32(acc[1], a[1], b);
    }
    __syncthreads();
#pragma unroll
    for (int mt=0; mt<2; mt++){
        int r = mt*16 + gid;
        int c = col0 + w*8 + sub*2;
        *(float2*)(out + (size_t)r*ldo + c)     = make_float2(acc[mt][0], acc[mt][1]);
        *(float2*)(out + (size_t)(r+8)*ldo + c) = make_float2(acc[mt][2], acc[mt][3]);
    }
}

__global__ void __launch_bounds__(256, 1) persist_kernel(
        const float* __restrict__ cnn,
        const float* __restrict__ Wfr,  const float* __restrict__ bfr,
        const float* __restrict__ Who,  const float* __restrict__ bho,
        const float* __restrict__ Wfre, const float* __restrict__ bfre,
        const float* __restrict__ Whoe, const float* __restrict__ bhoe,
        const float* __restrict__ Wa,   const float* __restrict__ ba,
        const float* __restrict__ Watt, const float* __restrict__ batt){
    int tid = threadIdx.x;
    int blk = blockIdx.x;
    int bq  = blk>>2, qq = blk&3;      // P5/P6 block role: (batch, quarter)
    int l   = tid&31;
    uint32_t* sAu = (uint32_t*)(dsh + SOFF_GT);           // 32 x 68
    uint32_t* sWu = (uint32_t*)(dsh + SOFF_GT + 32*68);   // 64 x 68

    // ---- one-time preload: ctx_embed slice into smem; Wa into regs
    for (int i = tid; i < 8192; i += 256){
        ((float4*)dsh)[i] = *(const float4*)(g_ctx_embed
            + ((size_t)bq*ATTN + qq*64 + (i>>7))*CTXD + (i&127)*4);
    }
    float4 wa0 = *(const float4*)(Wa + 0*128 + l*4);
    float4 wa1 = *(const float4*)(Wa + 1*128 + l*4);
    float4 wa2 = *(const float4*)(Wa + 2*128 + l*4);
    float4 wa3 = *(const float4*)(Wa + 3*128 + l*4);
    float ba0 = ba[0];
    gridbar();

    for (int t=0; t<TT; t++){
        // ======== P1: gates partials (640 tasks: 16 ks x 40 nt, 5/block), pipelined ========
        {
            int q = tid>>4, j4 = (tid&15)<<2;
            float4 pA0, pA1, pW0, pW1, pW2, pW3;
            // fetch task r into regs
            #define P1_FETCH(task) { \
                int ks = (task)/40, nt = (task)%40; \
                int k0 = ks*64, col0 = nt*64; \
                if (ks < 8){ \
                    if (t == 0){ pA0 = make_float4(0.f,0.f,0.f,0.f); pA1 = pA0; } \
                    else { \
                        float4 s0 = *(const float4*)(batt + k0 + j4); \
                        float4 s1 = s0; \
                        _Pragma("unroll") \
                        for (int p=0;p<8;p++){ \
                            const float4 v0 = *(const float4*)(g_p7 + (size_t)p*(BB*HID) + q*HID + k0 + j4); \
                            const float4 v1 = *(const float4*)(g_p7 + (size_t)p*(BB*HID) + (q+16)*HID + k0 + j4); \
                            s0.x+=v0.x; s0.y+=v0.y; s0.z+=v0.z; s0.w+=v0.w; \
                            s1.x+=v1.x; s1.y+=v1.y; s1.z+=v1.z; s1.w+=v1.w; \
                        } \
                        s0.x=tanhf(s0.x); s0.y=tanhf(s0.y); s0.z=tanhf(s0.z); s0.w=tanhf(s0.w); \
                        s1.x=tanhf(s1.x); s1.y=tanhf(s1.y); s1.z=tanhf(s1.z); s1.w=tanhf(s1.w); \
                        pA0 = s0; pA1 = s1; \
                    } \
                } else { \
                    pA0 = *(const float4*)(g_A + (size_t)q*KST + k0 + j4); \
                    pA1 = *(const float4*)(g_A + (size_t)(q+16)*KST + k0 + j4); \
                } \
                const float* wb = g_Wpack + (size_t)k0*NG + col0; \
                pW0 = *(const float4*)(wb + (size_t)(q   )*NG + j4); \
                pW1 = *(const float4*)(wb + (size_t)(q+16)*NG + j4); \
                pW2 = *(const float4*)(wb + (size_t)(q+32)*NG + j4); \
                pW3 = *(const float4*)(wb + (size_t)(q+48)*NG + j4); \
            }
            #define P1_COMMIT(task) { \
                int ks = (task)/40, nt = (task)%40; \
                int k0 = ks*64; \
                if (ks < 8 && nt == 0 && t > 0){ \
                    *(float4*)(g_outh + (size_t)(t-1)*(BB*HID) + q*HID + k0 + j4) = pA0; \
                    *(float4*)(g_outh + (size_t)(t-1)*(BB*HID) + (q+16)*HID + k0 + j4) = pA1; \
                } \
                *(uint4*)&sAu[q*68 + j4] = f4tf32(pA0); \
                *(uint4*)&sAu[(q+16)*68 + j4] = f4tf32(pA1); \
                *(uint4*)&sWu[(q   )*68 + j4] = f4tf32(pW0); \
                *(uint4*)&sWu[(q+16)*68 + j4] = f4tf32(pW1); \
                *(uint4*)&sWu[(q+32)*68 + j4] = f4tf32(pW2); \
                *(uint4*)&sWu[(q+48)*68 + j4] = f4tf32(pW3); \
            }
            P1_FETCH(blk);
            P1_COMMIT(blk);
            __syncthreads();
            for (int r=0; r<5; r++){
                if (r < 4) P1_FETCH(blk + (r+1)*GB);
                // compute task r
                {
                    int task = blk + r*GB;
                    int ks = task/40, nt = task%40;
                    int col0 = nt*64;
                    float* outp = g_gp + (size_t)ks*(BB*NG);
                    int w = tid>>5, lane = tid&31, gid = lane>>2, sub = lane&3;
                    float acc[2][4];
#pragma unroll
                    for (int mt=0;mt<2;mt++)
#pragma unroll
                        for (int i=0;i<4;i++) acc[mt][i]=0.f;
#pragma unroll
                    for (int kb=0; kb<64; kb+=8){
                        uint32_t a[2][4];
#pragma unroll
                        for (int mt=0; mt<2; mt++){
                            int rbase = mt*16;
                            a[mt][0] = sAu[(rbase+gid  )*68 + kb+sub  ];
                            a[mt][1] = sAu[(rbase+gid+8)*68 + kb+sub  ];
                            a[mt][2] = sAu[(rbase+gid  )*68 + kb+sub+4];
                            a[mt][3] = sAu[(rbase+gid+8)*68 + kb+sub+4];
                        }
                        uint32_t b[2];
                        b[0] = sWu[(kb+sub  )*68 + w*8 + gid];
                        b[1] = sWu[(kb+sub+4)*68 + w*8 + gid];
                        MMA_TF32(acc[0], a[0], b);
                        MMA_TF32(acc[1], a[1], b);
                    }
#pragma unroll
                    for (int mt=0; mt<2; mt++){
                        int rr = mt*16 + gid;
                        int c = col0 + w*8 + sub*2;
                        *(float2*)(outp + (size_t)rr*NG + c)     = make_float2(acc[mt][0], acc[mt][1]);
                        *(float2*)(outp + (size_t)(rr+8)*NG + c) = make_float2(acc[mt][2], acc[mt][3]);
                    }
                }
                __syncthreads();
                if (r < 4){
                    P1_COMMIT(blk + (r+1)*GB);
                    __syncthreads();
                }
            }
            #undef P1_FETCH
            #undef P1_COMMIT
        }
        gridbar();

        // ======== P2: reduce gates (16 buckets) + LSTM elementwise ========
        if (tid < 128){
            int idx = blk*128 + tid;
            int quad = idx>>2, sub = idx&3;
            int b = quad>>7, j = (quad&127)<<2;
            float4 gg[5];
#pragma unroll
            for (int c=0;c<5;c++){
                int col = c*HID + j;
                float4 x;
                if (sub == 0) x = *(const float4*)(g_xproj + (size_t)t*(BB*NG) + b*NG + col);
                else x = make_float4(0.f,0.f,0.f,0.f);
#pragma unroll
                for (int s=0;s<4;s++){
                    const float4 v = *(const float4*)(g_gp + (size_t)(sub*4+s)*(BB*NG) + b*NG + col);
                    x.x+=v.x; x.y+=v.y; x.z+=v.z; x.w+=v.w;
                }
                gg[c] = x;
            }
#pragma unroll
            for (int c=0;c<5;c++){
                gg[c].x += __shfl_down_sync(0xffffffffu, gg[c].x, 2);
                gg[c].y += __shfl_down_sync(0xffffffffu, gg[c].y, 2);
                gg[c].z += __shfl_down_sync(0xffffffffu, gg[c].z, 2);
                gg[c].w += __shfl_down_sync(0xffffffffu, gg[c].w, 2);
                gg[c].x += __shfl_down_sync(0xffffffffu, gg[c].x, 1);
                gg[c].y += __shfl_down_sync(0xffffffffu, gg[c].y, 1);
                gg[c].z += __shfl_down_sync(0xffffffffu, gg[c].z, 1);
                gg[c].w += __shfl_down_sync(0xffffffffu, gg[c].w, 1);
            }
            if (sub == 0){
                float4 cold = *(const float4*)(g_c + b*HID + j);
                float co[4] = {cold.x, cold.y, cold.z, cold.w};
                float iv4[4] = {gg[0].x,gg[0].y,gg[0].z,gg[0].w};
                float fv4[4] = {gg[1].x,gg[1].y,gg[1].z,gg[1].w};
                float gv4[4] = {gg[2].x,gg[2].y,gg[2].z,gg[2].w};
                float ov4[4] = {gg[3].x,gg[3].y,gg[3].z,gg[3].w};
                float n54[4] = {gg[4].x,gg[4].y,gg[4].z,gg[4].w};
                float cn4[4], hn4[4], f04[4];
#pragma unroll
                for (int e=0;e<4;e++){
                    float cn = sigf(fv4[e])*co[e] + sigf(iv4[e])*tanhf(gv4[e]);
                    float tc = tanhf(cn);
                    cn4[e] = cn;
                    hn4[e] = sigf(ov4[e])*tc;
                    f04[e] = sigf(n54[e])*tc;
                }
                *(float4*)(g_c   + b*HID + j) = make_float4(cn4[0],cn4[1],cn4[2],cn4[3]);
                *(float4*)(g_A   + b*KST + HID + j) = make_float4(hn4[0],hn4[1],hn4[2],hn4[3]);
                *(float4*)(g_fr0 + b*HID + j) = make_float4(f04[0],f04[1],f04[2],f04[3]);
            }
        }
        gridbar();

        // ======== P3: fr0@Wfr and h@Who partials (128 tasks, 1/block) ========
        {
            int ks = blk & 7, nt = (blk>>3)&7, mat = blk>>6;
            const float* A = mat ? (g_A + HID) : g_fr0;
            int lda = mat ? KST : HID;
            const float* W = mat ? Who : Wfr;
            gtask64(A, lda, W, HID, nt*64, ks*64,
                  g_p3 + (size_t)mat*(8*BB*HID) + (size_t)ks*(BB*HID), HID,
                  nullptr, nullptr, -1);
        }
        gridbar();

        // ======== P4: fr@Wfre, hol@Whoe partials (A staged from p3, 8 buckets) ========
        {
            int ks = blk & 7, nt = (blk>>3)&7, mat = blk>>6;
            const float* W = mat ? Whoe : Wfre;
            gtask64(nullptr, 0, W, HID, nt*64, ks*64,
                  g_p4 + (size_t)mat*(8*BB*HID) + (size_t)ks*(BB*HID), HID,
                  g_p3 + (size_t)mat*(8*BB*HID), mat ? bho : bfr, mat ? 2 : 1);
        }
        gridbar();

        // ======== P5: attention scores (smem ctx; hoe/fre staged from p4, 8 partials) ========
        {
            if (tid < 128){
                int j = tid*4;
                float4 s = *(const float4*)(bhoe + j);
#pragma unroll
                for (int p=0;p<8;p++){
                    const float4 v = *(const float4*)(g_p4 + (size_t)(8+p)*(BB*HID) + bq*HID + j);
                    s.x+=v.x; s.y+=v.y; s.z+=v.z; s.w+=v.w;
                }
                *(float4*)&dsh[SOFF_HOE + j] = s;
            } else if (qq == 0){
                int j = (tid-128)*4;
                float4 s = *(const float4*)(bfre + j);
#pragma unroll
                for (int p=0;p<8;p++){
                    const float4 v = *(const float4*)(g_p4 + (size_t)p*(BB*HID) + bq*HID + j);
                    s.x+=v.x; s.y+=v.y; s.z+=v.z; s.w+=v.w;
                }
                *(float4*)&dsh[SOFF_FRE + j] = s;
            }
            __syncthreads();
            int w = tid>>5;
            float4 hv0 = *(const float4*)&dsh[SOFF_HOE + 0*128 + l*4];
            float4 hv1 = *(const float4*)&dsh[SOFF_HOE + 1*128 + l*4];
            float4 hv2 = *(const float4*)&dsh[SOFF_HOE + 2*128 + l*4];
            float4 hv3 = *(const float4*)&dsh[SOFF_HOE + 3*128 + l*4];
#pragma unroll
            for (int it=0; it<8; it++){
                int al = it*8 + w;
                const float* e = dsh + al*512;
                float acc = 0.f;
                float4 ev;
                ev = *(const float4*)&e[0*128 + l*4];
                acc += wa0.x*tanha(ev.x+hv0.x); acc += wa0.y*tanha(ev.y+hv0.y);
                acc += wa0.z*tanha(ev.z+hv0.z); acc += wa0.w*tanha(ev.w+hv0.w);
                ev = *(const float4*)&e[1*128 + l*4];
                acc += wa1.x*tanha(ev.x+hv1.x); acc += wa1.y*tanha(ev.y+hv1.y);
                acc += wa1.z*tanha(ev.z+hv1.z); acc += wa1.w*tanha(ev.w+hv1.w);
                ev = *(const float4*)&e[2*128 + l*4];
                acc += wa2.x*tanha(ev.x+hv2.x); acc += wa2.y*tanha(ev.y+hv2.y);
                acc += wa2.z*tanha(ev.z+hv2.z); acc += wa2.w*tanha(ev.w+hv2.w);
                ev = *(const float4*)&e[3*128 + l*4];
                acc += wa3.x*tanha(ev.x+hv3.x); acc += wa3.y*tanha(ev.y+hv3.y);
                acc += wa3.z*tanha(ev.z+hv3.z); acc += wa3.w*tanha(ev.w+hv3.w);
#pragma unroll
                for (int off=16; off; off>>=1) acc += __shfl_xor_sync(0xffffffffu, acc, off);
                if (l == 0) g_scores[bq*NA + qq*64 + al + 1] = acc + ba0;
            }
            if (qq == 0 && w == 0){
                float acc = 0.f;
                float4 ev;
                ev = *(const float4*)&dsh[SOFF_FRE + 0*128 + l*4];
                acc += wa0.x*tanha(ev.x+hv0.x); acc += wa0.y*tanha(ev.y+hv0.y);
                acc += wa0.z*tanha(ev.z+hv0.z); acc += wa0.w*tanha(ev.w+hv0.w);
                ev = *(const float4*)&dsh[SOFF_FRE + 1*128 + l*4];
                acc += wa1.x*tanha(ev.x+hv1.x); acc += wa1.y*tanha(ev.y+hv1.y);
                acc += wa1.z*tanha(ev.z+hv1.z); acc += wa1.w*tanha(ev.w+hv1.w);
                ev = *(const float4*)&dsh[SOFF_FRE + 2*128 + l*4];
                acc += wa2.x*tanha(ev.x+hv2.x); acc += wa2.y*tanha(ev.y+hv2.y);
                acc += wa2.z*tanha(ev.z+hv2.z); acc += wa2.w*tanha(ev.w+hv2.w);
                ev = *(const float4*)&dsh[SOFF_FRE + 3*128 + l*4];
                acc += wa3.x*tanha(ev.x+hv3.x); acc += wa3.y*tanha(ev.y+hv3.y);
                acc += wa3.z*tanha(ev.z+hv3.z); acc += wa3.w*tanha(ev.w+hv3.w);
#pragma unroll
                for (int off=16; off; off>>=1) acc += __shfl_xor_sync(0xffffffffu, acc, off);
                if (l == 0) g_scores[bq*NA] = acc + ba0;
            }
        }
        gridbar();

        // ======== P6: softmax + vis (fr, hol reduced inline from 8 partials) -> visph ========
        {
            float* s_sc  = dsh + SOFF_GT;
            float* s_red = dsh + SOFF_GT + 272;
            float* s_v   = dsh + SOFF_GT + 544;
            s_sc[tid] = g_scores[bq*NA + tid];
            if (tid == 0) s_sc[256] = g_scores[bq*NA + 256];
            __syncthreads();
            float mv = s_sc[tid];
            if (tid == 0) mv = fmaxf(mv, s_sc[256]);
            s_red[tid] = mv; __syncthreads();
            for (int st=128; st; st>>=1){ if (tid<st) s_red[tid] = fmaxf(s_red[tid], s_red[tid+st]); __syncthreads(); }
            float mx = s_red[0]; __syncthreads();
            float ev  = expf(s_sc[tid] - mx);
            float ev2 = (tid==0) ? expf(s_sc[256] - mx) : 0.f;
            s_red[tid] = ev + ev2; __syncthreads();
            for (int st=128; st; st>>=1){ if (tid<st) s_red[tid] += s_red[tid+st]; __syncthreads(); }
            float inv = 1.f / s_red[0];
            __syncthreads();
            s_sc[tid] = ev * inv;
            if (tid == 0) s_sc[256] = ev2 * inv;
            __syncthreads();
            int aa = tid>>5, hq = tid&31;
            int h = qq*128 + hq*4;
            float4 acc = make_float4(0.f,0.f,0.f,0.f);
            int astart = aa;
            if (aa == 0){
                float4 s = *(const float4*)(bfr + h);
#pragma unroll
                for (int p=0;p<8;p++){
                    const float4 v = *(const float4*)(g_p3 + (size_t)p*(BB*HID) + bq*HID + h);
                    s.x+=v.x; s.y+=v.y; s.z+=v.z; s.w+=v.w;
                }
                s.x=fmaxf(s.x,0.f); s.y=fmaxf(s.y,0.f); s.z=fmaxf(s.z,0.f); s.w=fmaxf(s.w,0.f);
                float w0 = s_sc[0];
                acc.x = w0*s.x; acc.y = w0*s.y; acc.z = w0*s.z; acc.w = w0*s.w;
                astart = 8;
            }
            for (int a = astart; a < NA; a += 8){
                float w = s_sc[a];
                float4 v = *(const float4*)(cnn + ((size_t)bq*ATTN + (a-1))*CTXD + h);
                acc.x += w*v.x; acc.y += w*v.y; acc.z += w*v.z; acc.w += w*v.w;
            }
            *(float4*)&s_v[aa*128 + hq*4] = acc;
            __syncthreads();
            if (tid < 32){
                int h2 = qq*128 + tid*4;
                float4 s = make_float4(0.f,0.f,0.f,0.f);
#pragma unroll
                for (int a2=0;a2<8;a2++){
                    const float4 v = *(const float4*)&s_v[a2*128 + tid*4];
                    s.x+=v.x; s.y+=v.y; s.z+=v.z; s.w+=v.w;
                }
                float4 ho = *(const float4*)(bho + h2);
#pragma unroll
                for (int p=0;p<8;p++){
                    const float4 v = *(const float4*)(g_p3 + (size_t)(8+p)*(BB*HID) + bq*HID + h2);
                    ho.x+=v.x; ho.y+=v.y; ho.z+=v.z; ho.w+=v.w;
                }
                s.x += tanhf(ho.x); s.y += tanhf(ho.y); s.z += tanhf(ho.z); s.w += tanhf(ho.w);
                *(float4*)(g_visph + bq*HID + h2) = s;
            }
            __syncthreads();
        }
        gridbar();

        // ======== P7: outh partials (64 tasks: 8 ks x 8 nt) ========
        if (blk < 64){
            int ks = blk & 7, nt = blk>>3;
            gtask64(g_visph, HID, Watt, HID, nt*64, ks*64,
                  g_p7 + (size_t)ks*(BB*HID), HID, nullptr, nullptr, -1);
        }
        gridbar();
    }

    // ---- epilogue: finalize out(TT-1) into g_outh[TT-1]
    if (tid < 32){
        int quad = blk*32 + tid;
        int b = quad>>7, j = (quad&127)<<2;
        float4 s = *(const float4*)(batt + j);
#pragma unroll
        for (int p=0;p<8;p++){
            const float4 v = *(const float4*)(g_p7 + (size_t)p*(BB*HID) + b*HID + j);
            s.x+=v.x; s.y+=v.y; s.z+=v.z; s.w+=v.w;
        }
        s.x=tanhf(s.x); s.y=tanhf(s.y); s.z=tanhf(s.z); s.w=tanhf(s.w);
        *(float4*)(g_outh + (size_t)(TT-1)*(BB*HID) + b*HID + j) = s;
    }
}

// ---------------- log_softmax + [t][b] -> [b][t] remap ----------------
__global__ void k_logsm(float* __restrict__ out){
    int r = blockIdx.x;
    int t = r >> 5, b = r & 31;
    const float* row = g_logits + (size_t)r*VOC;
    float* orow = out + ((size_t)b*TT + t)*VOC;
    __shared__ float red[256];
    int tid = threadIdx.x;
    float mx = -1e30f;
    for (int i=tid; i<VOC; i+=256) mx = fmaxf(mx, row[i]);
    red[tid] = mx; __syncthreads();
    for (int st=128; st>0; st>>=1){ if (tid<st) red[tid] = fmaxf(red[tid], red[tid+st]); __syncthreads(); }
    mx = red[0]; __syncthreads();
    float sm = 0.f;
    for (int i=tid; i<VOC; i+=256) sm += expf(row[i] - mx);
    red[tid] = sm; __syncthreads();
    for (int st=128; st>0; st>>=1){ if (tid<st) red[tid] += red[tid+st]; __syncthreads(); }
    float ls = mx + logf(red[0]);
    for (int i=tid; i<VOC; i+=256) orow[i] = row[i] - ls;
}

// ---------------- launch ----------------
extern "C" void kernel_launch(void* const* d_in, const int* in_sizes, int n_in,
                              void* d_out, int out_size){
    const float* cnn  = (const float*)d_in[0];
    const int*   seq  = (const int*)  d_in[1];
    const float* emb  = (const float*)d_in[2];
    const float* Wce  = (const float*)d_in[3];  const float* bce  = (const float*)d_in[4];
    const float* Wih  = (const float*)d_in[5];  const float* bih  = (const float*)d_in[6];
    const float* Whh  = (const float*)d_in[7];  const float* bhh  = (const float*)d_in[8];
    const float* Wi2h = (const float*)d_in[9];  const float* bi2h = (const float*)d_in[10];
    const float* Wh2h = (const float*)d_in[11]; const float* bh2h = (const float*)d_in[12];
    const float* Wfr  = (const float*)d_in[13]; const float* bfr  = (const float*)d_in[14];
    const float* Wfre = (const float*)d_in[15]; const float* bfre = (const float*)d_in[16];
    const float* Who  = (const float*)d_in[17]; const float* bho  = (const float*)d_in[18];
    const float* Whoe = (const float*)d_in[19]; const float* bhoe = (const float*)d_in[20];
    const float* Wa   = (const float*)d_in[21]; const float* ba   = (const float*)d_in[22];
    const float* Watt = (const float*)d_in[23]; const float* batt = (const float*)d_in[24];
    const float* Wlog = (const float*)d_in[25]; const float* blog = (const float*)d_in[26];
    float* out = (float*)d_out;

    cudaFuncSetAttribute(persist_kernel, cudaFuncAttributeMaxDynamicSharedMemorySize,
                         SMEM_FLOATS*4);

    k_init<<<192, 256>>>();
    k_packW<<<(KST*NG)/256, 256>>>(Wih, Whh, Wi2h, Wh2h);
    k_packX<<<(EMBD*NG)/256, 256>>>(Wih, Wi2h, bih, bhh, bi2h, bh2h);
    k_gather<<<(TT*BB*EMBD)/256, 256>>>(seq, emb);
    k_gemm_tf32<<<dim3(CTXD/64, (BB*ATTN)/128), 256>>>(0, cnn, Wce, bce, CTXD, CTXD, 1);
    k_gemm_tf32<<<dim3(NG/64, (TT*BB)/128), 256>>>(1, nullptr, nullptr, nullptr, NG, EMBD, 0);

    persist_kernel<<<GB, 256, SMEM_FLOATS*4>>>(cnn, Wfr, bfr, Who, bho, Wfre, bfre,
                                               Whoe, bhoe, Wa, ba, Watt, batt);

    k_gemm_tf32<<<dim3((VOC+63)/64, (TT*BB)/128), 256>>>(2, nullptr, Wlog, blog, VOC, HID, 0);
    k_logsm<<<TT*BB, 256>>>(out);
}

// round 15
// speedup vs baseline: 2.1455x; 1.0223x over previous
#include <cuda_runtime.h>
#include <math.h>
#include <stdint.h>

#define BB 32
#define HID 512
#define CTXD 512
#define EMBD 256
#define ATTN 256
#define VOC 5000
#define TT 160
#define NG 2560
#define KST 1024
#define NA 257
#define GB 128           // persistent grid blocks
#define NTASK1 320       // P1 tasks: 16 ks x 20 nt (N=128)

// ---------------- device scratch (static; no allocation) ----------------
__device__ float g_ctx_embed[BB*ATTN*CTXD];
__device__ float g_xproj[TT*BB*NG];
__device__ float g_Xemb[TT*BB*EMBD];
__device__ float g_Wpack[KST*NG];
__device__ float g_WxPack[EMBD*NG];
__device__ float g_biasPack[NG];
__device__ float g_A[BB*KST];          // [unused(512) | h(512)]
__device__ float g_c[BB*HID];
__device__ float g_gp[16*BB*NG];       // gates partials: 16 splitK buckets (K=64 each)
__device__ float g_p3[2*8*BB*HID];     // fr0@Wfr, h@Who partials (8 buckets)
__device__ float g_p4[2*8*BB*HID];     // fr@Wfre, hol@Whoe partials
__device__ float g_p7[8*BB*HID];       // visph@Watt partials
__device__ float g_fr0[BB*HID];
__device__ float g_scores[BB*NA];
__device__ float g_visph[BB*HID];
__device__ float g_outh[TT*BB*HID];
__device__ float g_logits[TT*BB*VOC];

// flat grid barrier state (round-9/12 validated optimum)
__device__ unsigned g_barg;
__device__ unsigned g_barc;

// dynamic shared layout (floats):
// [0      .. 32768)  s_ctx  : 64 x 512 ctx_embed slice (step-invariant)
// [32768  .. 33280)  s_hoe  : 512
// [33280  .. 33792)  s_fre  : 512
// [33792  .. 44416)  gtask region: sA 32x68 (2176) + sW up to 64x132 (8448); P6 aliases this
extern __shared__ float dsh[];
#define SOFF_HOE 32768
#define SOFF_FRE 33280
#define SOFF_GT  33792
#define SMEM_FLOATS 44416

__device__ __forceinline__ float sigf(float x){ return 1.f/(1.f+expf(-x)); }
__device__ __forceinline__ float tanha(float x){ float y; asm("tanh.approx.f32 %0, %1;" : "=f"(y) : "f"(x)); return y; }
__device__ __forceinline__ uint32_t f2tf32(float x){
    uint32_t u; asm("cvt.rna.tf32.f32 %0, %1;" : "=r"(u) : "f"(x)); return u;
}
__device__ __forceinline__ uint4 f4tf32(float4 v){
    uint4 t; t.x=f2tf32(v.x); t.y=f2tf32(v.y); t.z=f2tf32(v.z); t.w=f2tf32(v.w); return t;
}
#define MMA_TF32(d, a, b) \
    asm volatile("mma.sync.aligned.m16n8k8.row.col.f32.tf32.tf32.f32 " \
        "{%0,%1,%2,%3}, {%4,%5,%6,%7}, {%8,%9}, {%0,%1,%2,%3};" \
        : "+f"((d)[0]), "+f"((d)[1]), "+f"((d)[2]), "+f"((d)[3]) \
        : "r"((a)[0]), "r"((a)[1]), "r"((a)[2]), "r"((a)[3]), "r"((b)[0]), "r"((b)[1]))

// ---------------- setup kernels ----------------
__global__ void k_init(){
    int i = blockIdx.x*256 + threadIdx.x;
    if (i < BB*KST) g_A[i] = 0.f;
    if (i < BB*HID) g_c[i] = 0.f;
}

__global__ void k_packW(const float* __restrict__ Wih, const float* __restrict__ Whh,
                        const float* __restrict__ Wi2h, const float* __restrict__ Wh2h){
    int idx = blockIdx.x*256 + threadIdx.x;   // exactly KST*NG
    int k = idx / NG, n = idx % NG;
    float v;
    if (k < HID) v = (n < 4*HID) ? Wih[(size_t)(EMBD+k)*4*HID + n] : Wi2h[(size_t)(EMBD+k)*HID + (n-4*HID)];
    else         v = (n < 4*HID) ? Whh[(size_t)(k-HID)*4*HID + n]  : Wh2h[(size_t)(k-HID)*HID + (n-4*HID)];
    g_Wpack[idx] = v;
}

__global__ void k_packX(const float* __restrict__ Wih, const float* __restrict__ Wi2h,
                        const float* __restrict__ bih, const float* __restrict__ bhh,
                        const float* __restrict__ bi2h, const float* __restrict__ bh2h){
    int idx = blockIdx.x*256 + threadIdx.x;   // exactly EMBD*NG
    if (idx < NG)
        g_biasPack[idx] = (idx < 4*HID) ? (bih[idx] + bhh[idx]) : (bi2h[idx-4*HID] + bh2h[idx-4*HID]);
    int k = idx / NG, n = idx % NG;
    g_WxPack[idx] = (n < 4*HID) ? Wih[(size_t)k*4*HID + n] : Wi2h[(size_t)k*HID + (n-4*HID)];
}

__global__ void k_gather(const int* __restrict__ seq, const float* __restrict__ embed){
    int idx = blockIdx.x*256 + threadIdx.x;   // exactly TT*BB*EMBD
    int e = idx & (EMBD-1);
    int r = idx >> 8;
    int t = r >> 5, b = r & 31;
    int tok = seq[b*161 + t];
    g_Xemb[idx] = embed[(size_t)tok*EMBD + e];
}

// ---------------- generic tf32 tensor-core GEMM (pre-GEMMs + logits) ----------------
__global__ void __launch_bounds__(256) k_gemm_tf32(int mode,
        const float* __restrict__ Aext, const float* __restrict__ Wext,
        const float* __restrict__ bext, int N, int K, int act){
    const float* A; const float* W; const float* bias; float* C; int lda, ldw, ldc;
    if (mode == 0){ A=Aext;   W=Wext;     bias=bext;       C=g_ctx_embed; lda=512; ldw=512; ldc=512; }
    else if (mode==1){ A=g_Xemb; W=g_WxPack; bias=g_biasPack; C=g_xproj;  lda=256; ldw=NG;  ldc=NG;  }
    else            { A=g_outh;  W=Wext;     bias=bext;       C=g_logits; lda=512; ldw=VOC; ldc=VOC; }

    __shared__ uint32_t sA[128*36];
    __shared__ uint32_t sB[32*68];
    int tid = threadIdx.x;
    int row0 = blockIdx.y*128, col0 = blockIdx.x*64;
    int w = tid>>5, lane = tid&31;
    int wm = w&3, wn = w>>2;
    int gid = lane>>2, sub = lane&3;

    float acc[2][4][4];
#pragma unroll
    for (int mt=0; mt<2; mt++)
#pragma unroll
        for (int nt=0; nt<4; nt++)
#pragma unroll
            for (int i=0;i<4;i++) acc[mt][nt][i]=0.f;

    for (int k0=0; k0<K; k0+=32){
#pragma unroll
        for (int r=0;r<4;r++){
            int f = tid + r*256;
            int m = f>>3, kq = (f&7)<<2;
            float4 v = *(const float4*)(A + (size_t)(row0+m)*lda + k0 + kq);
            *(uint4*)&sA[m*36+kq] = f4tf32(v);
        }
#pragma unroll
        for (int r=0;r<2;r++){
            int f = tid + r*256;
            int kr = f>>4, cq = (f&15)<<2;
            int c = col0 + cq;
            float4 v;
            if (c + 3 < N){
                v = *(const float4*)(W + (size_t)(k0+kr)*ldw + c);
            } else {
                v.x = (c   < N) ? W[(size_t)(k0+kr)*ldw + c  ] : 0.f;
                v.y = (c+1 < N) ? W[(size_t)(k0+kr)*ldw + c+1] : 0.f;
                v.z = (c+2 < N) ? W[(size_t)(k0+kr)*ldw + c+2] : 0.f;
                v.w = (c+3 < N) ? W[(size_t)(k0+kr)*ldw + c+3] : 0.f;
            }
            *(uint4*)&sB[kr*68+cq] = f4tf32(v);
        }
        __syncthreads();
#pragma unroll
        for (int ks=0; ks<4; ks++){
            int kb = ks*8;
            uint32_t a[2][4];
#pragma unroll
            for (int mt=0; mt<2; mt++){
                int rbase = wm*32 + mt*16;
                a[mt][0] = sA[(rbase+gid  )*36 + kb+sub  ];
                a[mt][1] = sA[(rbase+gid+8)*36 + kb+sub  ];
                a[mt][2] = sA[(rbase+gid  )*36 + kb+sub+4];
                a[mt][3] = sA[(rbase+gid+8)*36 + kb+sub+4];
            }
            uint32_t b[4][2];
#pragma unroll
            for (int nt=0; nt<4; nt++){
                int cbase = wn*32 + nt*8 + gid;
                b[nt][0] = sB[(kb+sub  )*68 + cbase];
                b[nt][1] = sB[(kb+sub+4)*68 + cbase];
            }
#pragma unroll
            for (int mt=0; mt<2; mt++)
#pragma unroll
                for (int nt=0; nt<4; nt++)
                    MMA_TF32(acc[mt][nt], a[mt], b[nt]);
        }
        __syncthreads();
    }
#pragma unroll
    for (int mt=0; mt<2; mt++){
        int r = row0 + wm*32 + mt*16 + gid;
#pragma unroll
        for (int nt=0; nt<4; nt++){
            int c = col0 + wn*32 + nt*8 + sub*2;
#pragma unroll
            for (int half=0; half<2; half++){
                int rr = r + half*8;
                float v0 = acc[mt][nt][half*2+0];
                float v1 = acc[mt][nt][half*2+1];
                if (c+1 < N){
                    v0 += bias[c]; v1 += bias[c+1];
                    if (act == 1){ v0 = fmaxf(v0,0.f); v1 = fmaxf(v1,0.f); }
                    *(float2*)(C + (size_t)rr*ldc + c) = make_float2(v0, v1);
                } else if (c < N){
                    v0 += bias[c];
                    if (act == 1) v0 = fmaxf(v0,0.f);
                    C[(size_t)rr*ldc + c] = v0;
                }
            }
        }
    }
}

// ---------------- flat grid barrier ----------------
__device__ __forceinline__ void gridbar(){
    __syncthreads();
    if (threadIdx.x == 0){
        unsigned gen;
        asm volatile("ld.relaxed.gpu.global.u32 %0, [%1];" : "=r"(gen) : "l"(&g_barg));
        unsigned old;
        asm volatile("atom.acq_rel.gpu.global.add.u32 %0, [%1], %2;"
                     : "=r"(old) : "l"(&g_barc), "r"(1u) : "memory");
        if (old == (unsigned)(GB-1)){
            g_barc = 0u;
            unsigned ng = gen + 1u;
            asm volatile("st.release.gpu.global.u32 [%0], %1;" :: "l"(&g_barg), "r"(ng) : "memory");
        } else {
            unsigned cur;
            do {
                asm volatile("ld.acquire.gpu.global.u32 %0, [%1];" : "=r"(cur) : "l"(&g_barg) : "memory");
            } while (cur == gen);
        }
    }
    __syncthreads();
}

// One GEMM task via tf32 mma: out[0:32, col0:+64] (partial) = A[0:32, k0:+64] @ W[k0:+64, col0:+64]
// stage_mode: -1 load A directly; 1 relu(sum8 partials + bias); 2 tanh(...).
__device__ __forceinline__ void gtask64(const float* A, int lda,
                                        const float* W, int ldw,
                                        int col0, int k0,
                                        float* out, int ldo,
                                        const float* stage_base, const float* stage_bias,
                                        int stage_mode){
    uint32_t* sA = (uint32_t*)(dsh + SOFF_GT);           // 32 x 68
    uint32_t* sW = (uint32_t*)(dsh + SOFF_GT + 32*68);   // 64 x 68
    int tid = threadIdx.x;
    int q = tid>>4, j4 = (tid&15)<<2;
#pragma unroll
    for (int h=0; h<2; h++){
        int m = q + 16*h;
        float4 av;
        if (stage_mode < 0){
            av = *(const float4*)(A + (size_t)m*lda + k0 + j4);
        } else {
            float4 s = *(const float4*)(stage_bias + k0 + j4);
#pragma unroll
            for (int p=0;p<8;p++){
                const float4 v = *(const float4*)(stage_base + p*(BB*HID) + m*HID + k0 + j4);
                s.x+=v.x; s.y+=v.y; s.z+=v.z; s.w+=v.w;
            }
            if (stage_mode == 1){ s.x=fmaxf(s.x,0.f); s.y=fmaxf(s.y,0.f); s.z=fmaxf(s.z,0.f); s.w=fmaxf(s.w,0.f); }
            else                { s.x=tanhf(s.x); s.y=tanhf(s.y); s.z=tanhf(s.z); s.w=tanhf(s.w); }
            av = s;
        }
        *(uint4*)&sA[m*68 + j4] = f4tf32(av);
    }
#pragma unroll
    for (int rep=0;rep<4;rep++){
        int row = q + 16*rep;
        float4 v = *(const float4*)(W + (size_t)(k0+row)*ldw + col0 + j4);
        *(uint4*)&sW[row*68 + j4] = f4tf32(v);
    }
    __syncthreads();
    int w = tid>>5, lane = tid&31, gid = lane>>2, sub = lane&3;
    float acc[2][4];
#pragma unroll
    for (int mt=0;mt<2;mt++)
#pragma unroll
        for (int i=0;i<4;i++) acc[mt][i]=0.f;
#pragma unroll
    for (int kb=0; kb<64; kb+=8){
        uint32_t a[2][4];
#pragma unroll
        for (int mt=0; mt<2; mt++){
            int rbase = mt*16;
            a[mt][0] = sA[(rbase+gid  )*68 + kb+sub  ];
            a[mt][1] = sA[(rbase+gid+8)*68 + kb+sub  ];
            a[mt][2] = sA[(rbase+gid  )*68 + kb+sub+4];
            a[mt][3] = sA[(rbase+gid+8)*68 + kb+sub+4];
        }
        uint32_t b[2];
        b[0] = sW[(kb+sub  )*68 + w*8 + gid];
        b[1] = sW[(kb+sub+4)*68 + w*8 + gid];
        MMA_TF32(acc[0], a[0], b);
        MMA_TF32(acc[1], a[1], b);
    }
    __syncthreads();
#pragma unroll
    for (int mt=0; mt<2; mt++){
        int r = mt*16 + gid;
        int c = col0 + w*8 + sub*2;
        *(float2*)(out + (size_t)r*ldo + c)     = make_float2(acc[mt][0], acc[mt][1]);
        *(float2*)(out + (size_t)(r+8)*ldo + c) = make_float2(acc[mt][2], acc[mt][3]);
    }
}

__global__ void __launch_bounds__(256, 1) persist_kernel(
        const float* __restrict__ cnn,
        const float* __restrict__ Wfr,  const float* __restrict__ bfr,
        const float* __restrict__ Who,  const float* __restrict__ bho,
        const float* __restrict__ Wfre, const float* __restrict__ bfre,
        const float* __restrict__ Whoe, const float* __restrict__ bhoe,
        const float* __restrict__ Wa,   const float* __restrict__ ba,
        const float* __restrict__ Watt, const float* __restrict__ batt){
    int tid = threadIdx.x;
    int blk = blockIdx.x;
    int bq  = blk>>2, qq = blk&3;      // P5/P6 block role: (batch, quarter)
    int l   = tid&31;
    uint32_t* sAu = (uint32_t*)(dsh + SOFF_GT);           // 32 x 68
    uint32_t* sW1 = (uint32_t*)(dsh + SOFF_GT + 32*68);   // P1: 64 x 132

    // ---- one-time preload: ctx_embed slice into smem; Wa into regs
    for (int i = tid; i < 8192; i += 256){
        ((float4*)dsh)[i] = *(const float4*)(g_ctx_embed
            + ((size_t)bq*ATTN + qq*64 + (i>>7))*CTXD + (i&127)*4);
    }
    float4 wa0 = *(const float4*)(Wa + 0*128 + l*4);
    float4 wa1 = *(const float4*)(Wa + 1*128 + l*4);
    float4 wa2 = *(const float4*)(Wa + 2*128 + l*4);
    float4 wa3 = *(const float4*)(Wa + 3*128 + l*4);
    float ba0 = ba[0];
    gridbar();

    for (int t=0; t<TT; t++){
        // ======== P1: gates partials (320 tasks: 16 ks x 20 nt of 32x128x64) ========
        {
            int q = tid>>4, j4 = (tid&15)<<2;
            float4 pA0, pA1, pW[8];
            #define P1_FETCH(task) { \
                int ks = (task)/20, nt = (task)%20; \
                int k0 = ks*64, col0 = nt*128; \
                if (ks < 8){ \
                    if (t == 0){ pA0 = make_float4(0.f,0.f,0.f,0.f); pA1 = pA0; } \
                    else { \
                        float4 s0 = *(const float4*)(batt + k0 + j4); \
                        float4 s1 = s0; \
                        _Pragma("unroll") \
                        for (int p=0;p<8;p++){ \
                            const float4 v0 = *(const float4*)(g_p7 + (size_t)p*(BB*HID) + q*HID + k0 + j4); \
                            const float4 v1 = *(const float4*)(g_p7 + (size_t)p*(BB*HID) + (q+16)*HID + k0 + j4); \
                            s0.x+=v0.x; s0.y+=v0.y; s0.z+=v0.z; s0.w+=v0.w; \
                            s1.x+=v1.x; s1.y+=v1.y; s1.z+=v1.z; s1.w+=v1.w; \
                        } \
                        s0.x=tanhf(s0.x); s0.y=tanhf(s0.y); s0.z=tanhf(s0.z); s0.w=tanhf(s0.w); \
                        s1.x=tanhf(s1.x); s1.y=tanhf(s1.y); s1.z=tanhf(s1.z); s1.w=tanhf(s1.w); \
                        pA0 = s0; pA1 = s1; \
                    } \
                } else { \
                    pA0 = *(const float4*)(g_A + (size_t)q*KST + k0 + j4); \
                    pA1 = *(const float4*)(g_A + (size_t)(q+16)*KST + k0 + j4); \
                } \
                const float* wb = g_Wpack + (size_t)k0*NG + col0; \
                _Pragma("unroll") \
                for (int rep=0;rep<8;rep++){ \
                    int f = tid + rep*256; \
                    pW[rep] = *(const float4*)(wb + (size_t)(f>>5)*NG + ((f&31)<<2)); \
                } \
            }
            #define P1_COMMIT(task) { \
                int ks = (task)/20, nt = (task)%20; \
                int k0 = ks*64; \
                if (ks < 8 && nt == 0 && t > 0){ \
                    *(float4*)(g_outh + (size_t)(t-1)*(BB*HID) + q*HID + k0 + j4) = pA0; \
                    *(float4*)(g_outh + (size_t)(t-1)*(BB*HID) + (q+16)*HID + k0 + j4) = pA1; \
                } \
                *(uint4*)&sAu[q*68 + j4] = f4tf32(pA0); \
                *(uint4*)&sAu[(q+16)*68 + j4] = f4tf32(pA1); \
                _Pragma("unroll") \
                for (int rep=0;rep<8;rep++){ \
                    int f = tid + rep*256; \
                    *(uint4*)&sW1[(f>>5)*132 + ((f&31)<<2)] = f4tf32(pW[rep]); \
                } \
            }
            int ntask_me = (blk + 2*GB < NTASK1) ? 3 : 2;
            P1_FETCH(blk);
            P1_COMMIT(blk);
            __syncthreads();
            for (int r=0; r<ntask_me; r++){
                if (r+1 < ntask_me) P1_FETCH(blk + (r+1)*GB);
                // compute task r
                {
                    int task = blk + r*GB;
                    int ks = task/20, nt = task%20;
                    int col0 = nt*128;
                    float* outp = g_gp + (size_t)ks*(BB*NG);
                    int w = tid>>5, lane = tid&31, gid = lane>>2, sub = lane&3;
                    float acc[2][2][4];
#pragma unroll
                    for (int mt=0;mt<2;mt++)
#pragma unroll
                        for (int nt2=0;nt2<2;nt2++)
#pragma unroll
                            for (int i=0;i<4;i++) acc[mt][nt2][i]=0.f;
#pragma unroll
                    for (int kb=0; kb<64; kb+=8){
                        uint32_t a[2][4];
#pragma unroll
                        for (int mt=0; mt<2; mt++){
                            int rbase = mt*16;
                            a[mt][0] = sAu[(rbase+gid  )*68 + kb+sub  ];
                            a[mt][1] = sAu[(rbase+gid+8)*68 + kb+sub  ];
                            a[mt][2] = sAu[(rbase+gid  )*68 + kb+sub+4];
                            a[mt][3] = sAu[(rbase+gid+8)*68 + kb+sub+4];
                        }
                        uint32_t b[2][2];
#pragma unroll
                        for (int nt2=0; nt2<2; nt2++){
                            int cbase = w*16 + nt2*8 + gid;
                            b[nt2][0] = sW1[(kb+sub  )*132 + cbase];
                            b[nt2][1] = sW1[(kb+sub+4)*132 + cbase];
                        }
#pragma unroll
                        for (int mt=0; mt<2; mt++)
#pragma unroll
                            for (int nt2=0; nt2<2; nt2++)
                                MMA_TF32(acc[mt][nt2], a[mt], b[nt2]);
                    }
#pragma unroll
                    for (int mt=0; mt<2; mt++){
                        int rr = mt*16 + gid;
#pragma unroll
                        for (int nt2=0; nt2<2; nt2++){
                            int c = col0 + w*16 + nt2*8 + sub*2;
                            *(float2*)(outp + (size_t)rr*NG + c)     = make_float2(acc[mt][nt2][0], acc[mt][nt2][1]);
                            *(float2*)(outp + (size_t)(rr+8)*NG + c) = make_float2(acc[mt][nt2][2], acc[mt][nt2][3]);
                        }
                    }
                }
                __syncthreads();
                if (r+1 < ntask_me){
                    P1_COMMIT(blk + (r+1)*GB);
                    __syncthreads();
                }
            }
            #undef P1_FETCH
            #undef P1_COMMIT
        }
        gridbar();

        // ======== P2: reduce gates (16 buckets) + LSTM elementwise ========
        if (tid < 128){
            int idx = blk*128 + tid;
            int quad = idx>>2, sub = idx&3;
            int b = quad>>7, j = (quad&127)<<2;
            float4 gg[5];
#pragma unroll
            for (int c=0;c<5;c++){
                int col = c*HID + j;
                float4 x;
                if (sub == 0) x = *(const float4*)(g_xproj + (size_t)t*(BB*NG) + b*NG + col);
                else x = make_float4(0.f,0.f,0.f,0.f);
#pragma unroll
                for (int s=0;s<4;s++){
                    const float4 v = *(const float4*)(g_gp + (size_t)(sub*4+s)*(BB*NG) + b*NG + col);
                    x.x+=v.x; x.y+=v.y; x.z+=v.z; x.w+=v.w;
                }
                gg[c] = x;
            }
#pragma unroll
            for (int c=0;c<5;c++){
                gg[c].x += __shfl_down_sync(0xffffffffu, gg[c].x, 2);
                gg[c].y += __shfl_down_sync(0xffffffffu, gg[c].y, 2);
                gg[c].z += __shfl_down_sync(0xffffffffu, gg[c].z, 2);
                gg[c].w += __shfl_down_sync(0xffffffffu, gg[c].w, 2);
                gg[c].x += __shfl_down_sync(0xffffffffu, gg[c].x, 1);
                gg[c].y += __shfl_down_sync(0xffffffffu, gg[c].y, 1);
                gg[c].z += __shfl_down_sync(0xffffffffu, gg[c].z, 1);
                gg[c].w += __shfl_down_sync(0xffffffffu, gg[c].w, 1);
            }
            if (sub == 0){
                float4 cold = *(const float4*)(g_c + b*HID + j);
                float co[4] = {cold.x, cold.y, cold.z, cold.w};
                float iv4[4] = {gg[0].x,gg[0].y,gg[0].z,gg[0].w};
                float fv4[4] = {gg[1].x,gg[1].y,gg[1].z,gg[1].w};
                float gv4[4] = {gg[2].x,gg[2].y,gg[2].z,gg[2].w};
                float ov4[4] = {gg[3].x,gg[3].y,gg[3].z,gg[3].w};
                float n54[4] = {gg[4].x,gg[4].y,gg[4].z,gg[4].w};
                float cn4[4], hn4[4], f04[4];
#pragma unroll
                for (int e=0;e<4;e++){
                    float cn = sigf(fv4[e])*co[e] + sigf(iv4[e])*tanhf(gv4[e]);
                    float tc = tanhf(cn);
                    cn4[e] = cn;
                    hn4[e] = sigf(ov4[e])*tc;
                    f04[e] = sigf(n54[e])*tc;
                }
                *(float4*)(g_c   + b*HID + j) = make_float4(cn4[0],cn4[1],cn4[2],cn4[3]);
                *(float4*)(g_A   + b*KST + HID + j) = make_float4(hn4[0],hn4[1],hn4[2],hn4[3]);
                *(float4*)(g_fr0 + b*HID + j) = make_float4(f04[0],f04[1],f04[2],f04[3]);
            }
        }
        gridbar();

        // ======== P3: fr0@Wfr and h@Who partials (128 tasks, 1/block) ========
        {
            int ks = blk & 7, nt = (blk>>3)&7, mat = blk>>6;
            const float* A = mat ? (g_A + HID) : g_fr0;
            int lda = mat ? KST : HID;
            const float* W = mat ? Who : Wfr;
            gtask64(A, lda, W, HID, nt*64, ks*64,
                  g_p3 + (size_t)mat*(8*BB*HID) + (size_t)ks*(BB*HID), HID,
                  nullptr, nullptr, -1);
        }
        gridbar();

        // ======== P4: fr@Wfre, hol@Whoe partials (A staged from p3, 8 buckets) ========
        {
            int ks = blk & 7, nt = (blk>>3)&7, mat = blk>>6;
            const float* W = mat ? Whoe : Wfre;
            gtask64(nullptr, 0, W, HID, nt*64, ks*64,
                  g_p4 + (size_t)mat*(8*BB*HID) + (size_t)ks*(BB*HID), HID,
                  g_p3 + (size_t)mat*(8*BB*HID), mat ? bho : bfr, mat ? 2 : 1);
        }
        gridbar();

        // ======== P5: attention scores (smem ctx; hoe/fre staged from p4, 8 partials) ========
        {
            if (tid < 128){
                int j = tid*4;
                float4 s = *(const float4*)(bhoe + j);
#pragma unroll
                for (int p=0;p<8;p++){
                    const float4 v = *(const float4*)(g_p4 + (size_t)(8+p)*(BB*HID) + bq*HID + j);
                    s.x+=v.x; s.y+=v.y; s.z+=v.z; s.w+=v.w;
                }
                *(float4*)&dsh[SOFF_HOE + j] = s;
            } else if (qq == 0){
                int j = (tid-128)*4;
                float4 s = *(const float4*)(bfre + j);
#pragma unroll
                for (int p=0;p<8;p++){
                    const float4 v = *(const float4*)(g_p4 + (size_t)p*(BB*HID) + bq*HID + j);
                    s.x+=v.x; s.y+=v.y; s.z+=v.z; s.w+=v.w;
                }
                *(float4*)&dsh[SOFF_FRE + j] = s;
            }
            __syncthreads();
            int w = tid>>5;
            float4 hv0 = *(const float4*)&dsh[SOFF_HOE + 0*128 + l*4];
            float4 hv1 = *(const float4*)&dsh[SOFF_HOE + 1*128 + l*4];
            float4 hv2 = *(const float4*)&dsh[SOFF_HOE + 2*128 + l*4];
            float4 hv3 = *(const float4*)&dsh[SOFF_HOE + 3*128 + l*4];
#pragma unroll
            for (int it=0; it<8; it++){
                int al = it*8 + w;
                const float* e = dsh + al*512;
                float acc = 0.f;
                float4 ev;
                ev = *(const float4*)&e[0*128 + l*4];
                acc += wa0.x*tanha(ev.x+hv0.x); acc += wa0.y*tanha(ev.y+hv0.y);
                acc += wa0.z*tanha(ev.z+hv0.z); acc += wa0.w*tanha(ev.w+hv0.w);
                ev = *(const float4*)&e[1*128 + l*4];
                acc += wa1.x*tanha(ev.x+hv1.x); acc += wa1.y*tanha(ev.y+hv1.y);
                acc += wa1.z*tanha(ev.z+hv1.z); acc += wa1.w*tanha(ev.w+hv1.w);
                ev = *(const float4*)&e[2*128 + l*4];
                acc += wa2.x*tanha(ev.x+hv2.x); acc += wa2.y*tanha(ev.y+hv2.y);
                acc += wa2.z*tanha(ev.z+hv2.z); acc += wa2.w*tanha(ev.w+hv2.w);
                ev = *(const float4*)&e[3*128 + l*4];
                acc += wa3.x*tanha(ev.x+hv3.x); acc += wa3.y*tanha(ev.y+hv3.y);
                acc += wa3.z*tanha(ev.z+hv3.z); acc += wa3.w*tanha(ev.w+hv3.w);
#pragma unroll
                for (int off=16; off; off>>=1) acc += __shfl_xor_sync(0xffffffffu, acc, off);
                if (l == 0) g_scores[bq*NA + qq*64 + al + 1] = acc + ba0;
            }
            if (qq == 0 && w == 0){
                float acc = 0.f;
                float4 ev;
                ev = *(const float4*)&dsh[SOFF_FRE + 0*128 + l*4];
                acc += wa0.x*tanha(ev.x+hv0.x); acc += wa0.y*tanha(ev.y+hv0.y);
                acc += wa0.z*tanha(ev.z+hv0.z); acc += wa0.w*tanha(ev.w+hv0.w);
                ev = *(const float4*)&dsh[SOFF_FRE + 1*128 + l*4];
                acc += wa1.x*tanha(ev.x+hv1.x); acc += wa1.y*tanha(ev.y+hv1.y);
                acc += wa1.z*tanha(ev.z+hv1.z); acc += wa1.w*tanha(ev.w+hv1.w);
                ev = *(const float4*)&dsh[SOFF_FRE + 2*128 + l*4];
                acc += wa2.x*tanha(ev.x+hv2.x); acc += wa2.y*tanha(ev.y+hv2.y);
                acc += wa2.z*tanha(ev.z+hv2.z); acc += wa2.w*tanha(ev.w+hv2.w);
                ev = *(const float4*)&dsh[SOFF_FRE + 3*128 + l*4];
                acc += wa3.x*tanha(ev.x+hv3.x); acc += wa3.y*tanha(ev.y+hv3.y);
                acc += wa3.z*tanha(ev.z+hv3.z); acc += wa3.w*tanha(ev.w+hv3.w);
#pragma unroll
                for (int off=16; off; off>>=1) acc += __shfl_xor_sync(0xffffffffu, acc, off);
                if (l == 0) g_scores[bq*NA] = acc + ba0;
            }
        }
        gridbar();

        // ======== P6: softmax + vis (fr, hol reduced inline from 8 partials) -> visph ========
        {
            float* s_sc  = dsh + SOFF_GT;
            float* s_red = dsh + SOFF_GT + 272;
            float* s_v   = dsh + SOFF_GT + 544;
            s_sc[tid] = g_scores[bq*NA + tid];
            if (tid == 0) s_sc[256] = g_scores[bq*NA + 256];
            __syncthreads();
            float mv = s_sc[tid];
            if (tid == 0) mv = fmaxf(mv, s_sc[256]);
            s_red[tid] = mv; __syncthreads();
            for (int st=128; st; st>>=1){ if (tid<st) s_red[tid] = fmaxf(s_red[tid], s_red[tid+st]); __syncthreads(); }
            float mx = s_red[0]; __syncthreads();
            float ev  = expf(s_sc[tid] - mx);
            float ev2 = (tid==0) ? expf(s_sc[256] - mx) : 0.f;
            s_red[tid] = ev + ev2; __syncthreads();
            for (int st=128; st; st>>=1){ if (tid<st) s_red[tid] += s_red[tid+st]; __syncthreads(); }
            float inv = 1.f / s_red[0];
            __syncthreads();
            s_sc[tid] = ev * inv;
            if (tid == 0) s_sc[256] = ev2 * inv;
            __syncthreads();
            int aa = tid>>5, hq = tid&31;
            int h = qq*128 + hq*4;
            float4 acc = make_float4(0.f,0.f,0.f,0.f);
            int astart = aa;
            if (aa == 0){
                float4 s = *(const float4*)(bfr + h);
#pragma unroll
                for (int p=0;p<8;p++){
                    const float4 v = *(const float4*)(g_p3 + (size_t)p*(BB*HID) + bq*HID + h);
                    s.x+=v.x; s.y+=v.y; s.z+=v.z; s.w+=v.w;
                }
                s.x=fmaxf(s.x,0.f); s.y=fmaxf(s.y,0.f); s.z=fmaxf(s.z,0.f); s.w=fmaxf(s.w,0.f);
                float w0 = s_sc[0];
                acc.x = w0*s.x; acc.y = w0*s.y; acc.z = w0*s.z; acc.w = w0*s.w;
                astart = 8;
            }
            for (int a = astart; a < NA; a += 8){
                float w = s_sc[a];
                float4 v = *(const float4*)(cnn + ((size_t)bq*ATTN + (a-1))*CTXD + h);
                acc.x += w*v.x; acc.y += w*v.y; acc.z += w*v.z; acc.w += w*v.w;
            }
            *(float4*)&s_v[aa*128 + hq*4] = acc;
            __syncthreads();
            if (tid < 32){
                int h2 = qq*128 + tid*4;
                float4 s = make_float4(0.f,0.f,0.f,0.f);
#pragma unroll
                for (int a2=0;a2<8;a2++){
                    const float4 v = *(const float4*)&s_v[a2*128 + tid*4];
                    s.x+=v.x; s.y+=v.y; s.z+=v.z; s.w+=v.w;
                }
                float4 ho = *(const float4*)(bho + h2);
#pragma unroll
                for (int p=0;p<8;p++){
                    const float4 v = *(const float4*)(g_p3 + (size_t)(8+p)*(BB*HID) + bq*HID + h2);
                    ho.x+=v.x; ho.y+=v.y; ho.z+=v.z; ho.w+=v.w;
                }
                s.x += tanhf(ho.x); s.y += tanhf(ho.y); s.z += tanhf(ho.z); s.w += tanhf(ho.w);
                *(float4*)(g_visph + bq*HID + h2) = s;
            }
            __syncthreads();
        }
        gridbar();

        // ======== P7: outh partials (64 tasks: 8 ks x 8 nt) ========
        if (blk < 64){
            int ks = blk & 7, nt = blk>>3;
            gtask64(g_visph, HID, Watt, HID, nt*64, ks*64,
                  g_p7 + (size_t)ks*(BB*HID), HID, nullptr, nullptr, -1);
        }
        gridbar();
    }

    // ---- epilogue: finalize out(TT-1) into g_outh[TT-1]
    if (tid < 32){
        int quad = blk*32 + tid;
        int b = quad>>7, j = (quad&127)<<2;
        float4 s = *(const float4*)(batt + j);
#pragma unroll
        for (int p=0;p<8;p++){
            const float4 v = *(const float4*)(g_p7 + (size_t)p*(BB*HID) + b*HID + j);
            s.x+=v.x; s.y+=v.y; s.z+=v.z; s.w+=v.w;
        }
        s.x=tanhf(s.x); s.y=tanhf(s.y); s.z=tanhf(s.z); s.w=tanhf(s.w);
        *(float4*)(g_outh + (size_t)(TT-1)*(BB*HID) + b*HID + j) = s;
    }
}

// ---------------- log_softmax + [t][b] -> [b][t] remap ----------------
__global__ void k_logsm(float* __restrict__ out){
    int r = blockIdx.x;
    int t = r >> 5, b = r & 31;
    const float* row = g_logits + (size_t)r*VOC;
    float* orow = out + ((size_t)b*TT + t)*VOC;
    __shared__ float red[256];
    int tid = threadIdx.x;
    float mx = -1e30f;
    for (int i=tid; i<VOC; i+=256) mx = fmaxf(mx, row[i]);
    red[tid] = mx; __syncthreads();
    for (int st=128; st>0; st>>=1){ if (tid<st) red[tid] = fmaxf(red[tid], red[tid+st]); __syncthreads(); }
    mx = red[0]; __syncthreads();
    float sm = 0.f;
    for (int i=tid; i<VOC; i+=256) sm += expf(row[i] - mx);
    red[tid] = sm; __syncthreads();
    for (int st=128; st>0; st>>=1){ if (tid<st) red[tid] += red[tid+st]; __syncthreads(); }
    float ls = mx + logf(red[0]);
    for (int i=tid; i<VOC; i+=256) orow[i] = row[i] - ls;
}

// ---------------- launch ----------------
extern "C" void kernel_launch(void* const* d_in, const int* in_sizes, int n_in,
                              void* d_out, int out_size){
    const float* cnn  = (const float*)d_in[0];
    const int*   seq  = (const int*)  d_in[1];
    const float* emb  = (const float*)d_in[2];
    const float* Wce  = (const float*)d_in[3];  const float* bce  = (const float*)d_in[4];
    const float* Wih  = (const float*)d_in[5];  const float* bih  = (const float*)d_in[6];
    const float* Whh  = (const float*)d_in[7];  const float* bhh  = (const float*)d_in[8];
    const float* Wi2h = (const float*)d_in[9];  const float* bi2h = (const float*)d_in[10];
    const float* Wh2h = (const float*)d_in[11]; const float* bh2h = (const float*)d_in[12];
    const float* Wfr  = (const float*)d_in[13]; const float* bfr  = (const float*)d_in[14];
    const float* Wfre = (const float*)d_in[15]; const float* bfre = (const float*)d_in[16];
    const float* Who  = (const float*)d_in[17]; const float* bho  = (const float*)d_in[18];
    const float* Whoe = (const float*)d_in[19]; const float* bhoe = (const float*)d_in[20];
    const float* Wa   = (const float*)d_in[21]; const float* ba   = (const float*)d_in[22];
    const float* Watt = (const float*)d_in[23]; const float* batt = (const float*)d_in[24];
    const float* Wlog = (const float*)d_in[25]; const float* blog = (const float*)d_in[26];
    float* out = (float*)d_out;

    cudaFuncSetAttribute(persist_kernel, cudaFuncAttributeMaxDynamicSharedMemorySize,
                         SMEM_FLOATS*4);

    k_init<<<192, 256>>>();
    k_packW<<<(KST*NG)/256, 256>>>(Wih, Whh, Wi2h, Wh2h);
    k_packX<<<(EMBD*NG)/256, 256>>>(Wih, Wi2h, bih, bhh, bi2h, bh2h);
    k_gather<<<(TT*BB*EMBD)/256, 256>>>(seq, emb);
    k_gemm_tf32<<<dim3(CTXD/64, (BB*ATTN)/128), 256>>>(0, cnn, Wce, bce, CTXD, CTXD, 1);
    k_gemm_tf32<<<dim3(NG/64, (TT*BB)/128), 256>>>(1, nullptr, nullptr, nullptr, NG, EMBD, 0);

    persist_kernel<<<GB, 256, SMEM_FLOATS*4>>>(cnn, Wfr, bfr, Who, bho, Wfre, bfre,
                                               Whoe, bhoe, Wa, ba, Watt, batt);

    k_gemm_tf32<<<dim3((VOC+63)/64, (TT*BB)/128), 256>>>(2, nullptr, Wlog, blog, VOC, HID, 0);
    k_logsm<<<TT*BB, 256>>>(out);
}

// round 16
// speedup vs baseline: 2.3594x; 1.0997x over previous
#include <cuda_runtime.h>
#include <cuda_bf16.h>
#include <math.h>
#include <stdint.h>

#define BB 32
#define HID 512
#define CTXD 512
#define EMBD 256
#define ATTN 256
#define VOC 5000
#define TT 160
#define NG 2560
#define KST 1024
#define NA 257
#define GB 128           // persistent grid blocks
#define NTASK1 320       // P1 tasks: 16 ks x 20 nt (N=128, K=64)

// ---------------- device scratch (static; no allocation) ----------------
__device__ float g_ctx_embed[BB*ATTN*CTXD];
__device__ float g_xproj[TT*BB*NG];
__device__ float g_Xemb[TT*BB*EMBD];
__device__ uint32_t g_WpackB[(KST/2)*NG];      // bf16 pair-packed [k/2][NG]
__device__ uint32_t g_W5B[5*(HID/2)*HID];      // Wfr,Who,Wfre,Whoe,Watt bf16 pair-packed
__device__ float g_WxPack[EMBD*NG];
__device__ float g_biasPack[NG];
__device__ float g_A[BB*KST];          // [unused(512) | h(512)]
__device__ float g_c[BB*HID];
__device__ float g_gp[16*BB*NG];       // gates partials: 16 splitK buckets (K=64 each)
__device__ float g_p3[2*8*BB*HID];     // fr0@Wfr, h@Who partials (8 buckets)
__device__ float g_p4[2*8*BB*HID];     // fr@Wfre, hol@Whoe partials
__device__ float g_p7[8*BB*HID];       // visph@Watt partials
__device__ float g_fr0[BB*HID];
__device__ float g_scores[BB*NA];
__device__ float g_visph[BB*HID];
__device__ float g_outh[TT*BB*HID];
__device__ float g_logits[TT*BB*VOC];

// flat grid barrier state (validated optimum)
__device__ unsigned g_barg;
__device__ unsigned g_barc;

// dynamic shared layout (floats):
// [0      .. 32768)  s_ctx  : 64 x 512 ctx_embed slice (step-invariant)
// [32768  .. 33280)  s_hoe  : 512
// [33280  .. 33792)  s_fre  : 512
// [33792  .. 39104)  gtask region: sA2 32x34 (1088 u32) + sW up to 32x132 (4224 u32); P6 aliases
extern __shared__ float dsh[];
#define SOFF_HOE 32768
#define SOFF_FRE 33280
#define SOFF_GT  33792
#define SMEM_FLOATS 39104

__device__ __forceinline__ float sigf(float x){ return 1.f/(1.f+expf(-x)); }
__device__ __forceinline__ float tanha(float x){ float y; asm("tanh.approx.f32 %0, %1;" : "=f"(y) : "f"(x)); return y; }
__device__ __forceinline__ uint32_t f2tf32(float x){
    uint32_t u; asm("cvt.rna.tf32.f32 %0, %1;" : "=r"(u) : "f"(x)); return u;
}
__device__ __forceinline__ uint4 f4tf32(float4 v){
    uint4 t; t.x=f2tf32(v.x); t.y=f2tf32(v.y); t.z=f2tf32(v.z); t.w=f2tf32(v.w); return t;
}
__device__ __forceinline__ uint32_t f2b2(float lo, float hi){
    __nv_bfloat162 h = __floats2bfloat162_rn(lo, hi);
    return *(uint32_t*)&h;
}
#define MMA_TF32(d, a, b) \
    asm volatile("mma.sync.aligned.m16n8k8.row.col.f32.tf32.tf32.f32 " \
        "{%0,%1,%2,%3}, {%4,%5,%6,%7}, {%8,%9}, {%0,%1,%2,%3};" \
        : "+f"((d)[0]), "+f"((d)[1]), "+f"((d)[2]), "+f"((d)[3]) \
        : "r"((a)[0]), "r"((a)[1]), "r"((a)[2]), "r"((a)[3]), "r"((b)[0]), "r"((b)[1]))
#define MMA_BF16(d, a, b) \
    asm volatile("mma.sync.aligned.m16n8k16.row.col.f32.bf16.bf16.f32 " \
        "{%0,%1,%2,%3}, {%4,%5,%6,%7}, {%8,%9}, {%0,%1,%2,%3};" \
        : "+f"((d)[0]), "+f"((d)[1]), "+f"((d)[2]), "+f"((d)[3]) \
        : "r"((a)[0]), "r"((a)[1]), "r"((a)[2]), "r"((a)[3]), "r"((b)[0]), "r"((b)[1]))

// ---------------- setup kernels ----------------
__global__ void k_init(){
    int i = blockIdx.x*256 + threadIdx.x;
    if (i < BB*KST) g_A[i] = 0.f;
    if (i < BB*HID) g_c[i] = 0.f;
}

__device__ __forceinline__ float fetchWpack(int k, int n,
        const float* Wih, const float* Whh, const float* Wi2h, const float* Wh2h){
    if (k < HID) return (n < 4*HID) ? Wih[(size_t)(EMBD+k)*4*HID + n] : Wi2h[(size_t)(EMBD+k)*HID + (n-4*HID)];
    return (n < 4*HID) ? Whh[(size_t)(k-HID)*4*HID + n] : Wh2h[(size_t)(k-HID)*HID + (n-4*HID)];
}

__global__ void k_packWB(const float* __restrict__ Wih, const float* __restrict__ Whh,
                         const float* __restrict__ Wi2h, const float* __restrict__ Wh2h){
    int idx = blockIdx.x*256 + threadIdx.x;   // exactly (KST/2)*NG
    int k2 = idx / NG, n = idx % NG;
    float lo = fetchWpack(2*k2,   n, Wih, Whh, Wi2h, Wh2h);
    float hi = fetchWpack(2*k2+1, n, Wih, Whh, Wi2h, Wh2h);
    g_WpackB[idx] = f2b2(lo, hi);
}

__global__ void k_pack5B(const float* __restrict__ Wfr, const float* __restrict__ Who,
                         const float* __restrict__ Wfre, const float* __restrict__ Whoe,
                         const float* __restrict__ Watt){
    int idx = blockIdx.x*256 + threadIdx.x;   // exactly 5*(HID/2)*HID
    int mat = idx / ((HID/2)*HID);
    int rem = idx % ((HID/2)*HID);
    int k2 = rem / HID, n = rem % HID;
    const float* src = (mat==0)?Wfr:(mat==1)?Who:(mat==2)?Wfre:(mat==3)?Whoe:Watt;
    g_W5B[idx] = f2b2(src[(size_t)(2*k2)*HID + n], src[(size_t)(2*k2+1)*HID + n]);
}

__global__ void k_packX(const float* __restrict__ Wih, const float* __restrict__ Wi2h,
                        const float* __restrict__ bih, const float* __restrict__ bhh,
                        const float* __restrict__ bi2h, const float* __restrict__ bh2h){
    int idx = blockIdx.x*256 + threadIdx.x;   // exactly EMBD*NG
    if (idx < NG)
        g_biasPack[idx] = (idx < 4*HID) ? (bih[idx] + bhh[idx]) : (bi2h[idx-4*HID] + bh2h[idx-4*HID]);
    int k = idx / NG, n = idx % NG;
    g_WxPack[idx] = (n < 4*HID) ? Wih[(size_t)k*4*HID + n] : Wi2h[(size_t)k*HID + (n-4*HID)];
}

__global__ void k_gather(const int* __restrict__ seq, const float* __restrict__ embed){
    int idx = blockIdx.x*256 + threadIdx.x;   // exactly TT*BB*EMBD
    int e = idx & (EMBD-1);
    int r = idx >> 8;
    int t = r >> 5, b = r & 31;
    int tok = seq[b*161 + t];
    g_Xemb[idx] = embed[(size_t)tok*EMBD + e];
}

// ---------------- generic tf32 tensor-core GEMM (pre-GEMMs + logits; unchanged) ----------------
__global__ void __launch_bounds__(256) k_gemm_tf32(int mode,
        const float* __restrict__ Aext, const float* __restrict__ Wext,
        const float* __restrict__ bext, int N, int K, int act){
    const float* A; const float* W; const float* bias; float* C; int lda, ldw, ldc;
    if (mode == 0){ A=Aext;   W=Wext;     bias=bext;       C=g_ctx_embed; lda=512; ldw=512; ldc=512; }
    else if (mode==1){ A=g_Xemb; W=g_WxPack; bias=g_biasPack; C=g_xproj;  lda=256; ldw=NG;  ldc=NG;  }
    else            { A=g_outh;  W=Wext;     bias=bext;       C=g_logits; lda=512; ldw=VOC; ldc=VOC; }

    __shared__ uint32_t sA[128*36];
    __shared__ uint32_t sB[32*68];
    int tid = threadIdx.x;
    int row0 = blockIdx.y*128, col0 = blockIdx.x*64;
    int w = tid>>5, lane = tid&31;
    int wm = w&3, wn = w>>2;
    int gid = lane>>2, sub = lane&3;

    float acc[2][4][4];
#pragma unroll
    for (int mt=0; mt<2; mt++)
#pragma unroll
        for (int nt=0; nt<4; nt++)
#pragma unroll
            for (int i=0;i<4;i++) acc[mt][nt][i]=0.f;

    for (int k0=0; k0<K; k0+=32){
#pragma unroll
        for (int r=0;r<4;r++){
            int f = tid + r*256;
            int m = f>>3, kq = (f&7)<<2;
            float4 v = *(const float4*)(A + (size_t)(row0+m)*lda + k0 + kq);
            *(uint4*)&sA[m*36+kq] = f4tf32(v);
        }
#pragma unroll
        for (int r=0;r<2;r++){
            int f = tid + r*256;
            int kr = f>>4, cq = (f&15)<<2;
            int c = col0 + cq;
            float4 v;
            if (c + 3 < N){
                v = *(const float4*)(W + (size_t)(k0+kr)*ldw + c);
            } else {
                v.x = (c   < N) ? W[(size_t)(k0+kr)*ldw + c  ] : 0.f;
                v.y = (c+1 < N) ? W[(size_t)(k0+kr)*ldw + c+1] : 0.f;
                v.z = (c+2 < N) ? W[(size_t)(k0+kr)*ldw + c+2] : 0.f;
                v.w = (c+3 < N) ? W[(size_t)(k0+kr)*ldw + c+3] : 0.f;
            }
            *(uint4*)&sB[kr*68+cq] = f4tf32(v);
        }
        __syncthreads();
#pragma unroll
        for (int ks=0; ks<4; ks++){
            int kb = ks*8;
            uint32_t a[2][4];
#pragma unroll
            for (int mt=0; mt<2; mt++){
                int rbase = wm*32 + mt*16;
                a[mt][0] = sA[(rbase+gid  )*36 + kb+sub  ];
                a[mt][1] = sA[(rbase+gid+8)*36 + kb+sub  ];
                a[mt][2] = sA[(rbase+gid  )*36 + kb+sub+4];
                a[mt][3] = sA[(rbase+gid+8)*36 + kb+sub+4];
            }
            uint32_t b[4][2];
#pragma unroll
            for (int nt=0; nt<4; nt++){
                int cbase = wn*32 + nt*8 + gid;
                b[nt][0] = sB[(kb+sub  )*68 + cbase];
                b[nt][1] = sB[(kb+sub+4)*68 + cbase];
            }
#pragma unroll
            for (int mt=0; mt<2; mt++)
#pragma unroll
                for (int nt=0; nt<4; nt++)
                    MMA_TF32(acc[mt][nt], a[mt], b[nt]);
        }
        __syncthreads();
    }
#pragma unroll
    for (int mt=0; mt<2; mt++){
        int r = row0 + wm*32 + mt*16 + gid;
#pragma unroll
        for (int nt=0; nt<4; nt++){
            int c = col0 + wn*32 + nt*8 + sub*2;
#pragma unroll
            for (int half=0; half<2; half++){
                int rr = r + half*8;
                float v0 = acc[mt][nt][half*2+0];
                float v1 = acc[mt][nt][half*2+1];
                if (c+1 < N){
                    v0 += bias[c]; v1 += bias[c+1];
                    if (act == 1){ v0 = fmaxf(v0,0.f); v1 = fmaxf(v1,0.f); }
                    *(float2*)(C + (size_t)rr*ldc + c) = make_float2(v0, v1);
                } else if (c < N){
                    v0 += bias[c];
                    if (act == 1) v0 = fmaxf(v0,0.f);
                    C[(size_t)rr*ldc + c] = v0;
                }
            }
        }
    }
}

// ---------------- flat grid barrier ----------------
__device__ __forceinline__ void gridbar(){
    __syncthreads();
    if (threadIdx.x == 0){
        unsigned gen;
        asm volatile("ld.relaxed.gpu.global.u32 %0, [%1];" : "=r"(gen) : "l"(&g_barg));
        unsigned old;
        asm volatile("atom.acq_rel.gpu.global.add.u32 %0, [%1], %2;"
                     : "=r"(old) : "l"(&g_barc), "r"(1u) : "memory");
        if (old == (unsigned)(GB-1)){
            g_barc = 0u;
            unsigned ng = gen + 1u;
            asm volatile("st.release.gpu.global.u32 [%0], %1;" :: "l"(&g_barg), "r"(ng) : "memory");
        } else {
            unsigned cur;
            do {
                asm volatile("ld.acquire.gpu.global.u32 %0, [%1];" : "=r"(cur) : "l"(&g_barg) : "memory");
            } while (cur == gen);
        }
    }
    __syncthreads();
}

// One bf16 GEMM task: out[0:32, col0:+64] (partial) = A[0:32, k0:+64] @ W[k0:+64, col0:+64]
// WB: bf16 pair-packed [HID/2][HID]. stage_mode: -1 direct A; 1 relu(sum8+bias); 2 tanh(...).
__device__ __forceinline__ void gtask64b(const float* A, int lda,
                                         const uint32_t* WB,
                                         int col0, int k0,
                                         float* out, int ldo,
                                         const float* stage_base, const float* stage_bias,
                                         int stage_mode){
    uint32_t* sA2 = (uint32_t*)(dsh + SOFF_GT);      // 32 rows x 32 k2 (pitch 34)
    uint32_t* sW2 = sA2 + 1088;                      // 32 k2 x 64 cols (pitch 68)
    int tid = threadIdx.x;
    int q = tid>>4, j4 = (tid&15)<<2, j2 = (tid&15)<<1;
    int k20 = k0>>1;
#pragma unroll
    for (int h=0; h<2; h++){
        int m = q + 16*h;
        float4 av;
        if (stage_mode < 0){
            av = *(const float4*)(A + (size_t)m*lda + k0 + j4);
        } else {
            float4 s = *(const float4*)(stage_bias + k0 + j4);
#pragma unroll
            for (int p=0;p<8;p++){
                const float4 v = *(const float4*)(stage_base + p*(BB*HID) + m*HID + k0 + j4);
                s.x+=v.x; s.y+=v.y; s.z+=v.z; s.w+=v.w;
            }
            if (stage_mode == 1){ s.x=fmaxf(s.x,0.f); s.y=fmaxf(s.y,0.f); s.z=fmaxf(s.z,0.f); s.w=fmaxf(s.w,0.f); }
            else                { s.x=tanhf(s.x); s.y=tanhf(s.y); s.z=tanhf(s.z); s.w=tanhf(s.w); }
            av = s;
        }
        uint2 p2; p2.x = f2b2(av.x, av.y); p2.y = f2b2(av.z, av.w);
        *(uint2*)&sA2[m*34 + j2] = p2;
    }
#pragma unroll
    for (int rep=0;rep<2;rep++){
        int f = tid + rep*256;
        int row = f>>4, c4 = (f&15)<<2;
        uint4 v = *(const uint4*)(WB + (size_t)(k20+row)*HID + col0 + c4);
        *(uint4*)&sW2[row*68 + c4] = v;
    }
    __syncthreads();
    int w = tid>>5, lane = tid&31, gid = lane>>2, sub = lane&3;
    float acc[2][4];
#pragma unroll
    for (int mt=0;mt<2;mt++)
#pragma unroll
        for (int i=0;i<4;i++) acc[mt][i]=0.f;
#pragma unroll
    for (int kb8=0; kb8<32; kb8+=8){
        uint32_t a[2][4];
#pragma unroll
        for (int mt=0; mt<2; mt++){
            int rbase = mt*16;
            a[mt][0] = sA2[(rbase+gid  )*34 + kb8+sub  ];
            a[mt][1] = sA2[(rbase+gid+8)*34 + kb8+sub  ];
            a[mt][2] = sA2[(rbase+gid  )*34 + kb8+sub+4];
            a[mt][3] = sA2[(rbase+gid+8)*34 + kb8+sub+4];
        }
        uint32_t b[2];
        b[0] = sW2[(kb8+sub  )*68 + w*8 + gid];
        b[1] = sW2[(kb8+sub+4)*68 + w*8 + gid];
        MMA_BF16(acc[0], a[0], b);
        MMA_BF16(acc[1], a[1], b);
    }
    __syncthreads();
#pragma unroll
    for (int mt=0; mt<2; mt++){
        int r = mt*16 + gid;
        int c = col0 + w*8 + sub*2;
        *(float2*)(out + (size_t)r*ldo + c)     = make_float2(acc[mt][0], acc[mt][1]);
        *(float2*)(out + (size_t)(r+8)*ldo + c) = make_float2(acc[mt][2], acc[mt][3]);
    }
}

__global__ void __launch_bounds__(256, 1) persist_kernel(
        const float* __restrict__ cnn,
        const float* __restrict__ bfr,  const float* __restrict__ bho,
        const float* __restrict__ bfre, const float* __restrict__ bhoe,
        const float* __restrict__ Wa,   const float* __restrict__ ba,
        const float* __restrict__ batt){
    int tid = threadIdx.x;
    int blk = blockIdx.x;
    int bq  = blk>>2, qq = blk&3;      // P5/P6 block role: (batch, quarter)
    int l   = tid&31;
    uint32_t* sA2 = (uint32_t*)(dsh + SOFF_GT);   // 32 x 34
    uint32_t* sW1 = sA2 + 1088;                   // P1: 32 k2 x 128 cols (pitch 132)

    // ---- one-time preload: ctx_embed slice into smem; Wa into regs
    for (int i = tid; i < 8192; i += 256){
        ((float4*)dsh)[i] = *(const float4*)(g_ctx_embed
            + ((size_t)bq*ATTN + qq*64 + (i>>7))*CTXD + (i&127)*4);
    }
    float4 wa0 = *(const float4*)(Wa + 0*128 + l*4);
    float4 wa1 = *(const float4*)(Wa + 1*128 + l*4);
    float4 wa2 = *(const float4*)(Wa + 2*128 + l*4);
    float4 wa3 = *(const float4*)(Wa + 3*128 + l*4);
    float ba0 = ba[0];
    gridbar();

    for (int t=0; t<TT; t++){
        // ======== P1: gates partials (320 tasks: 16 ks x 20 nt of 32x128x64, bf16) ========
        {
            int q = tid>>4, j4 = (tid&15)<<2, j2 = (tid&15)<<1;
            float4 pA0, pA1; uint4 pW[4];
            #define P1_FETCH(task) { \
                int ks = (task)/20, nt = (task)%20; \
                int k0 = ks*64, col0 = nt*128; \
                if (ks < 8){ \
                    if (t == 0){ pA0 = make_float4(0.f,0.f,0.f,0.f); pA1 = pA0; } \
                    else { \
                        float4 s0 = *(const float4*)(batt + k0 + j4); \
                        float4 s1 = s0; \
                        _Pragma("unroll") \
                        for (int p=0;p<8;p++){ \
                            const float4 v0 = *(const float4*)(g_p7 + (size_t)p*(BB*HID) + q*HID + k0 + j4); \
                            const float4 v1 = *(const float4*)(g_p7 + (size_t)p*(BB*HID) + (q+16)*HID + k0 + j4); \
                            s0.x+=v0.x; s0.y+=v0.y; s0.z+=v0.z; s0.w+=v0.w; \
                            s1.x+=v1.x; s1.y+=v1.y; s1.z+=v1.z; s1.w+=v1.w; \
                        } \
                        s0.x=tanhf(s0.x); s0.y=tanhf(s0.y); s0.z=tanhf(s0.z); s0.w=tanhf(s0.w); \
                        s1.x=tanhf(s1.x); s1.y=tanhf(s1.y); s1.z=tanhf(s1.z); s1.w=tanhf(s1.w); \
                        pA0 = s0; pA1 = s1; \
                    } \
                } else { \
                    pA0 = *(const float4*)(g_A + (size_t)q*KST + k0 + j4); \
                    pA1 = *(const float4*)(g_A + (size_t)(q+16)*KST + k0 + j4); \
                } \
                const uint32_t* wb = g_WpackB + (size_t)(ks*32)*NG + col0; \
                _Pragma("unroll") \
                for (int rep=0;rep<4;rep++){ \
                    int f = tid + rep*256; \
                    pW[rep] = *(const uint4*)(wb + (size_t)(f>>5)*NG + ((f&31)<<2)); \
                } \
            }
            #define P1_COMMIT(task) { \
                int ks = (task)/20, nt = (task)%20; \
                int k0 = ks*64; \
                if (ks < 8 && nt == 0 && t > 0){ \
                    *(float4*)(g_outh + (size_t)(t-1)*(BB*HID) + q*HID + k0 + j4) = pA0; \
                    *(float4*)(g_outh + (size_t)(t-1)*(BB*HID) + (q+16)*HID + k0 + j4) = pA1; \
                } \
                uint2 c0; c0.x = f2b2(pA0.x, pA0.y); c0.y = f2b2(pA0.z, pA0.w); \
                uint2 c1; c1.x = f2b2(pA1.x, pA1.y); c1.y = f2b2(pA1.z, pA1.w); \
                *(uint2*)&sA2[q*34 + j2] = c0; \
                *(uint2*)&sA2[(q+16)*34 + j2] = c1; \
                _Pragma("unroll") \
                for (int rep=0;rep<4;rep++){ \
                    int f = tid + rep*256; \
                    *(uint4*)&sW1[(f>>5)*132 + ((f&31)<<2)] = pW[rep]; \
                } \
            }
            int ntask_me = (blk + 2*GB < NTASK1) ? 3 : 2;
            P1_FETCH(blk);
            P1_COMMIT(blk);
            __syncthreads();
            for (int r=0; r<ntask_me; r++){
                if (r+1 < ntask_me) P1_FETCH(blk + (r+1)*GB);
                {
                    int task = blk + r*GB;
                    int ks = task/20, nt = task%20;
                    int col0 = nt*128;
                    float* outp = g_gp + (size_t)ks*(BB*NG);
                    int w = tid>>5, lane = tid&31, gid = lane>>2, sub = lane&3;
                    float acc[2][2][4];
#pragma unroll
                    for (int mt=0;mt<2;mt++)
#pragma unroll
                        for (int nt2=0;nt2<2;nt2++)
#pragma unroll
                            for (int i=0;i<4;i++) acc[mt][nt2][i]=0.f;
#pragma unroll
                    for (int kb8=0; kb8<32; kb8+=8){
                        uint32_t a[2][4];
#pragma unroll
                        for (int mt=0; mt<2; mt++){
                            int rbase = mt*16;
                            a[mt][0] = sA2[(rbase+gid  )*34 + kb8+sub  ];
                            a[mt][1] = sA2[(rbase+gid+8)*34 + kb8+sub  ];
                            a[mt][2] = sA2[(rbase+gid  )*34 + kb8+sub+4];
                            a[mt][3] = sA2[(rbase+gid+8)*34 + kb8+sub+4];
                        }
                        uint32_t b[2][2];
#pragma unroll
                        for (int nt2=0; nt2<2; nt2++){
                            int cbase = w*16 + nt2*8 + gid;
                            b[nt2][0] = sW1[(kb8+sub  )*132 + cbase];
                            b[nt2][1] = sW1[(kb8+sub+4)*132 + cbase];
                        }
#pragma unroll
                        for (int mt=0; mt<2; mt++)
#pragma unroll
                            for (int nt2=0; nt2<2; nt2++)
                                MMA_BF16(acc[mt][nt2], a[mt], b[nt2]);
                    }
#pragma unroll
                    for (int mt=0; mt<2; mt++){
                        int rr = mt*16 + gid;
#pragma unroll
                        for (int nt2=0; nt2<2; nt2++){
                            int c = col0 + w*16 + nt2*8 + sub*2;
                            *(float2*)(outp + (size_t)rr*NG + c)     = make_float2(acc[mt][nt2][0], acc[mt][nt2][1]);
                            *(float2*)(outp + (size_t)(rr+8)*NG + c) = make_float2(acc[mt][nt2][2], acc[mt][nt2][3]);
                        }
                    }
                }
                __syncthreads();
                if (r+1 < ntask_me){
                    P1_COMMIT(blk + (r+1)*GB);
                    __syncthreads();
                }
            }
            #undef P1_FETCH
            #undef P1_COMMIT
        }
        gridbar();

        // ======== P2: reduce gates (16 buckets) + LSTM elementwise ========
        if (tid < 128){
            int idx = blk*128 + tid;
            int quad = idx>>2, sub = idx&3;
            int b = quad>>7, j = (quad&127)<<2;
            float4 gg[5];
#pragma unroll
            for (int c=0;c<5;c++){
                int col = c*HID + j;
                float4 x;
                if (sub == 0) x = *(const float4*)(g_xproj + (size_t)t*(BB*NG) + b*NG + col);
                else x = make_float4(0.f,0.f,0.f,0.f);
#pragma unroll
                for (int s=0;s<4;s++){
                    const float4 v = *(const float4*)(g_gp + (size_t)(sub*4+s)*(BB*NG) + b*NG + col);
                    x.x+=v.x; x.y+=v.y; x.z+=v.z; x.w+=v.w;
                }
                gg[c] = x;
            }
#pragma unroll
            for (int c=0;c<5;c++){
                gg[c].x += __shfl_down_sync(0xffffffffu, gg[c].x, 2);
                gg[c].y += __shfl_down_sync(0xffffffffu, gg[c].y, 2);
                gg[c].z += __shfl_down_sync(0xffffffffu, gg[c].z, 2);
                gg[c].w += __shfl_down_sync(0xffffffffu, gg[c].w, 2);
                gg[c].x += __shfl_down_sync(0xffffffffu, gg[c].x, 1);
                gg[c].y += __shfl_down_sync(0xffffffffu, gg[c].y, 1);
                gg[c].z += __shfl_down_sync(0xffffffffu, gg[c].z, 1);
                gg[c].w += __shfl_down_sync(0xffffffffu, gg[c].w, 1);
            }
            if (sub == 0){
                float4 cold = *(const float4*)(g_c + b*HID + j);
                float co[4] = {cold.x, cold.y, cold.z, cold.w};
                float iv4[4] = {gg[0].x,gg[0].y,gg[0].z,gg[0].w};
                float fv4[4] = {gg[1].x,gg[1].y,gg[1].z,gg[1].w};
                float gv4[4] = {gg[2].x,gg[2].y,gg[2].z,gg[2].w};
                float ov4[4] = {gg[3].x,gg[3].y,gg[3].z,gg[3].w};
                float n54[4] = {gg[4].x,gg[4].y,gg[4].z,gg[4].w};
                float cn4[4], hn4[4], f04[4];
#pragma unroll
                for (int e=0;e<4;e++){
                    float cn = sigf(fv4[e])*co[e] + sigf(iv4[e])*tanhf(gv4[e]);
                    float tc = tanhf(cn);
                    cn4[e] = cn;
                    hn4[e] = sigf(ov4[e])*tc;
                    f04[e] = sigf(n54[e])*tc;
                }
                *(float4*)(g_c   + b*HID + j) = make_float4(cn4[0],cn4[1],cn4[2],cn4[3]);
                *(float4*)(g_A   + b*KST + HID + j) = make_float4(hn4[0],hn4[1],hn4[2],hn4[3]);
                *(float4*)(g_fr0 + b*HID + j) = make_float4(f04[0],f04[1],f04[2],f04[3]);
            }
        }
        gridbar();

        // ======== P3: fr0@Wfr and h@Who partials (128 tasks, 1/block, bf16) ========
        {
            int ks = blk & 7, nt = (blk>>3)&7, mat = blk>>6;
            const float* A = mat ? (g_A + HID) : g_fr0;
            int lda = mat ? KST : HID;
            const uint32_t* WB = g_W5B + (size_t)mat*((HID/2)*HID);
            gtask64b(A, lda, WB, nt*64, ks*64,
                  g_p3 + (size_t)mat*(8*BB*HID) + (size_t)ks*(BB*HID), HID,
                  nullptr, nullptr, -1);
        }
        gridbar();

        // ======== P4: fr@Wfre, hol@Whoe partials (A staged from p3, bf16) ========
        {
            int ks = blk & 7, nt = (blk>>3)&7, mat = blk>>6;
            const uint32_t* WB = g_W5B + (size_t)(2+mat)*((HID/2)*HID);
            gtask64b(nullptr, 0, WB, nt*64, ks*64,
                  g_p4 + (size_t)mat*(8*BB*HID) + (size_t)ks*(BB*HID), HID,
                  g_p3 + (size_t)mat*(8*BB*HID), mat ? bho : bfr, mat ? 2 : 1);
        }
        gridbar();

        // ======== P5: attention scores (smem ctx; hoe/fre staged from p4, 8 partials) ========
        {
            if (tid < 128){
                int j = tid*4;
                float4 s = *(const float4*)(bhoe + j);
#pragma unroll
                for (int p=0;p<8;p++){
                    const float4 v = *(const float4*)(g_p4 + (size_t)(8+p)*(BB*HID) + bq*HID + j);
                    s.x+=v.x; s.y+=v.y; s.z+=v.z; s.w+=v.w;
                }
                *(float4*)&dsh[SOFF_HOE + j] = s;
            } else if (qq == 0){
                int j = (tid-128)*4;
                float4 s = *(const float4*)(bfre + j);
#pragma unroll
                for (int p=0;p<8;p++){
                    const float4 v = *(const float4*)(g_p4 + (size_t)p*(BB*HID) + bq*HID + j);
                    s.x+=v.x; s.y+=v.y; s.z+=v.z; s.w+=v.w;
                }
                *(float4*)&dsh[SOFF_FRE + j] = s;
            }
            __syncthreads();
            int w = tid>>5;
            float4 hv0 = *(const float4*)&dsh[SOFF_HOE + 0*128 + l*4];
            float4 hv1 = *(const float4*)&dsh[SOFF_HOE + 1*128 + l*4];
            float4 hv2 = *(const float4*)&dsh[SOFF_HOE + 2*128 + l*4];
            float4 hv3 = *(const float4*)&dsh[SOFF_HOE + 3*128 + l*4];
#pragma unroll
            for (int it=0; it<8; it++){
                int al = it*8 + w;
                const float* e = dsh + al*512;
                float acc = 0.f;
                float4 ev;
                ev = *(const float4*)&e[0*128 + l*4];
                acc += wa0.x*tanha(ev.x+hv0.x); acc += wa0.y*tanha(ev.y+hv0.y);
                acc += wa0.z*tanha(ev.z+hv0.z); acc += wa0.w*tanha(ev.w+hv0.w);
                ev = *(const float4*)&e[1*128 + l*4];
                acc += wa1.x*tanha(ev.x+hv1.x); acc += wa1.y*tanha(ev.y+hv1.y);
                acc += wa1.z*tanha(ev.z+hv1.z); acc += wa1.w*tanha(ev.w+hv1.w);
                ev = *(const float4*)&e[2*128 + l*4];
                acc += wa2.x*tanha(ev.x+hv2.x); acc += wa2.y*tanha(ev.y+hv2.y);
                acc += wa2.z*tanha(ev.z+hv2.z); acc += wa2.w*tanha(ev.w+hv2.w);
                ev = *(const float4*)&e[3*128 + l*4];
                acc += wa3.x*tanha(ev.x+hv3.x); acc += wa3.y*tanha(ev.y+hv3.y);
                acc += wa3.z*tanha(ev.z+hv3.z); acc += wa3.w*tanha(ev.w+hv3.w);
#pragma unroll
                for (int off=16; off; off>>=1) acc += __shfl_xor_sync(0xffffffffu, acc, off);
                if (l == 0) g_scores[bq*NA + qq*64 + al + 1] = acc + ba0;
            }
            if (qq == 0 && w == 0){
                float acc = 0.f;
                float4 ev;
                ev = *(const float4*)&dsh[SOFF_FRE + 0*128 + l*4];
                acc += wa0.x*tanha(ev.x+hv0.x); acc += wa0.y*tanha(ev.y+hv0.y);
                acc += wa0.z*tanha(ev.z+hv0.z); acc += wa0.w*tanha(ev.w+hv0.w);
                ev = *(const float4*)&dsh[SOFF_FRE + 1*128 + l*4];
                acc += wa1.x*tanha(ev.x+hv1.x); acc += wa1.y*tanha(ev.y+hv1.y);
                acc += wa1.z*tanha(ev.z+hv1.z); acc += wa1.w*tanha(ev.w+hv1.w);
                ev = *(const float4*)&dsh[SOFF_FRE + 2*128 + l*4];
                acc += wa2.x*tanha(ev.x+hv2.x); acc += wa2.y*tanha(ev.y+hv2.y);
                acc += wa2.z*tanha(ev.z+hv2.z); acc += wa2.w*tanha(ev.w+hv2.w);
                ev = *(const float4*)&dsh[SOFF_FRE + 3*128 + l*4];
                acc += wa3.x*tanha(ev.x+hv3.x); acc += wa3.y*tanha(ev.y+hv3.y);
                acc += wa3.z*tanha(ev.z+hv3.z); acc += wa3.w*tanha(ev.w+hv3.w);
#pragma unroll
                for (int off=16; off; off>>=1) acc += __shfl_xor_sync(0xffffffffu, acc, off);
                if (l == 0) g_scores[bq*NA] = acc + ba0;
            }
        }
        gridbar();

        // ======== P6: softmax + vis (fr, hol reduced inline from 8 partials) -> visph ========
        {
            float* s_sc  = dsh + SOFF_GT;
            float* s_red = dsh + SOFF_GT + 272;
            float* s_v   = dsh + SOFF_GT + 544;
            s_sc[tid] = g_scores[bq*NA + tid];
            if (tid == 0) s_sc[256] = g_scores[bq*NA + 256];
            __syncthreads();
            float mv = s_sc[tid];
            if (tid == 0) mv = fmaxf(mv, s_sc[256]);
            s_red[tid] = mv; __syncthreads();
            for (int st=128; st; st>>=1){ if (tid<st) s_red[tid] = fmaxf(s_red[tid], s_red[tid+st]); __syncthreads(); }
            float mx = s_red[0]; __syncthreads();
            float ev  = expf(s_sc[tid] - mx);
            float ev2 = (tid==0) ? expf(s_sc[256] - mx) : 0.f;
            s_red[tid] = ev + ev2; __syncthreads();
            for (int st=128; st; st>>=1){ if (tid<st) s_red[tid] += s_red[tid+st]; __syncthreads(); }
            float inv = 1.f / s_red[0];
            __syncthreads();
            s_sc[tid] = ev * inv;
            if (tid == 0) s_sc[256] = ev2 * inv;
            __syncthreads();
            int aa = tid>>5, hq = tid&31;
            int h = qq*128 + hq*4;
            float4 acc = make_float4(0.f,0.f,0.f,0.f);
            int astart = aa;
            if (aa == 0){
                float4 s = *(const float4*)(bfr + h);
#pragma unroll
                for (int p=0;p<8;p++){
                    const float4 v = *(const float4*)(g_p3 + (size_t)p*(BB*HID) + bq*HID + h);
                    s.x+=v.x; s.y+=v.y; s.z+=v.z; s.w+=v.w;
                }
                s.x=fmaxf(s.x,0.f); s.y=fmaxf(s.y,0.f); s.z=fmaxf(s.z,0.f); s.w=fmaxf(s.w,0.f);
                float w0 = s_sc[0];
                acc.x = w0*s.x; acc.y = w0*s.y; acc.z = w0*s.z; acc.w = w0*s.w;
                astart = 8;
            }
            for (int a = astart; a < NA; a += 8){
                float w = s_sc[a];
                float4 v = *(const float4*)(cnn + ((size_t)bq*ATTN + (a-1))*CTXD + h);
                acc.x += w*v.x; acc.y += w*v.y; acc.z += w*v.z; acc.w += w*v.w;
            }
            *(float4*)&s_v[aa*128 + hq*4] = acc;
            __syncthreads();
            if (tid < 32){
                int h2 = qq*128 + tid*4;
                float4 s = make_float4(0.f,0.f,0.f,0.f);
#pragma unroll
                for (int a2=0;a2<8;a2++){
                    const float4 v = *(const float4*)&s_v[a2*128 + tid*4];
                    s.x+=v.x; s.y+=v.y; s.z+=v.z; s.w+=v.w;
                }
                float4 ho = *(const float4*)(bho + h2);
#pragma unroll
                for (int p=0;p<8;p++){
                    const float4 v = *(const float4*)(g_p3 + (size_t)(8+p)*(BB*HID) + bq*HID + h2);
                    ho.x+=v.x; ho.y+=v.y; ho.z+=v.z; ho.w+=v.w;
                }
                s.x += tanhf(ho.x); s.y += tanhf(ho.y); s.z += tanhf(ho.z); s.w += tanhf(ho.w);
                *(float4*)(g_visph + bq*HID + h2) = s;
            }
            __syncthreads();
        }
        gridbar();

        // ======== P7: outh partials (64 tasks: 8 ks x 8 nt, bf16 Watt) ========
        if (blk < 64){
            int ks = blk & 7, nt = blk>>3;
            gtask64b(g_visph, HID, g_W5B + (size_t)4*((HID/2)*HID), nt*64, ks*64,
                  g_p7 + (size_t)ks*(BB*HID), HID, nullptr, nullptr, -1);
        }
        gridbar();
    }

    // ---- epilogue: finalize out(TT-1) into g_outh[TT-1]
    if (tid < 32){
        int quad = blk*32 + tid;
        int b = quad>>7, j = (quad&127)<<2;
        float4 s = *(const float4*)(batt + j);
#pragma unroll
        for (int p=0;p<8;p++){
            const float4 v = *(const float4*)(g_p7 + (size_t)p*(BB*HID) + b*HID + j);
            s.x+=v.x; s.y+=v.y; s.z+=v.z; s.w+=v.w;
        }
        s.x=tanhf(s.x); s.y=tanhf(s.y); s.z=tanhf(s.z); s.w=tanhf(s.w);
        *(float4*)(g_outh + (size_t)(TT-1)*(BB*HID) + b*HID + j) = s;
    }
}

// ---------------- log_softmax + [t][b] -> [b][t] remap ----------------
__global__ void k_logsm(float* __restrict__ out){
    int r = blockIdx.x;
    int t = r >> 5, b = r & 31;
    const float* row = g_logits + (size_t)r*VOC;
    float* orow = out + ((size_t)b*TT + t)*VOC;
    __shared__ float red[256];
    int tid = threadIdx.x;
    float mx = -1e30f;
    for (int i=tid; i<VOC; i+=256) mx = fmaxf(mx, row[i]);
    red[tid] = mx; __syncthreads();
    for (int st=128; st>0; st>>=1){ if (tid<st) red[tid] = fmaxf(red[tid], red[tid+st]); __syncthreads(); }
    mx = red[0]; __syncthreads();
    float sm = 0.f;
    for (int i=tid; i<VOC; i+=256) sm += expf(row[i] - mx);
    red[tid] = sm; __syncthreads();
    for (int st=128; st>0; st>>=1){ if (tid<st) red[tid] += red[tid+st]; __syncthreads(); }
    float ls = mx + logf(red[0]);
    for (int i=tid; i<VOC; i+=256) orow[i] = row[i] - ls;
}

// ---------------- launch ----------------
extern "C" void kernel_launch(void* const* d_in, const int* in_sizes, int n_in,
                              void* d_out, int out_size){
    const float* cnn  = (const float*)d_in[0];
    const int*   seq  = (const int*)  d_in[1];
    const float* emb  = (const float*)d_in[2];
    const float* Wce  = (const float*)d_in[3];  const float* bce  = (const float*)d_in[4];
    const float* Wih  = (const float*)d_in[5];  const float* bih  = (const float*)d_in[6];
    const float* Whh  = (const float*)d_in[7];  const float* bhh  = (const float*)d_in[8];
    const float* Wi2h = (const float*)d_in[9];  const float* bi2h = (const float*)d_in[10];
    const float* Wh2h = (const float*)d_in[11]; const float* bh2h = (const float*)d_in[12];
    const float* Wfr  = (const float*)d_in[13]; const float* bfr  = (const float*)d_in[14];
    const float* Wfre = (const float*)d_in[15]; const float* bfre = (const float*)d_in[16];
    const float* Who  = (const float*)d_in[17]; const float* bho  = (const float*)d_in[18];
    const float* Whoe = (const float*)d_in[19]; const float* bhoe = (const float*)d_in[20];
    const float* Wa   = (const float*)d_in[21]; const float* ba   = (const float*)d_in[22];
    const float* Watt = (const float*)d_in[23]; const float* batt = (const float*)d_in[24];
    const float* Wlog = (const float*)d_in[25]; const float* blog = (const float*)d_in[26];
    float* out = (float*)d_out;

    cudaFuncSetAttribute(persist_kernel, cudaFuncAttributeMaxDynamicSharedMemorySize,
                         SMEM_FLOATS*4);

    k_init<<<192, 256>>>();
    k_packWB<<<((KST/2)*NG)/256, 256>>>(Wih, Whh, Wi2h, Wh2h);
    k_pack5B<<<(5*(HID/2)*HID)/256, 256>>>(Wfr, Who, Wfre, Whoe, Watt);
    k_packX<<<(EMBD*NG)/256, 256>>>(Wih, Wi2h, bih, bhh, bi2h, bh2h);
    k_gather<<<(TT*BB*EMBD)/256, 256>>>(seq, emb);
    k_gemm_tf32<<<dim3(CTXD/64, (BB*ATTN)/128), 256>>>(0, cnn, Wce, bce, CTXD, CTXD, 1);
    k_gemm_tf32<<<dim3(NG/64, (TT*BB)/128), 256>>>(1, nullptr, nullptr, nullptr, NG, EMBD, 0);

    persist_kernel<<<GB, 256, SMEM_FLOATS*4>>>(cnn, bfr, bho, bfre, bhoe, Wa, ba, batt);

    k_gemm_tf32<<<dim3((VOC+63)/64, (TT*BB)/128), 256>>>(2, nullptr, Wlog, blog, VOC, HID, 0);
    k_logsm<<<TT*BB, 256>>>(out);
}